// round 7
// baseline (speedup 1.0000x reference)
#include <cuda_runtime.h>
#include <math.h>

#define B_      128
#define EMB_    256
#define NTOK    394
#define MTOK    (B_ * NTOK)          // 50432
#define MPE     (B_ * 196)           // 25088

#define KC      32
#define STG     3
#define ASTR    36
#define BSTR    136
#define SMEM_NN ((STG * (128 * ASTR + 32 * BSTR)) * 4)
#define FA_SMEM ((64*132 + 2*64*132 + 2*64*136 + 64*68 + 256) * 4)   // 189440
#define FA_NKT  7

// ---------------- scratch ---------------------------------------------------
__device__ float g_T1[MPE * 768];
__device__ float g_T2[MPE * 192];
__device__ float g_Wt[507904];
__device__ float g_z [MTOK * EMB_];
__device__ float g_h [MTOK * EMB_];
__device__ float g_q [MTOK * EMB_];
__device__ float g_k [MTOK * EMB_];
__device__ float g_v [MTOK * EMB_];
__device__ float g_o [MTOK * EMB_];
__device__ float g_pool[B_ * 8 * EMB_];

#define OFF_W1 0
#define OFF_W2 196608
#define OFF_WQ 245760
#define OFF_WK 311296
#define OFF_WV 376832
#define OFF_WP 442368

// ---------------- helpers ----------------------------------------------------
__device__ __forceinline__ float f2tf_f(float f) {
    unsigned u; asm("cvt.rna.tf32.f32 %0, %1;" : "=r"(u) : "f"(f));
    return __uint_as_float(u);
}
__device__ __forceinline__ void mma8(float* acc, const unsigned* a, const unsigned* b) {
    asm volatile(
        "mma.sync.aligned.m16n8k8.row.col.f32.tf32.tf32.f32 "
        "{%0,%1,%2,%3}, {%4,%5,%6,%7}, {%8,%9}, {%0,%1,%2,%3};\n"
        : "+f"(acc[0]), "+f"(acc[1]), "+f"(acc[2]), "+f"(acc[3])
        : "r"(a[0]), "r"(a[1]), "r"(a[2]), "r"(a[3]), "r"(b[0]), "r"(b[1]));
}
__device__ __forceinline__ void cpa16(float* dst, const float* src, bool pred) {
    unsigned d = (unsigned)__cvta_generic_to_shared(dst);
    int sz = pred ? 16 : 0;
    asm volatile("cp.async.cg.shared.global [%0], [%1], 16, %2;\n"
                 :: "r"(d), "l"(src), "r"(sz));
}
__device__ __forceinline__ void cpa_commit() { asm volatile("cp.async.commit_group;\n"); }
template <int N>
__device__ __forceinline__ void cpa_wait() { asm volatile("cp.async.wait_group %0;\n" :: "n"(N)); }

// ---------------- weight prep ------------------------------------------------
__global__ void prep_w(const float* __restrict__ W1, const float* __restrict__ W2,
                       const float* __restrict__ Wq, const float* __restrict__ Wk,
                       const float* __restrict__ Wv, const float* __restrict__ Wp,
                       float* __restrict__ out) {
    int i = blockIdx.x * 256 + threadIdx.x;
    const float* src; int j;
    if (i < OFF_W2)      { src = W1; j = i; }
    else if (i < OFF_WQ) { src = W2; j = i - OFF_W2; }
    else if (i < OFF_WK) { src = Wq; j = i - OFF_WQ; }
    else if (i < OFF_WV) { src = Wk; j = i - OFF_WK; }
    else if (i < OFF_WP) { src = Wv; j = i - OFF_WV; }
    else                 { src = Wp; j = i - OFF_WP; }
    out[i] = f2tf_f(src[j]);
}

// ---------------- im2col ------------------------------------------------------
__global__ void im2col1(const float* __restrict__ x, float* __restrict__ T) {
    __shared__ float buf[768];
    int j = blockIdx.x, b = blockIdx.y;
    int ph = j / 14, pw = j % 14;
    const float* xb = x + (size_t)b * 3 * 224 * 224 + (size_t)(ph * 16) * 224 + pw * 16;
    int t = threadIdx.x;
    int pi = t >> 4, pj = t & 15;
#pragma unroll
    for (int c = 0; c < 3; c++)
        buf[(pi * 16 + pj) * 3 + c] = f2tf_f(xb[((size_t)c * 224 + pi) * 224 + pj]);
    __syncthreads();
    float* Tr = T + ((size_t)b * 196 + j) * 768;
#pragma unroll
    for (int k = 0; k < 3; k++) Tr[t + k * 256] = buf[t + k * 256];
}
__global__ void im2col2(const float* __restrict__ x, float* __restrict__ T) {
    __shared__ float buf[192];
    int i = blockIdx.x, b = blockIdx.y;
    int jdx = 4 * i + 3;
    int ph = jdx / 28, pw = jdx % 28;
    const float* xb = x + (size_t)b * 3 * 224 * 224 + (size_t)(ph * 8) * 224 + pw * 8;
    int t = threadIdx.x;
    int c = t >> 6, pos = t & 63;
    int pi = pos >> 3, pj = pos & 7;
    buf[pos * 3 + c] = f2tf_f(xb[((size_t)c * 224 + pi) * 224 + pj]);
    __syncthreads();
    T[((size_t)b * 196 + i) * 192 + t] = buf[t];
}
__global__ void cls_fill(const float* __restrict__ cls1,
                         const float* __restrict__ cls2,
                         float* __restrict__ z) {
    int b = blockIdx.x, e = threadIdx.x;
    z[((size_t)b * NTOK + 0)   * EMB_ + e] = cls2[e];
    z[((size_t)b * NTOK + 197) * EMB_ + e] = cls1[e];
}

// ---------------- NN GEMM (cp.async 3-stage, 128x128) -------------------------
// mode 0: plain  1: patch1->z  2: patch2->z  3: qkv (cvt)
__global__ __launch_bounds__(256)
void gemm_nn(const float* __restrict__ A, const float* __restrict__ Bm,
             const float* __restrict__ bias, float* __restrict__ C,
             int M, int N, int K, int mode) {
    extern __shared__ float smem[];
    float* As = smem;
    float* Bs = smem + STG * 128 * ASTR;
    int tid = threadIdx.x;
    int bm = blockIdx.y * 128, bn = blockIdx.x * 128;
    int wid = tid >> 5, lane = tid & 31;
    int wm = wid & 3, wn = wid >> 2;
    int gid = lane >> 2, tg = lane & 3;
    int aRow = tid >> 3, aC4 = (tid & 7) << 2;

    auto loadA = [&](int s, int k0) {
        float* dst = As + s * 128 * ASTR;
#pragma unroll
        for (int i = 0; i < 4; i++) {
            int row = aRow + i * 32;
            bool p = (bm + row) < M;
            const float* src = A + (size_t)(p ? bm + row : bm) * K + k0 + aC4;
            cpa16(dst + row * ASTR + aC4, src, p);
        }
    };
    auto loadB = [&](int s, int k0) {
        float* dst = Bs + s * 32 * BSTR;
#pragma unroll
        for (int i = 0; i < 4; i++) {
            int idx = tid + i * 256;
            int kr = idx >> 5, c4 = (idx & 31) << 2;
            bool p = (k0 + kr) < K;
            const float* src = Bm + (size_t)(p ? k0 + kr : 0) * N + bn + c4;
            cpa16(dst + kr * BSTR + c4, src, p);
        }
    };

    float acc[2][8][4] = {};
    int nk = K / KC;
#pragma unroll
    for (int s = 0; s < STG - 1; s++) { loadA(s, s * KC); loadB(s, s * KC); cpa_commit(); }

    for (int it = 0; it < nk; it++) {
        cpa_wait<STG - 2>();
        __syncthreads();
        int nxt = it + STG - 1;
        if (nxt < nk) { loadA(nxt % STG, nxt * KC); loadB(nxt % STG, nxt * KC); }
        cpa_commit();
        int s = it % STG;
        const float* ap = As + s * 128 * ASTR + (wm * 32 + gid) * ASTR + tg;
        const float* bp = Bs + s * 32 * BSTR + tg * BSTR + wn * 64 + gid;
#pragma unroll
        for (int kk = 0; kk < KC; kk += 8) {
            unsigned af[2][4], bf[8][2];
#pragma unroll
            for (int mt = 0; mt < 2; mt++) {
                af[mt][0] = __float_as_uint(ap[mt * 16 * ASTR + kk]);
                af[mt][1] = __float_as_uint(ap[(mt * 16 + 8) * ASTR + kk]);
                af[mt][2] = __float_as_uint(ap[mt * 16 * ASTR + kk + 4]);
                af[mt][3] = __float_as_uint(ap[(mt * 16 + 8) * ASTR + kk + 4]);
            }
#pragma unroll
            for (int nt = 0; nt < 8; nt++) {
                bf[nt][0] = __float_as_uint(bp[kk * BSTR + nt * 8]);
                bf[nt][1] = __float_as_uint(bp[(kk + 4) * BSTR + nt * 8]);
            }
#pragma unroll
            for (int mt = 0; mt < 2; mt++)
#pragma unroll
                for (int nt = 0; nt < 8; nt++)
                    mma8(acc[mt][nt], af[mt], bf[nt]);
        }
        __syncthreads();
    }

#pragma unroll
    for (int mt = 0; mt < 2; mt++) {
#pragma unroll
        for (int nt = 0; nt < 8; nt++) {
            int n = bn + wn * 64 + nt * 8 + tg * 2;
            float bv0 = bias ? bias[n] : 0.f;
            float bv1 = bias ? bias[n + 1] : 0.f;
#pragma unroll
            for (int half = 0; half < 2; half++) {
                int m = bm + wm * 32 + mt * 16 + gid + half * 8;
                if (m >= M) continue;
                float v0 = acc[mt][nt][half * 2 + 0] + bv0;
                float v1 = acc[mt][nt][half * 2 + 1] + bv1;
                if (mode == 3) { v0 = f2tf_f(v0); v1 = f2tf_f(v1); }
                float2 val = make_float2(v0, v1);
                if (mode == 0) {
                    *(float2*)&C[(size_t)m * N + n] = val;
                } else if (mode == 1) {
                    int b = m / 196, jj = m % 196;
                    *(float2*)&C[((size_t)b * NTOK + 198 + jj) * EMB_ + n] = val;
                } else if (mode == 2) {
                    int b = m / 196, jj = m % 196;
                    *(float2*)&C[((size_t)b * NTOK + 1 + jj) * EMB_ + n] = val;
                } else {
                    int b = m / NTOK, t = m % NTOK;
                    int hh = n >> 7, d = n & 127;
                    *(float2*)&C[(((size_t)b * 2 + hh) * NTOK + t) * 128 + d] = val;
                }
            }
        }
    }
}

// ---------------- flash attention (cross-warp-correct online softmax) --------
__global__ __launch_bounds__(256)
void flash_attn(const float* __restrict__ Qg, const float* __restrict__ Kg,
                const float* __restrict__ Vg, float* __restrict__ Og) {
    extern __shared__ float smem[];
    float* Qs = smem;                       // [64][132]
    float* Ks = Qs + 64 * 132;              // [2][64][132]
    float* Vs = Ks + 2 * 64 * 132;          // [2][64][136]
    float* Ps = Vs + 2 * 64 * 136;          // [64][68]
    float* redM = Ps + 64 * 68;             // [64][2]
    float* redS = redM + 128;               // [64][2]
    int tid = threadIdx.x, lane = tid & 31, wid = tid >> 5;
    int wm = wid & 3, wn = wid >> 2;
    int gid = lane >> 2, tg = lane & 3;
    int qt = blockIdx.x, bh = blockIdx.y;
    const float* Qb = Qg + (size_t)bh * 394 * 128;
    const float* Kb = Kg + (size_t)bh * 394 * 128;
    const float* Vb = Vg + (size_t)bh * 394 * 128;
    float* Ob = Og + (size_t)(bh >> 1) * NTOK * EMB_ + (bh & 1) * 128;
    int qbase = qt * 64;
    int r0 = wm * 16 + gid, r1 = r0 + 8;    // S-tile rows owned by this thread

    auto loadQ = [&]() {
#pragma unroll
        for (int i = 0; i < 8; i++) {
            int idx = tid + i * 256; int row = idx >> 5; int cc = (idx & 31) << 2;
            bool p = (qbase + row) < 394;
            cpa16(Qs + row * 132 + cc, Qb + (size_t)(p ? qbase + row : 0) * 128 + cc, p);
        }
    };
    auto loadK = [&](int st, int kt) {
        float* dst = Ks + st * 64 * 132;
#pragma unroll
        for (int i = 0; i < 8; i++) {
            int idx = tid + i * 256; int row = idx >> 5; int cc = (idx & 31) << 2;
            bool p = (kt * 64 + row) < 394;
            cpa16(dst + row * 132 + cc, Kb + (size_t)(p ? kt * 64 + row : 0) * 128 + cc, p);
        }
    };
    auto loadV = [&](int st, int kt) {
        float* dst = Vs + st * 64 * 136;
#pragma unroll
        for (int i = 0; i < 8; i++) {
            int idx = tid + i * 256; int row = idx >> 5; int cc = (idx & 31) << 2;
            bool p = (kt * 64 + row) < 394;
            cpa16(dst + row * 136 + cc, Vb + (size_t)(p ? kt * 64 + row : 0) * 128 + cc, p);
        }
    };

    loadQ(); loadK(0, 0); loadV(0, 0); cpa_commit();
    loadK(1, 1); loadV(1, 1); cpa_commit();

    float accO[8][4] = {};
    float m0 = -1e30f, m1 = -1e30f, l0 = 0.f, l1 = 0.f;

    for (int kt = 0; kt < FA_NKT; kt++) {
        int st = kt & 1;
        cpa_wait<1>();
        __syncthreads();

        // ---- S = Q @ K^T : warp covers rows [wm*16,+16), cols [wn*32,+32) ----
        float accS[4][4] = {};
        const float* qp = Qs + r0 * 132 + tg;
        const float* kp = Ks + st * 64 * 132 + (wn * 32 + gid) * 132 + tg;
#pragma unroll
        for (int kk = 0; kk < 128; kk += 8) {
            unsigned af[4];
            af[0] = __float_as_uint(qp[kk]);
            af[1] = __float_as_uint(qp[8 * 132 + kk]);
            af[2] = __float_as_uint(qp[kk + 4]);
            af[3] = __float_as_uint(qp[8 * 132 + kk + 4]);
#pragma unroll
            for (int nt = 0; nt < 4; nt++) {
                unsigned bf[2];
                bf[0] = __float_as_uint(kp[nt * 8 * 132 + kk]);
                bf[1] = __float_as_uint(kp[nt * 8 * 132 + kk + 4]);
                mma8(accS[nt], af, bf);
            }
        }
        // mask cols >= 394
        int cbase = kt * 64 + wn * 32 + tg * 2;
#pragma unroll
        for (int nt = 0; nt < 4; nt++) {
            int c0 = cbase + nt * 8;
            if (c0 >= 394)     { accS[nt][0] = -1e30f; accS[nt][2] = -1e30f; }
            if (c0 + 1 >= 394) { accS[nt][1] = -1e30f; accS[nt][3] = -1e30f; }
        }
        // ---- warp-local (32-col) max ----
        float rm0 = -1e30f, rm1 = -1e30f;
#pragma unroll
        for (int nt = 0; nt < 4; nt++) {
            rm0 = fmaxf(rm0, fmaxf(accS[nt][0], accS[nt][1]));
            rm1 = fmaxf(rm1, fmaxf(accS[nt][2], accS[nt][3]));
        }
        rm0 = fmaxf(rm0, __shfl_xor_sync(0xffffffff, rm0, 1));
        rm0 = fmaxf(rm0, __shfl_xor_sync(0xffffffff, rm0, 2));
        rm1 = fmaxf(rm1, __shfl_xor_sync(0xffffffff, rm1, 1));
        rm1 = fmaxf(rm1, __shfl_xor_sync(0xffffffff, rm1, 2));
        // ---- local exp + local sum (vs local max) ----
        float rs0 = 0.f, rs1 = 0.f;
#pragma unroll
        for (int nt = 0; nt < 4; nt++) {
            accS[nt][0] = __expf(accS[nt][0] - rm0);
            accS[nt][1] = __expf(accS[nt][1] - rm0);
            accS[nt][2] = __expf(accS[nt][2] - rm1);
            accS[nt][3] = __expf(accS[nt][3] - rm1);
            rs0 += accS[nt][0] + accS[nt][1];
            rs1 += accS[nt][2] + accS[nt][3];
        }
        rs0 += __shfl_xor_sync(0xffffffff, rs0, 1);
        rs0 += __shfl_xor_sync(0xffffffff, rs0, 2);
        rs1 += __shfl_xor_sync(0xffffffff, rs1, 1);
        rs1 += __shfl_xor_sync(0xffffffff, rs1, 2);
        // ---- publish (max,sum) per row per wn half; merge globally ----
        if (tg == 0) {
            redM[r0 * 2 + wn] = rm0;  redS[r0 * 2 + wn] = rs0;
            redM[r1 * 2 + wn] = rm1;  redS[r1 * 2 + wn] = rs1;
        }
        __syncthreads();
        float a0 = redM[r0 * 2], a1 = redM[r0 * 2 + 1];
        float gm0 = fmaxf(a0, a1);
        float gs0 = redS[r0 * 2] * __expf(a0 - gm0) + redS[r0 * 2 + 1] * __expf(a1 - gm0);
        float b0v = redM[r1 * 2], b1v = redM[r1 * 2 + 1];
        float gm1 = fmaxf(b0v, b1v);
        float gs1 = redS[r1 * 2] * __expf(b0v - gm1) + redS[r1 * 2 + 1] * __expf(b1v - gm1);
        // ---- online update ----
        float mn0 = fmaxf(m0, gm0), mn1 = fmaxf(m1, gm1);
        float sc0 = __expf(m0 - mn0), sc1 = __expf(m1 - mn1);
        l0 = l0 * sc0 + gs0 * __expf(gm0 - mn0);
        l1 = l1 * sc1 + gs1 * __expf(gm1 - mn1);
        m0 = mn0;  m1 = mn1;
        float fw0 = __expf(rm0 - mn0), fw1 = __expf(rm1 - mn1);  // P correction
#pragma unroll
        for (int nt = 0; nt < 8; nt++) {
            accO[nt][0] *= sc0; accO[nt][1] *= sc0;
            accO[nt][2] *= sc1; accO[nt][3] *= sc1;
        }
        // ---- stage P (corrected to global max scale) ----
        float* pw = Ps + r0 * 68 + wn * 32 + tg * 2;
#pragma unroll
        for (int nt = 0; nt < 4; nt++) {
            *(float2*)&pw[nt * 8] =
                make_float2(f2tf_f(accS[nt][0] * fw0), f2tf_f(accS[nt][1] * fw0));
            *(float2*)&pw[8 * 68 + nt * 8] =
                make_float2(f2tf_f(accS[nt][2] * fw1), f2tf_f(accS[nt][3] * fw1));
        }
        __syncthreads();
        // ---- O += P @ V ----
        const float* pp = Ps + r0 * 68 + tg;
        const float* vp = Vs + st * 64 * 136 + tg * 136 + wn * 64 + gid;
#pragma unroll
        for (int kk = 0; kk < 64; kk += 8) {
            unsigned af[4];
            af[0] = __float_as_uint(pp[kk]);
            af[1] = __float_as_uint(pp[8 * 68 + kk]);
            af[2] = __float_as_uint(pp[kk + 4]);
            af[3] = __float_as_uint(pp[8 * 68 + kk + 4]);
#pragma unroll
            for (int nt = 0; nt < 8; nt++) {
                unsigned bf[2];
                bf[0] = __float_as_uint(vp[kk * 136 + nt * 8]);
                bf[1] = __float_as_uint(vp[(kk + 4) * 136 + nt * 8]);
                mma8(accO[nt], af, bf);
            }
        }
        __syncthreads();
        if (kt + 2 < FA_NKT) { loadK(st, kt + 2); loadV(st, kt + 2); }
        cpa_commit();
    }

    float inv0 = 1.f / (l0 * 16.f), inv1 = 1.f / (l1 * 16.f);
    int gr0 = qbase + r0, gr1 = qbase + r1;
#pragma unroll
    for (int nt = 0; nt < 8; nt++) {
        int col = wn * 64 + nt * 8 + tg * 2;
        if (gr0 < 394)
            *(float2*)&Ob[(size_t)gr0 * EMB_ + col] =
                make_float2(f2tf_f(accO[nt][0] * inv0), f2tf_f(accO[nt][1] * inv0));
        if (gr1 < 394)
            *(float2*)&Ob[(size_t)gr1 * EMB_ + col] =
                make_float2(f2tf_f(accO[nt][2] * inv1), f2tf_f(accO[nt][3] * inv1));
    }
}

// ---------------- layer norm --------------------------------------------------
__global__ __launch_bounds__(256)
void ln_kernel(const float* __restrict__ in, const float* __restrict__ g,
               const float* __restrict__ b, float* __restrict__ out,
               const float* __restrict__ addsrc, int docvt) {
    int r = blockIdx.x, e = threadIdx.x;
    size_t idx = (size_t)r * EMB_ + e;
    float v = in[idx];
    float s = v, s2 = v * v;
#pragma unroll
    for (int off = 16; off > 0; off >>= 1) {
        s  += __shfl_xor_sync(0xffffffff, s,  off);
        s2 += __shfl_xor_sync(0xffffffff, s2, off);
    }
    __shared__ float ss[8], ss2[8];
    if ((e & 31) == 0) { ss[e >> 5] = s; ss2[e >> 5] = s2; }
    __syncthreads();
    float tot = 0.f, tot2 = 0.f;
#pragma unroll
    for (int i = 0; i < 8; i++) { tot += ss[i]; tot2 += ss2[i]; }
    float mean = tot * (1.f / EMB_);
    float var = tot2 * (1.f / EMB_) - mean * mean;
    float nv = (v - mean) * rsqrtf(var + 1e-5f) * g[e] + b[e];
    if (docvt) nv = f2tf_f(nv);
    out[idx] = addsrc ? (addsrc[idx] + nv) : nv;
}

// ---------------- two-stage pool + head ---------------------------------------
__global__ __launch_bounds__(256)
void pool_partial(const float* __restrict__ z, float* __restrict__ pool) {
    int b = blockIdx.x, seg = blockIdx.y, e = threadIdx.x;
    int t0 = seg * 50;
    int t1 = t0 + 50; if (t1 > 394) t1 = 394;
    const float* zb = z + (size_t)b * NTOK * EMB_;
    float s = 0.f;
    for (int t = t0; t < t1; t++) s += zb[(size_t)t * EMB_ + e];
    pool[((size_t)b * 8 + seg) * EMB_ + e] = s;
}

__global__ __launch_bounds__(256)
void head_kernel(const float* __restrict__ pool, const float* __restrict__ g,
                 const float* __restrict__ bb, const float* __restrict__ Wc,
                 const float* __restrict__ bc, float* __restrict__ out) {
    int b = blockIdx.x, e = threadIdx.x;
    float s = 0.f;
#pragma unroll
    for (int i = 0; i < 8; i++) s += pool[((size_t)b * 8 + i) * EMB_ + e];
    float pooled = s * (1.f / NTOK);
    __shared__ float red[256];
    red[e] = pooled; __syncthreads();
    for (int st = 128; st > 0; st >>= 1) { if (e < st) red[e] += red[e + st]; __syncthreads(); }
    float mean = red[0] * (1.f / EMB_);
    __syncthreads();
    float d = pooled - mean;
    red[e] = d * d; __syncthreads();
    for (int st = 128; st > 0; st >>= 1) { if (e < st) red[e] += red[e + st]; __syncthreads(); }
    float var = red[0] * (1.f / EMB_);
    __syncthreads();
    float nv = d * rsqrtf(var + 1e-5f) * g[e] + bb[e];
    red[e] = nv * Wc[e * 2 + 0]; __syncthreads();
    for (int st = 128; st > 0; st >>= 1) { if (e < st) red[e] += red[e + st]; __syncthreads(); }
    float l0 = red[0] + bc[0];
    __syncthreads();
    red[e] = nv * Wc[e * 2 + 1]; __syncthreads();
    for (int st = 128; st > 0; st >>= 1) { if (e < st) red[e] += red[e + st]; __syncthreads(); }
    float l1 = red[0] + bc[1];
    if (e == 0) {
        float mx = fmaxf(l0, l1);
        float lse = mx + logf(expf(l0 - mx) + expf(l1 - mx));
        out[b * 2 + 0] = l0 - lse;
        out[b * 2 + 1] = l1 - lse;
    }
}

// ---------------- launch --------------------------------------------------------
extern "C" void kernel_launch(void* const* d_in, const int* in_sizes, int n_in,
                              void* d_out, int out_size) {
    const float* x     = (const float*)d_in[0];
    const float* W1    = (const float*)d_in[1];
    const float* b1    = (const float*)d_in[2];
    const float* cls1  = (const float*)d_in[3];
    const float* W2    = (const float*)d_in[4];
    const float* b2    = (const float*)d_in[5];
    const float* cls2  = (const float*)d_in[6];
    const float* ln1_g = (const float*)d_in[7];
    const float* ln1_b = (const float*)d_in[8];
    const float* Wq    = (const float*)d_in[9];
    const float* bq    = (const float*)d_in[10];
    const float* Wk    = (const float*)d_in[11];
    const float* bk    = (const float*)d_in[12];
    const float* Wv    = (const float*)d_in[13];
    const float* bv    = (const float*)d_in[14];
    const float* Wp    = (const float*)d_in[15];
    const float* bp    = (const float*)d_in[16];
    const float* ln2_g = (const float*)d_in[17];
    const float* ln2_b = (const float*)d_in[18];
    const float* lnc_g = (const float*)d_in[19];
    const float* lnc_b = (const float*)d_in[20];
    const float* Wc    = (const float*)d_in[21];
    const float* bc    = (const float*)d_in[22];
    float* out = (float*)d_out;

    static int inited = 0;
    if (!inited) {
        cudaFuncSetAttribute(gemm_nn, cudaFuncAttributeMaxDynamicSharedMemorySize, SMEM_NN);
        cudaFuncSetAttribute(flash_attn, cudaFuncAttributeMaxDynamicSharedMemorySize, FA_SMEM);
        inited = 1;
    }

    float *T1, *T2, *Wt, *z, *h, *q, *k, *v, *o, *pool;
    cudaGetSymbolAddress((void**)&T1, g_T1);
    cudaGetSymbolAddress((void**)&T2, g_T2);
    cudaGetSymbolAddress((void**)&Wt, g_Wt);
    cudaGetSymbolAddress((void**)&z,  g_z);
    cudaGetSymbolAddress((void**)&h,  g_h);
    cudaGetSymbolAddress((void**)&q,  g_q);
    cudaGetSymbolAddress((void**)&k,  g_k);
    cudaGetSymbolAddress((void**)&v,  g_v);
    cudaGetSymbolAddress((void**)&o,  g_o);
    cudaGetSymbolAddress((void**)&pool, g_pool);

    prep_w<<<507904 / 256, 256>>>(W1, W2, Wq, Wk, Wv, Wp, Wt);
    im2col1<<<dim3(196, B_), 256>>>(x, T1);
    im2col2<<<dim3(196, B_), 192>>>(x, T2);
    cls_fill<<<B_, 256>>>(cls1, cls2, z);

    gemm_nn<<<dim3(2, 196), 256, SMEM_NN>>>(T1, Wt + OFF_W1, b1, z, MPE, 256, 768, 1);
    gemm_nn<<<dim3(2, 196), 256, SMEM_NN>>>(T2, Wt + OFF_W2, b2, z, MPE, 256, 192, 2);

    ln_kernel<<<MTOK, 256>>>(z, ln1_g, ln1_b, h, nullptr, 1);

    gemm_nn<<<dim3(2, 394), 256, SMEM_NN>>>(h, Wt + OFF_WQ, bq, q, MTOK, 256, 256, 3);
    gemm_nn<<<dim3(2, 394), 256, SMEM_NN>>>(h, Wt + OFF_WK, bk, k, MTOK, 256, 256, 3);
    gemm_nn<<<dim3(2, 394), 256, SMEM_NN>>>(h, Wt + OFF_WV, bv, v, MTOK, 256, 256, 3);

    flash_attn<<<dim3(FA_NKT, 256), 256, FA_SMEM>>>(q, k, v, o);

    gemm_nn<<<dim3(2, 394), 256, SMEM_NN>>>(o, Wt + OFF_WP, bp, h, MTOK, 256, 256, 0);
    ln_kernel<<<MTOK, 256>>>(h, ln2_g, ln2_b, z, z, 0);

    pool_partial<<<dim3(B_, 8), 256>>>(z, pool);
    head_kernel<<<B_, 256>>>(pool, lnc_g, lnc_b, Wc, bc, out);
}

// round 8
// speedup vs baseline: 1.0003x; 1.0003x over previous
#include <cuda_runtime.h>
#include <math.h>

#define B_      128
#define EMB_    256
#define NTOK    394
#define MTOK    (B_ * NTOK)          // 50432
#define MPE     (B_ * 196)           // 25088

#define KC      32
#define STG     3
#define ASTR    36
#define BSTR    136
#define SMEM_NN ((STG * (128 * ASTR + 32 * BSTR)) * 4)
#define FA_SMEM ((64*132 + 2*64*132 + 2*64*136 + 64*68 + 256) * 4)   // 189440
#define FA_NKT  7

// ---------------- scratch ---------------------------------------------------
__device__ float g_T1[MPE * 768];
__device__ float g_T2[MPE * 192];
__device__ float g_Wt[507904];
__device__ float g_z [MTOK * EMB_];
__device__ float g_h [MTOK * EMB_];
__device__ float g_q [MTOK * EMB_];
__device__ float g_k [MTOK * EMB_];
__device__ float g_v [MTOK * EMB_];
__device__ float g_o [MTOK * EMB_];
__device__ float g_pool[B_ * 8 * EMB_];

#define OFF_W1 0
#define OFF_W2 196608
#define OFF_WQ 245760
#define OFF_WK 311296
#define OFF_WV 376832
#define OFF_WP 442368

// ---------------- helpers ----------------------------------------------------
__device__ __forceinline__ float f2tf_f(float f) {
    unsigned u; asm("cvt.rna.tf32.f32 %0, %1;" : "=r"(u) : "f"(f));
    return __uint_as_float(u);
}
__device__ __forceinline__ void mma8(float* acc, const unsigned* a, const unsigned* b) {
    asm volatile(
        "mma.sync.aligned.m16n8k8.row.col.f32.tf32.tf32.f32 "
        "{%0,%1,%2,%3}, {%4,%5,%6,%7}, {%8,%9}, {%0,%1,%2,%3};\n"
        : "+f"(acc[0]), "+f"(acc[1]), "+f"(acc[2]), "+f"(acc[3])
        : "r"(a[0]), "r"(a[1]), "r"(a[2]), "r"(a[3]), "r"(b[0]), "r"(b[1]));
}
__device__ __forceinline__ void cpa16(float* dst, const float* src, bool pred) {
    unsigned d = (unsigned)__cvta_generic_to_shared(dst);
    int sz = pred ? 16 : 0;
    asm volatile("cp.async.cg.shared.global [%0], [%1], 16, %2;\n"
                 :: "r"(d), "l"(src), "r"(sz));
}
__device__ __forceinline__ void cpa_commit() { asm volatile("cp.async.commit_group;\n"); }
template <int N>
__device__ __forceinline__ void cpa_wait() { asm volatile("cp.async.wait_group %0;\n" :: "n"(N)); }

// ---------------- weight prep ------------------------------------------------
__global__ void prep_w(const float* __restrict__ W1, const float* __restrict__ W2,
                       const float* __restrict__ Wq, const float* __restrict__ Wk,
                       const float* __restrict__ Wv, const float* __restrict__ Wp,
                       float* __restrict__ out) {
    int i = blockIdx.x * 256 + threadIdx.x;
    const float* src; int j;
    if (i < OFF_W2)      { src = W1; j = i; }
    else if (i < OFF_WQ) { src = W2; j = i - OFF_W2; }
    else if (i < OFF_WK) { src = Wq; j = i - OFF_WQ; }
    else if (i < OFF_WV) { src = Wk; j = i - OFF_WK; }
    else if (i < OFF_WP) { src = Wv; j = i - OFF_WV; }
    else                 { src = Wp; j = i - OFF_WP; }
    out[i] = f2tf_f(src[j]);
}

// ---------------- im2col ------------------------------------------------------
__global__ void im2col1(const float* __restrict__ x, float* __restrict__ T) {
    __shared__ float buf[768];
    int j = blockIdx.x, b = blockIdx.y;
    int ph = j / 14, pw = j % 14;
    const float* xb = x + (size_t)b * 3 * 224 * 224 + (size_t)(ph * 16) * 224 + pw * 16;
    int t = threadIdx.x;
    int pi = t >> 4, pj = t & 15;
#pragma unroll
    for (int c = 0; c < 3; c++)
        buf[(pi * 16 + pj) * 3 + c] = f2tf_f(xb[((size_t)c * 224 + pi) * 224 + pj]);
    __syncthreads();
    float* Tr = T + ((size_t)b * 196 + j) * 768;
#pragma unroll
    for (int k = 0; k < 3; k++) Tr[t + k * 256] = buf[t + k * 256];
}
__global__ void im2col2(const float* __restrict__ x, float* __restrict__ T) {
    __shared__ float buf[192];
    int i = blockIdx.x, b = blockIdx.y;
    int jdx = 4 * i + 3;
    int ph = jdx / 28, pw = jdx % 28;
    const float* xb = x + (size_t)b * 3 * 224 * 224 + (size_t)(ph * 8) * 224 + pw * 8;
    int t = threadIdx.x;
    int c = t >> 6, pos = t & 63;
    int pi = pos >> 3, pj = pos & 7;
    buf[pos * 3 + c] = f2tf_f(xb[((size_t)c * 224 + pi) * 224 + pj]);
    __syncthreads();
    T[((size_t)b * 196 + i) * 192 + t] = buf[t];
}
__global__ void cls_fill(const float* __restrict__ cls1,
                         const float* __restrict__ cls2,
                         float* __restrict__ z) {
    int b = blockIdx.x, e = threadIdx.x;
    z[((size_t)b * NTOK + 0)   * EMB_ + e] = cls2[e];
    z[((size_t)b * NTOK + 197) * EMB_ + e] = cls1[e];
}

// ---------------- NN GEMM (cp.async 3-stage, 128x128) -------------------------
// mode 0: plain  1: patch1->z  2: patch2->z  3: qkv (cvt)
__global__ __launch_bounds__(256)
void gemm_nn(const float* __restrict__ A, const float* __restrict__ Bm,
             const float* __restrict__ bias, float* __restrict__ C,
             int M, int N, int K, int mode) {
    extern __shared__ float smem[];
    float* As = smem;
    float* Bs = smem + STG * 128 * ASTR;
    int tid = threadIdx.x;
    int bm = blockIdx.y * 128, bn = blockIdx.x * 128;
    int wid = tid >> 5, lane = tid & 31;
    int wm = wid & 3, wn = wid >> 2;
    int gid = lane >> 2, tg = lane & 3;
    int aRow = tid >> 3, aC4 = (tid & 7) << 2;

    auto loadA = [&](int s, int k0) {
        float* dst = As + s * 128 * ASTR;
#pragma unroll
        for (int i = 0; i < 4; i++) {
            int row = aRow + i * 32;
            bool p = (bm + row) < M;
            const float* src = A + (size_t)(p ? bm + row : bm) * K + k0 + aC4;
            cpa16(dst + row * ASTR + aC4, src, p);
        }
    };
    auto loadB = [&](int s, int k0) {
        float* dst = Bs + s * 32 * BSTR;
#pragma unroll
        for (int i = 0; i < 4; i++) {
            int idx = tid + i * 256;
            int kr = idx >> 5, c4 = (idx & 31) << 2;
            bool p = (k0 + kr) < K;
            const float* src = Bm + (size_t)(p ? k0 + kr : 0) * N + bn + c4;
            cpa16(dst + kr * BSTR + c4, src, p);
        }
    };

    float acc[2][8][4] = {};
    int nk = K / KC;
#pragma unroll
    for (int s = 0; s < STG - 1; s++) { loadA(s, s * KC); loadB(s, s * KC); cpa_commit(); }

    for (int it = 0; it < nk; it++) {
        cpa_wait<STG - 2>();
        __syncthreads();
        int nxt = it + STG - 1;
        if (nxt < nk) { loadA(nxt % STG, nxt * KC); loadB(nxt % STG, nxt * KC); }
        cpa_commit();
        int s = it % STG;
        const float* ap = As + s * 128 * ASTR + (wm * 32 + gid) * ASTR + tg;
        const float* bp = Bs + s * 32 * BSTR + tg * BSTR + wn * 64 + gid;
#pragma unroll
        for (int kk = 0; kk < KC; kk += 8) {
            unsigned af[2][4], bf[8][2];
#pragma unroll
            for (int mt = 0; mt < 2; mt++) {
                af[mt][0] = __float_as_uint(ap[mt * 16 * ASTR + kk]);
                af[mt][1] = __float_as_uint(ap[(mt * 16 + 8) * ASTR + kk]);
                af[mt][2] = __float_as_uint(ap[mt * 16 * ASTR + kk + 4]);
                af[mt][3] = __float_as_uint(ap[(mt * 16 + 8) * ASTR + kk + 4]);
            }
#pragma unroll
            for (int nt = 0; nt < 8; nt++) {
                bf[nt][0] = __float_as_uint(bp[kk * BSTR + nt * 8]);
                bf[nt][1] = __float_as_uint(bp[(kk + 4) * BSTR + nt * 8]);
            }
#pragma unroll
            for (int mt = 0; mt < 2; mt++)
#pragma unroll
                for (int nt = 0; nt < 8; nt++)
                    mma8(acc[mt][nt], af[mt], bf[nt]);
        }
        __syncthreads();
    }

#pragma unroll
    for (int mt = 0; mt < 2; mt++) {
#pragma unroll
        for (int nt = 0; nt < 8; nt++) {
            int n = bn + wn * 64 + nt * 8 + tg * 2;
            float bv0 = bias ? bias[n] : 0.f;
            float bv1 = bias ? bias[n + 1] : 0.f;
#pragma unroll
            for (int half = 0; half < 2; half++) {
                int m = bm + wm * 32 + mt * 16 + gid + half * 8;
                if (m >= M) continue;
                float v0 = acc[mt][nt][half * 2 + 0] + bv0;
                float v1 = acc[mt][nt][half * 2 + 1] + bv1;
                if (mode == 3) { v0 = f2tf_f(v0); v1 = f2tf_f(v1); }
                float2 val = make_float2(v0, v1);
                if (mode == 0) {
                    *(float2*)&C[(size_t)m * N + n] = val;
                } else if (mode == 1) {
                    int b = m / 196, jj = m % 196;
                    *(float2*)&C[((size_t)b * NTOK + 198 + jj) * EMB_ + n] = val;
                } else if (mode == 2) {
                    int b = m / 196, jj = m % 196;
                    *(float2*)&C[((size_t)b * NTOK + 1 + jj) * EMB_ + n] = val;
                } else {
                    int b = m / NTOK, t = m % NTOK;
                    int hh = n >> 7, d = n & 127;
                    *(float2*)&C[(((size_t)b * 2 + hh) * NTOK + t) * 128 + d] = val;
                }
            }
        }
    }
}

// ---------------- flash attention (cross-warp-correct online softmax) --------
__global__ __launch_bounds__(256)
void flash_attn(const float* __restrict__ Qg, const float* __restrict__ Kg,
                const float* __restrict__ Vg, float* __restrict__ Og) {
    extern __shared__ float smem[];
    float* Qs = smem;                       // [64][132]
    float* Ks = Qs + 64 * 132;              // [2][64][132]
    float* Vs = Ks + 2 * 64 * 132;          // [2][64][136]
    float* Ps = Vs + 2 * 64 * 136;          // [64][68]
    float* redM = Ps + 64 * 68;             // [64][2]
    float* redS = redM + 128;               // [64][2]
    int tid = threadIdx.x, lane = tid & 31, wid = tid >> 5;
    int wm = wid & 3, wn = wid >> 2;
    int gid = lane >> 2, tg = lane & 3;
    int qt = blockIdx.x, bh = blockIdx.y;
    const float* Qb = Qg + (size_t)bh * 394 * 128;
    const float* Kb = Kg + (size_t)bh * 394 * 128;
    const float* Vb = Vg + (size_t)bh * 394 * 128;
    float* Ob = Og + (size_t)(bh >> 1) * NTOK * EMB_ + (bh & 1) * 128;
    int qbase = qt * 64;
    int r0 = wm * 16 + gid, r1 = r0 + 8;    // S-tile rows owned by this thread

    auto loadQ = [&]() {
#pragma unroll
        for (int i = 0; i < 8; i++) {
            int idx = tid + i * 256; int row = idx >> 5; int cc = (idx & 31) << 2;
            bool p = (qbase + row) < 394;
            cpa16(Qs + row * 132 + cc, Qb + (size_t)(p ? qbase + row : 0) * 128 + cc, p);
        }
    };
    auto loadK = [&](int st, int kt) {
        float* dst = Ks + st * 64 * 132;
#pragma unroll
        for (int i = 0; i < 8; i++) {
            int idx = tid + i * 256; int row = idx >> 5; int cc = (idx & 31) << 2;
            bool p = (kt * 64 + row) < 394;
            cpa16(dst + row * 132 + cc, Kb + (size_t)(p ? kt * 64 + row : 0) * 128 + cc, p);
        }
    };
    auto loadV = [&](int st, int kt) {
        float* dst = Vs + st * 64 * 136;
#pragma unroll
        for (int i = 0; i < 8; i++) {
            int idx = tid + i * 256; int row = idx >> 5; int cc = (idx & 31) << 2;
            bool p = (kt * 64 + row) < 394;
            cpa16(dst + row * 136 + cc, Vb + (size_t)(p ? kt * 64 + row : 0) * 128 + cc, p);
        }
    };

    loadQ(); loadK(0, 0); loadV(0, 0); cpa_commit();
    loadK(1, 1); loadV(1, 1); cpa_commit();

    float accO[8][4] = {};
    float m0 = -1e30f, m1 = -1e30f, l0 = 0.f, l1 = 0.f;

    for (int kt = 0; kt < FA_NKT; kt++) {
        int st = kt & 1;
        cpa_wait<1>();
        __syncthreads();

        // ---- S = Q @ K^T : warp covers rows [wm*16,+16), cols [wn*32,+32) ----
        float accS[4][4] = {};
        const float* qp = Qs + r0 * 132 + tg;
        const float* kp = Ks + st * 64 * 132 + (wn * 32 + gid) * 132 + tg;
#pragma unroll
        for (int kk = 0; kk < 128; kk += 8) {
            unsigned af[4];
            af[0] = __float_as_uint(qp[kk]);
            af[1] = __float_as_uint(qp[8 * 132 + kk]);
            af[2] = __float_as_uint(qp[kk + 4]);
            af[3] = __float_as_uint(qp[8 * 132 + kk + 4]);
#pragma unroll
            for (int nt = 0; nt < 4; nt++) {
                unsigned bf[2];
                bf[0] = __float_as_uint(kp[nt * 8 * 132 + kk]);
                bf[1] = __float_as_uint(kp[nt * 8 * 132 + kk + 4]);
                mma8(accS[nt], af, bf);
            }
        }
        // mask cols >= 394
        int cbase = kt * 64 + wn * 32 + tg * 2;
#pragma unroll
        for (int nt = 0; nt < 4; nt++) {
            int c0 = cbase + nt * 8;
            if (c0 >= 394)     { accS[nt][0] = -1e30f; accS[nt][2] = -1e30f; }
            if (c0 + 1 >= 394) { accS[nt][1] = -1e30f; accS[nt][3] = -1e30f; }
        }
        // ---- warp-local (32-col) max ----
        float rm0 = -1e30f, rm1 = -1e30f;
#pragma unroll
        for (int nt = 0; nt < 4; nt++) {
            rm0 = fmaxf(rm0, fmaxf(accS[nt][0], accS[nt][1]));
            rm1 = fmaxf(rm1, fmaxf(accS[nt][2], accS[nt][3]));
        }
        rm0 = fmaxf(rm0, __shfl_xor_sync(0xffffffff, rm0, 1));
        rm0 = fmaxf(rm0, __shfl_xor_sync(0xffffffff, rm0, 2));
        rm1 = fmaxf(rm1, __shfl_xor_sync(0xffffffff, rm1, 1));
        rm1 = fmaxf(rm1, __shfl_xor_sync(0xffffffff, rm1, 2));
        // ---- local exp + local sum (vs local max) ----
        float rs0 = 0.f, rs1 = 0.f;
#pragma unroll
        for (int nt = 0; nt < 4; nt++) {
            accS[nt][0] = __expf(accS[nt][0] - rm0);
            accS[nt][1] = __expf(accS[nt][1] - rm0);
            accS[nt][2] = __expf(accS[nt][2] - rm1);
            accS[nt][3] = __expf(accS[nt][3] - rm1);
            rs0 += accS[nt][0] + accS[nt][1];
            rs1 += accS[nt][2] + accS[nt][3];
        }
        rs0 += __shfl_xor_sync(0xffffffff, rs0, 1);
        rs0 += __shfl_xor_sync(0xffffffff, rs0, 2);
        rs1 += __shfl_xor_sync(0xffffffff, rs1, 1);
        rs1 += __shfl_xor_sync(0xffffffff, rs1, 2);
        // ---- publish (max,sum) per row per wn half; merge globally ----
        if (tg == 0) {
            redM[r0 * 2 + wn] = rm0;  redS[r0 * 2 + wn] = rs0;
            redM[r1 * 2 + wn] = rm1;  redS[r1 * 2 + wn] = rs1;
        }
        __syncthreads();
        float a0 = redM[r0 * 2], a1 = redM[r0 * 2 + 1];
        float gm0 = fmaxf(a0, a1);
        float gs0 = redS[r0 * 2] * __expf(a0 - gm0) + redS[r0 * 2 + 1] * __expf(a1 - gm0);
        float b0v = redM[r1 * 2], b1v = redM[r1 * 2 + 1];
        float gm1 = fmaxf(b0v, b1v);
        float gs1 = redS[r1 * 2] * __expf(b0v - gm1) + redS[r1 * 2 + 1] * __expf(b1v - gm1);
        // ---- online update ----
        float mn0 = fmaxf(m0, gm0), mn1 = fmaxf(m1, gm1);
        float sc0 = __expf(m0 - mn0), sc1 = __expf(m1 - mn1);
        l0 = l0 * sc0 + gs0 * __expf(gm0 - mn0);
        l1 = l1 * sc1 + gs1 * __expf(gm1 - mn1);
        m0 = mn0;  m1 = mn1;
        float fw0 = __expf(rm0 - mn0), fw1 = __expf(rm1 - mn1);  // P correction
#pragma unroll
        for (int nt = 0; nt < 8; nt++) {
            accO[nt][0] *= sc0; accO[nt][1] *= sc0;
            accO[nt][2] *= sc1; accO[nt][3] *= sc1;
        }
        // ---- stage P (corrected to global max scale) ----
        float* pw = Ps + r0 * 68 + wn * 32 + tg * 2;
#pragma unroll
        for (int nt = 0; nt < 4; nt++) {
            *(float2*)&pw[nt * 8] =
                make_float2(f2tf_f(accS[nt][0] * fw0), f2tf_f(accS[nt][1] * fw0));
            *(float2*)&pw[8 * 68 + nt * 8] =
                make_float2(f2tf_f(accS[nt][2] * fw1), f2tf_f(accS[nt][3] * fw1));
        }
        __syncthreads();
        // ---- O += P @ V ----
        const float* pp = Ps + r0 * 68 + tg;
        const float* vp = Vs + st * 64 * 136 + tg * 136 + wn * 64 + gid;
#pragma unroll
        for (int kk = 0; kk < 64; kk += 8) {
            unsigned af[4];
            af[0] = __float_as_uint(pp[kk]);
            af[1] = __float_as_uint(pp[8 * 68 + kk]);
            af[2] = __float_as_uint(pp[kk + 4]);
            af[3] = __float_as_uint(pp[8 * 68 + kk + 4]);
#pragma unroll
            for (int nt = 0; nt < 8; nt++) {
                unsigned bf[2];
                bf[0] = __float_as_uint(vp[kk * 136 + nt * 8]);
                bf[1] = __float_as_uint(vp[(kk + 4) * 136 + nt * 8]);
                mma8(accO[nt], af, bf);
            }
        }
        __syncthreads();
        if (kt + 2 < FA_NKT) { loadK(st, kt + 2); loadV(st, kt + 2); }
        cpa_commit();
    }

    float inv0 = 1.f / (l0 * 16.f), inv1 = 1.f / (l1 * 16.f);
    int gr0 = qbase + r0, gr1 = qbase + r1;
#pragma unroll
    for (int nt = 0; nt < 8; nt++) {
        int col = wn * 64 + nt * 8 + tg * 2;
        if (gr0 < 394)
            *(float2*)&Ob[(size_t)gr0 * EMB_ + col] =
                make_float2(f2tf_f(accO[nt][0] * inv0), f2tf_f(accO[nt][1] * inv0));
        if (gr1 < 394)
            *(float2*)&Ob[(size_t)gr1 * EMB_ + col] =
                make_float2(f2tf_f(accO[nt][2] * inv1), f2tf_f(accO[nt][3] * inv1));
    }
}

// ---------------- layer norm --------------------------------------------------
__global__ __launch_bounds__(256)
void ln_kernel(const float* __restrict__ in, const float* __restrict__ g,
               const float* __restrict__ b, float* __restrict__ out,
               const float* __restrict__ addsrc, int docvt) {
    int r = blockIdx.x, e = threadIdx.x;
    size_t idx = (size_t)r * EMB_ + e;
    float v = in[idx];
    float s = v, s2 = v * v;
#pragma unroll
    for (int off = 16; off > 0; off >>= 1) {
        s  += __shfl_xor_sync(0xffffffff, s,  off);
        s2 += __shfl_xor_sync(0xffffffff, s2, off);
    }
    __shared__ float ss[8], ss2[8];
    if ((e & 31) == 0) { ss[e >> 5] = s; ss2[e >> 5] = s2; }
    __syncthreads();
    float tot = 0.f, tot2 = 0.f;
#pragma unroll
    for (int i = 0; i < 8; i++) { tot += ss[i]; tot2 += ss2[i]; }
    float mean = tot * (1.f / EMB_);
    float var = tot2 * (1.f / EMB_) - mean * mean;
    float nv = (v - mean) * rsqrtf(var + 1e-5f) * g[e] + b[e];
    if (docvt) nv = f2tf_f(nv);
    out[idx] = addsrc ? (addsrc[idx] + nv) : nv;
}

// ---------------- two-stage pool + head ---------------------------------------
__global__ __launch_bounds__(256)
void pool_partial(const float* __restrict__ z, float* __restrict__ pool) {
    int b = blockIdx.x, seg = blockIdx.y, e = threadIdx.x;
    int t0 = seg * 50;
    int t1 = t0 + 50; if (t1 > 394) t1 = 394;
    const float* zb = z + (size_t)b * NTOK * EMB_;
    float s = 0.f;
    for (int t = t0; t < t1; t++) s += zb[(size_t)t * EMB_ + e];
    pool[((size_t)b * 8 + seg) * EMB_ + e] = s;
}

__global__ __launch_bounds__(256)
void head_kernel(const float* __restrict__ pool, const float* __restrict__ g,
                 const float* __restrict__ bb, const float* __restrict__ Wc,
                 const float* __restrict__ bc, float* __restrict__ out) {
    int b = blockIdx.x, e = threadIdx.x;
    float s = 0.f;
#pragma unroll
    for (int i = 0; i < 8; i++) s += pool[((size_t)b * 8 + i) * EMB_ + e];
    float pooled = s * (1.f / NTOK);
    __shared__ float red[256];
    red[e] = pooled; __syncthreads();
    for (int st = 128; st > 0; st >>= 1) { if (e < st) red[e] += red[e + st]; __syncthreads(); }
    float mean = red[0] * (1.f / EMB_);
    __syncthreads();
    float d = pooled - mean;
    red[e] = d * d; __syncthreads();
    for (int st = 128; st > 0; st >>= 1) { if (e < st) red[e] += red[e + st]; __syncthreads(); }
    float var = red[0] * (1.f / EMB_);
    __syncthreads();
    float nv = d * rsqrtf(var + 1e-5f) * g[e] + bb[e];
    red[e] = nv * Wc[e * 2 + 0]; __syncthreads();
    for (int st = 128; st > 0; st >>= 1) { if (e < st) red[e] += red[e + st]; __syncthreads(); }
    float l0 = red[0] + bc[0];
    __syncthreads();
    red[e] = nv * Wc[e * 2 + 1]; __syncthreads();
    for (int st = 128; st > 0; st >>= 1) { if (e < st) red[e] += red[e + st]; __syncthreads(); }
    float l1 = red[0] + bc[1];
    if (e == 0) {
        float mx = fmaxf(l0, l1);
        float lse = mx + logf(expf(l0 - mx) + expf(l1 - mx));
        out[b * 2 + 0] = l0 - lse;
        out[b * 2 + 1] = l1 - lse;
    }
}

// ---------------- launch --------------------------------------------------------
extern "C" void kernel_launch(void* const* d_in, const int* in_sizes, int n_in,
                              void* d_out, int out_size) {
    const float* x     = (const float*)d_in[0];
    const float* W1    = (const float*)d_in[1];
    const float* b1    = (const float*)d_in[2];
    const float* cls1  = (const float*)d_in[3];
    const float* W2    = (const float*)d_in[4];
    const float* b2    = (const float*)d_in[5];
    const float* cls2  = (const float*)d_in[6];
    const float* ln1_g = (const float*)d_in[7];
    const float* ln1_b = (const float*)d_in[8];
    const float* Wq    = (const float*)d_in[9];
    const float* bq    = (const float*)d_in[10];
    const float* Wk    = (const float*)d_in[11];
    const float* bk    = (const float*)d_in[12];
    const float* Wv    = (const float*)d_in[13];
    const float* bv    = (const float*)d_in[14];
    const float* Wp    = (const float*)d_in[15];
    const float* bp    = (const float*)d_in[16];
    const float* ln2_g = (const float*)d_in[17];
    const float* ln2_b = (const float*)d_in[18];
    const float* lnc_g = (const float*)d_in[19];
    const float* lnc_b = (const float*)d_in[20];
    const float* Wc    = (const float*)d_in[21];
    const float* bc    = (const float*)d_in[22];
    float* out = (float*)d_out;

    static int inited = 0;
    if (!inited) {
        cudaFuncSetAttribute(gemm_nn, cudaFuncAttributeMaxDynamicSharedMemorySize, SMEM_NN);
        cudaFuncSetAttribute(flash_attn, cudaFuncAttributeMaxDynamicSharedMemorySize, FA_SMEM);
        inited = 1;
    }

    float *T1, *T2, *Wt, *z, *h, *q, *k, *v, *o, *pool;
    cudaGetSymbolAddress((void**)&T1, g_T1);
    cudaGetSymbolAddress((void**)&T2, g_T2);
    cudaGetSymbolAddress((void**)&Wt, g_Wt);
    cudaGetSymbolAddress((void**)&z,  g_z);
    cudaGetSymbolAddress((void**)&h,  g_h);
    cudaGetSymbolAddress((void**)&q,  g_q);
    cudaGetSymbolAddress((void**)&k,  g_k);
    cudaGetSymbolAddress((void**)&v,  g_v);
    cudaGetSymbolAddress((void**)&o,  g_o);
    cudaGetSymbolAddress((void**)&pool, g_pool);

    prep_w<<<507904 / 256, 256>>>(W1, W2, Wq, Wk, Wv, Wp, Wt);
    im2col1<<<dim3(196, B_), 256>>>(x, T1);
    im2col2<<<dim3(196, B_), 192>>>(x, T2);
    cls_fill<<<B_, 256>>>(cls1, cls2, z);

    gemm_nn<<<dim3(2, 196), 256, SMEM_NN>>>(T1, Wt + OFF_W1, b1, z, MPE, 256, 768, 1);
    gemm_nn<<<dim3(2, 196), 256, SMEM_NN>>>(T2, Wt + OFF_W2, b2, z, MPE, 256, 192, 2);

    ln_kernel<<<MTOK, 256>>>(z, ln1_g, ln1_b, h, nullptr, 1);

    gemm_nn<<<dim3(2, 394), 256, SMEM_NN>>>(h, Wt + OFF_WQ, bq, q, MTOK, 256, 256, 3);
    gemm_nn<<<dim3(2, 394), 256, SMEM_NN>>>(h, Wt + OFF_WK, bk, k, MTOK, 256, 256, 3);
    gemm_nn<<<dim3(2, 394), 256, SMEM_NN>>>(h, Wt + OFF_WV, bv, v, MTOK, 256, 256, 3);

    flash_attn<<<dim3(FA_NKT, 256), 256, FA_SMEM>>>(q, k, v, o);

    gemm_nn<<<dim3(2, 394), 256, SMEM_NN>>>(o, Wt + OFF_WP, bp, h, MTOK, 256, 256, 0);
    ln_kernel<<<MTOK, 256>>>(h, ln2_g, ln2_b, z, z, 0);

    pool_partial<<<dim3(B_, 8), 256>>>(z, pool);
    head_kernel<<<B_, 256>>>(pool, lnc_g, lnc_b, Wc, bc, out);
}

// round 9
// speedup vs baseline: 1.0743x; 1.0740x over previous
#include <cuda_runtime.h>
#include <math.h>

#define B_      128
#define EMB_    256
#define NTOK    394
#define MTOK    (B_ * NTOK)          // 50432
#define MPE     (B_ * 196)           // 25088

#define KC      32
#define STG     3
#define ASTR    36
#define BSTR    136
#define SMEM_NN ((STG * (128 * ASTR + 32 * BSTR)) * 4)
#define FA_SMEM ((64*132 + 2*64*132 + 2*64*136 + 64*68 + 256) * 4)   // 189440
#define FA_NKT  7

// ---------------- scratch ---------------------------------------------------
__device__ float g_T2[MPE * 192];
__device__ float g_Wt[507904];       // W2 | Wp | W1perm | Wqkv (all tf32)
__device__ float g_bqkv[768];
__device__ float g_z [MTOK * EMB_];
__device__ float g_h [MTOK * EMB_];
__device__ float g_qkv[3 * MTOK * EMB_];
__device__ float g_o [MTOK * EMB_];
__device__ float g_pool[B_ * 8 * EMB_];

#define OFF_W2   0
#define OFF_WP   49152
#define OFF_W1P  114688
#define OFF_WQKV 311296
#define PREP_N   508672              // 507904 weights + 768 bias

// ---------------- helpers ----------------------------------------------------
__device__ __forceinline__ float f2tf_f(float f) {
    unsigned u; asm("cvt.rna.tf32.f32 %0, %1;" : "=r"(u) : "f"(f));
    return __uint_as_float(u);
}
__device__ __forceinline__ void mma8(float* acc, const unsigned* a, const unsigned* b) {
    asm volatile(
        "mma.sync.aligned.m16n8k8.row.col.f32.tf32.tf32.f32 "
        "{%0,%1,%2,%3}, {%4,%5,%6,%7}, {%8,%9}, {%0,%1,%2,%3};\n"
        : "+f"(acc[0]), "+f"(acc[1]), "+f"(acc[2]), "+f"(acc[3])
        : "r"(a[0]), "r"(a[1]), "r"(a[2]), "r"(a[3]), "r"(b[0]), "r"(b[1]));
}
__device__ __forceinline__ void cpa16(float* dst, const float* src, bool pred) {
    unsigned d = (unsigned)__cvta_generic_to_shared(dst);
    int sz = pred ? 16 : 0;
    asm volatile("cp.async.cg.shared.global [%0], [%1], 16, %2;\n"
                 :: "r"(d), "l"(src), "r"(sz));
}
__device__ __forceinline__ void cpa_commit() { asm volatile("cp.async.commit_group;\n"); }
template <int N>
__device__ __forceinline__ void cpa_wait() { asm volatile("cp.async.wait_group %0;\n" :: "n"(N)); }

// ---------------- weight prep (tf32 rounding + layout transforms) -----------
__global__ void prep_w(const float* __restrict__ W1, const float* __restrict__ W2,
                       const float* __restrict__ Wq, const float* __restrict__ Wk,
                       const float* __restrict__ Wv, const float* __restrict__ Wp,
                       const float* __restrict__ bq, const float* __restrict__ bk,
                       const float* __restrict__ bv,
                       float* __restrict__ out, float* __restrict__ bqkv) {
    int i = blockIdx.x * 256 + threadIdx.x;
    if (i >= PREP_N) return;
    if (i < OFF_WP) {
        out[i] = f2tf_f(W2[i]);
    } else if (i < OFF_W1P) {
        out[i] = f2tf_f(Wp[i - OFF_WP]);
    } else if (i < OFF_WQKV) {
        // W1 permuted: k' = c*256 + pi*16 + pj  ->  src row r = (pi*16+pj)*3 + c
        int idx = i - OFF_W1P;
        int kp = idx >> 8, n = idx & 255;
        int c = kp >> 8;                 // kp/256
        int rem = kp & 255;
        int pi = rem >> 4, pj = rem & 15;
        int r = (pi * 16 + pj) * 3 + c;
        out[i] = f2tf_f(W1[r * 256 + n]);
    } else if (i < OFF_WQKV + 196608) {
        // Wqkv[k][n], n in [0,768): which = n>>8
        int idx = i - OFF_WQKV;
        int k = idx / 768, n = idx % 768;
        int which = n >> 8, col = n & 255;
        const float* src = which == 0 ? Wq : which == 1 ? Wk : Wv;
        out[i] = f2tf_f(src[k * 256 + col]);
    } else {
        int j = i - 507904;              // < 768
        int which = j >> 8, col = j & 255;
        const float* src = which == 0 ? bq : which == 1 ? bk : bv;
        bqkv[j] = src[col];
    }
}

// ---------------- im2col (p=8 sampled patches only) --------------------------
__global__ void im2col2(const float* __restrict__ x, float* __restrict__ T) {
    __shared__ float buf[192];
    int i = blockIdx.x, b = blockIdx.y;
    int jdx = 4 * i + 3;
    int ph = jdx / 28, pw = jdx % 28;
    const float* xb = x + (size_t)b * 3 * 224 * 224 + (size_t)(ph * 8) * 224 + pw * 8;
    int t = threadIdx.x;
    int c = t >> 6, pos = t & 63;
    int pi = pos >> 3, pj = pos & 7;
    buf[pos * 3 + c] = f2tf_f(xb[((size_t)c * 224 + pi) * 224 + pj]);
    __syncthreads();
    T[((size_t)b * 196 + i) * 192 + t] = buf[t];
}
__global__ void cls_fill(const float* __restrict__ cls1,
                         const float* __restrict__ cls2,
                         float* __restrict__ z) {
    int b = blockIdx.x, e = threadIdx.x;
    z[((size_t)b * NTOK + 0)   * EMB_ + e] = cls2[e];
    z[((size_t)b * NTOK + 197) * EMB_ + e] = cls1[e];
}

// ---------------- patch1 GEMM, implicit im2col from x ------------------------
// C rows: m = b*196 + j -> z token 198+j.  K=768 channel-major (c,pi,pj).
__global__ __launch_bounds__(256)
void gemm_pe1(const float* __restrict__ x, const float* __restrict__ Bm,
              const float* __restrict__ bias, float* __restrict__ C) {
    extern __shared__ float smem[];
    float* As = smem;
    float* Bs = smem + STG * 128 * ASTR;
    int tid = threadIdx.x;
    int bm = blockIdx.y * 128, bn = blockIdx.x * 128;
    int wid = tid >> 5, lane = tid & 31;
    int wm = wid & 3, wn = wid >> 2;
    int gid = lane >> 2, tg = lane & 3;
    int aRow = tid >> 3, aC4 = (tid & 7) << 2;
    int pj0 = aC4 & 15, gsel = aC4 >> 4;       // which 16-group within KC

    size_t rowb[4];
#pragma unroll
    for (int i = 0; i < 4; i++) {
        int m = bm + aRow + i * 32;
        int b = m / 196, j = m % 196;
        int ph = j / 14, pw = j % 14;
        rowb[i] = (size_t)b * 150528 + (size_t)(ph * 16) * 224 + pw * 16;
    }

    auto loadA = [&](int s, int k0) {
        float* dst = As + s * 128 * ASTR;
        int gidx = (k0 >> 4) + gsel;           // 0..47
        int c = gidx >> 4, pi = gidx & 15;
        size_t off = (size_t)c * 50176 + pi * 224 + pj0;
#pragma unroll
        for (int i = 0; i < 4; i++)
            cpa16(dst + (aRow + i * 32) * ASTR + aC4, x + rowb[i] + off, true);
    };
    auto loadB = [&](int s, int k0) {
        float* dst = Bs + s * 32 * BSTR;
#pragma unroll
        for (int i = 0; i < 4; i++) {
            int idx = tid + i * 256;
            int kr = idx >> 5, c4 = (idx & 31) << 2;
            cpa16(dst + kr * BSTR + c4, Bm + (size_t)(k0 + kr) * 256 + bn + c4, true);
        }
    };

    float acc[2][8][4] = {};
    const int nk = 768 / KC;                   // 24
#pragma unroll
    for (int s = 0; s < STG - 1; s++) { loadA(s, s * KC); loadB(s, s * KC); cpa_commit(); }

    for (int it = 0; it < nk; it++) {
        cpa_wait<STG - 2>();
        __syncthreads();
        int nxt = it + STG - 1;
        if (nxt < nk) { loadA(nxt % STG, nxt * KC); loadB(nxt % STG, nxt * KC); }
        cpa_commit();
        int s = it % STG;
        const float* ap = As + s * 128 * ASTR + (wm * 32 + gid) * ASTR + tg;
        const float* bp = Bs + s * 32 * BSTR + tg * BSTR + wn * 64 + gid;
#pragma unroll
        for (int kk = 0; kk < KC; kk += 8) {
            unsigned af[2][4], bf[8][2];
#pragma unroll
            for (int mt = 0; mt < 2; mt++) {
                af[mt][0] = __float_as_uint(ap[mt * 16 * ASTR + kk]);
                af[mt][1] = __float_as_uint(ap[(mt * 16 + 8) * ASTR + kk]);
                af[mt][2] = __float_as_uint(ap[mt * 16 * ASTR + kk + 4]);
                af[mt][3] = __float_as_uint(ap[(mt * 16 + 8) * ASTR + kk + 4]);
            }
#pragma unroll
            for (int nt = 0; nt < 8; nt++) {
                bf[nt][0] = __float_as_uint(bp[kk * BSTR + nt * 8]);
                bf[nt][1] = __float_as_uint(bp[(kk + 4) * BSTR + nt * 8]);
            }
#pragma unroll
            for (int mt = 0; mt < 2; mt++)
#pragma unroll
                for (int nt = 0; nt < 8; nt++)
                    mma8(acc[mt][nt], af[mt], bf[nt]);
        }
        __syncthreads();
    }

#pragma unroll
    for (int mt = 0; mt < 2; mt++)
#pragma unroll
        for (int nt = 0; nt < 8; nt++) {
            int n = bn + wn * 64 + nt * 8 + tg * 2;
            float bv0 = bias[n], bv1 = bias[n + 1];
#pragma unroll
            for (int half = 0; half < 2; half++) {
                int m = bm + wm * 32 + mt * 16 + gid + half * 8;
                int b = m / 196, jj = m % 196;
                *(float2*)&C[((size_t)b * NTOK + 198 + jj) * EMB_ + n] =
                    make_float2(acc[mt][nt][half * 2] + bv0,
                                acc[mt][nt][half * 2 + 1] + bv1);
            }
        }
}

// ---------------- NN GEMM (cp.async 3-stage, 128x128 tile) -------------------
// mode 0: plain   mode 2: patch2->z   mode 5: fused qkv (cvt)
__global__ __launch_bounds__(256)
void gemm_nn(const float* __restrict__ A, const float* __restrict__ Bm,
             const float* __restrict__ bias, float* __restrict__ C,
             int M, int N, int K, int mode) {
    extern __shared__ float smem[];
    float* As = smem;
    float* Bs = smem + STG * 128 * ASTR;
    int tid = threadIdx.x;
    int bm = blockIdx.y * 128, bn = blockIdx.x * 128;
    int wid = tid >> 5, lane = tid & 31;
    int wm = wid & 3, wn = wid >> 2;
    int gid = lane >> 2, tg = lane & 3;
    int aRow = tid >> 3, aC4 = (tid & 7) << 2;

    auto loadA = [&](int s, int k0) {
        float* dst = As + s * 128 * ASTR;
#pragma unroll
        for (int i = 0; i < 4; i++) {
            int row = aRow + i * 32;
            bool p = (bm + row) < M;
            const float* src = A + (size_t)(p ? bm + row : bm) * K + k0 + aC4;
            cpa16(dst + row * ASTR + aC4, src, p);
        }
    };
    auto loadB = [&](int s, int k0) {
        float* dst = Bs + s * 32 * BSTR;
#pragma unroll
        for (int i = 0; i < 4; i++) {
            int idx = tid + i * 256;
            int kr = idx >> 5, c4 = (idx & 31) << 2;
            bool p = (k0 + kr) < K;
            const float* src = Bm + (size_t)(p ? k0 + kr : 0) * N + bn + c4;
            cpa16(dst + kr * BSTR + c4, src, p);
        }
    };

    float acc[2][8][4] = {};
    int nk = K / KC;
#pragma unroll
    for (int s = 0; s < STG - 1; s++) { loadA(s, s * KC); loadB(s, s * KC); cpa_commit(); }

    for (int it = 0; it < nk; it++) {
        cpa_wait<STG - 2>();
        __syncthreads();
        int nxt = it + STG - 1;
        if (nxt < nk) { loadA(nxt % STG, nxt * KC); loadB(nxt % STG, nxt * KC); }
        cpa_commit();
        int s = it % STG;
        const float* ap = As + s * 128 * ASTR + (wm * 32 + gid) * ASTR + tg;
        const float* bp = Bs + s * 32 * BSTR + tg * BSTR + wn * 64 + gid;
#pragma unroll
        for (int kk = 0; kk < KC; kk += 8) {
            unsigned af[2][4], bf[8][2];
#pragma unroll
            for (int mt = 0; mt < 2; mt++) {
                af[mt][0] = __float_as_uint(ap[mt * 16 * ASTR + kk]);
                af[mt][1] = __float_as_uint(ap[(mt * 16 + 8) * ASTR + kk]);
                af[mt][2] = __float_as_uint(ap[mt * 16 * ASTR + kk + 4]);
                af[mt][3] = __float_as_uint(ap[(mt * 16 + 8) * ASTR + kk + 4]);
            }
#pragma unroll
            for (int nt = 0; nt < 8; nt++) {
                bf[nt][0] = __float_as_uint(bp[kk * BSTR + nt * 8]);
                bf[nt][1] = __float_as_uint(bp[(kk + 4) * BSTR + nt * 8]);
            }
#pragma unroll
            for (int mt = 0; mt < 2; mt++)
#pragma unroll
                for (int nt = 0; nt < 8; nt++)
                    mma8(acc[mt][nt], af[mt], bf[nt]);
        }
        __syncthreads();
    }

#pragma unroll
    for (int mt = 0; mt < 2; mt++) {
#pragma unroll
        for (int nt = 0; nt < 8; nt++) {
            int n = bn + wn * 64 + nt * 8 + tg * 2;
            float bv0 = bias ? bias[n] : 0.f;
            float bv1 = bias ? bias[n + 1] : 0.f;
#pragma unroll
            for (int half = 0; half < 2; half++) {
                int m = bm + wm * 32 + mt * 16 + gid + half * 8;
                if (m >= M) continue;
                float v0 = acc[mt][nt][half * 2 + 0] + bv0;
                float v1 = acc[mt][nt][half * 2 + 1] + bv1;
                if (mode == 5) { v0 = f2tf_f(v0); v1 = f2tf_f(v1); }
                float2 val = make_float2(v0, v1);
                if (mode == 0) {
                    *(float2*)&C[(size_t)m * N + n] = val;
                } else if (mode == 2) {
                    int b = m / 196, jj = m % 196;
                    *(float2*)&C[((size_t)b * NTOK + 1 + jj) * EMB_ + n] = val;
                } else {
                    // fused qkv: which = n>>8, then (b, h, t, d) layout
                    int b = m / NTOK, t = m % NTOK;
                    int which = n >> 8, d2 = n & 255;
                    int hh = d2 >> 7, dd = d2 & 127;
                    *(float2*)&C[(size_t)which * (MTOK * EMB_) +
                                 (((size_t)b * 2 + hh) * NTOK + t) * 128 + dd] = val;
                }
            }
        }
    }
}

// ---------------- flash attention (cross-warp-correct online softmax) --------
__global__ __launch_bounds__(256)
void flash_attn(const float* __restrict__ Qg, const float* __restrict__ Kg,
                const float* __restrict__ Vg, float* __restrict__ Og) {
    extern __shared__ float smem[];
    float* Qs = smem;                       // [64][132]
    float* Ks = Qs + 64 * 132;              // [2][64][132]
    float* Vs = Ks + 2 * 64 * 132;          // [2][64][136]
    float* Ps = Vs + 2 * 64 * 136;          // [64][68]
    float* redM = Ps + 64 * 68;             // [64][2]
    float* redS = redM + 128;               // [64][2]
    int tid = threadIdx.x, lane = tid & 31, wid = tid >> 5;
    int wm = wid & 3, wn = wid >> 2;
    int gid = lane >> 2, tg = lane & 3;
    int qt = blockIdx.x, bh = blockIdx.y;
    const float* Qb = Qg + (size_t)bh * 394 * 128;
    const float* Kb = Kg + (size_t)bh * 394 * 128;
    const float* Vb = Vg + (size_t)bh * 394 * 128;
    float* Ob = Og + (size_t)(bh >> 1) * NTOK * EMB_ + (bh & 1) * 128;
    int qbase = qt * 64;
    int r0 = wm * 16 + gid, r1 = r0 + 8;

    auto loadQ = [&]() {
#pragma unroll
        for (int i = 0; i < 8; i++) {
            int idx = tid + i * 256; int row = idx >> 5; int cc = (idx & 31) << 2;
            bool p = (qbase + row) < 394;
            cpa16(Qs + row * 132 + cc, Qb + (size_t)(p ? qbase + row : 0) * 128 + cc, p);
        }
    };
    auto loadK = [&](int st, int kt) {
        float* dst = Ks + st * 64 * 132;
#pragma unroll
        for (int i = 0; i < 8; i++) {
            int idx = tid + i * 256; int row = idx >> 5; int cc = (idx & 31) << 2;
            bool p = (kt * 64 + row) < 394;
            cpa16(dst + row * 132 + cc, Kb + (size_t)(p ? kt * 64 + row : 0) * 128 + cc, p);
        }
    };
    auto loadV = [&](int st, int kt) {
        float* dst = Vs + st * 64 * 136;
#pragma unroll
        for (int i = 0; i < 8; i++) {
            int idx = tid + i * 256; int row = idx >> 5; int cc = (idx & 31) << 2;
            bool p = (kt * 64 + row) < 394;
            cpa16(dst + row * 136 + cc, Vb + (size_t)(p ? kt * 64 + row : 0) * 128 + cc, p);
        }
    };

    loadQ(); loadK(0, 0); loadV(0, 0); cpa_commit();
    loadK(1, 1); loadV(1, 1); cpa_commit();

    float accO[8][4] = {};
    float m0 = -1e30f, m1 = -1e30f, l0 = 0.f, l1 = 0.f;

    for (int kt = 0; kt < FA_NKT; kt++) {
        int st = kt & 1;
        cpa_wait<1>();
        __syncthreads();

        float accS[4][4] = {};
        const float* qp = Qs + r0 * 132 + tg;
        const float* kp = Ks + st * 64 * 132 + (wn * 32 + gid) * 132 + tg;
#pragma unroll
        for (int kk = 0; kk < 128; kk += 8) {
            unsigned af[4];
            af[0] = __float_as_uint(qp[kk]);
            af[1] = __float_as_uint(qp[8 * 132 + kk]);
            af[2] = __float_as_uint(qp[kk + 4]);
            af[3] = __float_as_uint(qp[8 * 132 + kk + 4]);
#pragma unroll
            for (int nt = 0; nt < 4; nt++) {
                unsigned bf[2];
                bf[0] = __float_as_uint(kp[nt * 8 * 132 + kk]);
                bf[1] = __float_as_uint(kp[nt * 8 * 132 + kk + 4]);
                mma8(accS[nt], af, bf);
            }
        }
        int cbase = kt * 64 + wn * 32 + tg * 2;
#pragma unroll
        for (int nt = 0; nt < 4; nt++) {
            int c0 = cbase + nt * 8;
            if (c0 >= 394)     { accS[nt][0] = -1e30f; accS[nt][2] = -1e30f; }
            if (c0 + 1 >= 394) { accS[nt][1] = -1e30f; accS[nt][3] = -1e30f; }
        }
        float rm0 = -1e30f, rm1 = -1e30f;
#pragma unroll
        for (int nt = 0; nt < 4; nt++) {
            rm0 = fmaxf(rm0, fmaxf(accS[nt][0], accS[nt][1]));
            rm1 = fmaxf(rm1, fmaxf(accS[nt][2], accS[nt][3]));
        }
        rm0 = fmaxf(rm0, __shfl_xor_sync(0xffffffff, rm0, 1));
        rm0 = fmaxf(rm0, __shfl_xor_sync(0xffffffff, rm0, 2));
        rm1 = fmaxf(rm1, __shfl_xor_sync(0xffffffff, rm1, 1));
        rm1 = fmaxf(rm1, __shfl_xor_sync(0xffffffff, rm1, 2));
        float rs0 = 0.f, rs1 = 0.f;
#pragma unroll
        for (int nt = 0; nt < 4; nt++) {
            accS[nt][0] = __expf(accS[nt][0] - rm0);
            accS[nt][1] = __expf(accS[nt][1] - rm0);
            accS[nt][2] = __expf(accS[nt][2] - rm1);
            accS[nt][3] = __expf(accS[nt][3] - rm1);
            rs0 += accS[nt][0] + accS[nt][1];
            rs1 += accS[nt][2] + accS[nt][3];
        }
        rs0 += __shfl_xor_sync(0xffffffff, rs0, 1);
        rs0 += __shfl_xor_sync(0xffffffff, rs0, 2);
        rs1 += __shfl_xor_sync(0xffffffff, rs1, 1);
        rs1 += __shfl_xor_sync(0xffffffff, rs1, 2);
        if (tg == 0) {
            redM[r0 * 2 + wn] = rm0;  redS[r0 * 2 + wn] = rs0;
            redM[r1 * 2 + wn] = rm1;  redS[r1 * 2 + wn] = rs1;
        }
        __syncthreads();
        float a0 = redM[r0 * 2], a1 = redM[r0 * 2 + 1];
        float gm0 = fmaxf(a0, a1);
        float gs0 = redS[r0 * 2] * __expf(a0 - gm0) + redS[r0 * 2 + 1] * __expf(a1 - gm0);
        float b0v = redM[r1 * 2], b1v = redM[r1 * 2 + 1];
        float gm1 = fmaxf(b0v, b1v);
        float gs1 = redS[r1 * 2] * __expf(b0v - gm1) + redS[r1 * 2 + 1] * __expf(b1v - gm1);
        float mn0 = fmaxf(m0, gm0), mn1 = fmaxf(m1, gm1);
        float sc0 = __expf(m0 - mn0), sc1 = __expf(m1 - mn1);
        l0 = l0 * sc0 + gs0 * __expf(gm0 - mn0);
        l1 = l1 * sc1 + gs1 * __expf(gm1 - mn1);
        m0 = mn0;  m1 = mn1;
        float fw0 = __expf(rm0 - mn0), fw1 = __expf(rm1 - mn1);
#pragma unroll
        for (int nt = 0; nt < 8; nt++) {
            accO[nt][0] *= sc0; accO[nt][1] *= sc0;
            accO[nt][2] *= sc1; accO[nt][3] *= sc1;
        }
        float* pw = Ps + r0 * 68 + wn * 32 + tg * 2;
#pragma unroll
        for (int nt = 0; nt < 4; nt++) {
            *(float2*)&pw[nt * 8] =
                make_float2(f2tf_f(accS[nt][0] * fw0), f2tf_f(accS[nt][1] * fw0));
            *(float2*)&pw[8 * 68 + nt * 8] =
                make_float2(f2tf_f(accS[nt][2] * fw1), f2tf_f(accS[nt][3] * fw1));
        }
        __syncthreads();
        const float* pp = Ps + r0 * 68 + tg;
        const float* vp = Vs + st * 64 * 136 + tg * 136 + wn * 64 + gid;
#pragma unroll
        for (int kk = 0; kk < 64; kk += 8) {
            unsigned af[4];
            af[0] = __float_as_uint(pp[kk]);
            af[1] = __float_as_uint(pp[8 * 68 + kk]);
            af[2] = __float_as_uint(pp[kk + 4]);
            af[3] = __float_as_uint(pp[8 * 68 + kk + 4]);
#pragma unroll
            for (int nt = 0; nt < 8; nt++) {
                unsigned bf[2];
                bf[0] = __float_as_uint(vp[kk * 136 + nt * 8]);
                bf[1] = __float_as_uint(vp[(kk + 4) * 136 + nt * 8]);
                mma8(accO[nt], af, bf);
            }
        }
        __syncthreads();
        if (kt + 2 < FA_NKT) { loadK(st, kt + 2); loadV(st, kt + 2); }
        cpa_commit();
    }

    float inv0 = 1.f / (l0 * 16.f), inv1 = 1.f / (l1 * 16.f);
    int gr0 = qbase + r0, gr1 = qbase + r1;
#pragma unroll
    for (int nt = 0; nt < 8; nt++) {
        int col = wn * 64 + nt * 8 + tg * 2;
        if (gr0 < 394)
            *(float2*)&Ob[(size_t)gr0 * EMB_ + col] =
                make_float2(f2tf_f(accO[nt][0] * inv0), f2tf_f(accO[nt][1] * inv0));
        if (gr1 < 394)
            *(float2*)&Ob[(size_t)gr1 * EMB_ + col] =
                make_float2(f2tf_f(accO[nt][2] * inv1), f2tf_f(accO[nt][3] * inv1));
    }
}

// ---------------- layer norm --------------------------------------------------
__global__ __launch_bounds__(256)
void ln_kernel(const float* __restrict__ in, const float* __restrict__ g,
               const float* __restrict__ b, float* __restrict__ out,
               const float* __restrict__ addsrc, int docvt) {
    int r = blockIdx.x, e = threadIdx.x;
    size_t idx = (size_t)r * EMB_ + e;
    float v = in[idx];
    float s = v, s2 = v * v;
#pragma unroll
    for (int off = 16; off > 0; off >>= 1) {
        s  += __shfl_xor_sync(0xffffffff, s,  off);
        s2 += __shfl_xor_sync(0xffffffff, s2, off);
    }
    __shared__ float ss[8], ss2[8];
    if ((e & 31) == 0) { ss[e >> 5] = s; ss2[e >> 5] = s2; }
    __syncthreads();
    float tot = 0.f, tot2 = 0.f;
#pragma unroll
    for (int i = 0; i < 8; i++) { tot += ss[i]; tot2 += ss2[i]; }
    float mean = tot * (1.f / EMB_);
    float var = tot2 * (1.f / EMB_) - mean * mean;
    float nv = (v - mean) * rsqrtf(var + 1e-5f) * g[e] + b[e];
    if (docvt) nv = f2tf_f(nv);
    out[idx] = addsrc ? (addsrc[idx] + nv) : nv;
}

// ---------------- two-stage pool + head ---------------------------------------
__global__ __launch_bounds__(256)
void pool_partial(const float* __restrict__ z, float* __restrict__ pool) {
    int b = blockIdx.x, seg = blockIdx.y, e = threadIdx.x;
    int t0 = seg * 50;
    int t1 = t0 + 50; if (t1 > 394) t1 = 394;
    const float* zb = z + (size_t)b * NTOK * EMB_;
    float s = 0.f;
    for (int t = t0; t < t1; t++) s += zb[(size_t)t * EMB_ + e];
    pool[((size_t)b * 8 + seg) * EMB_ + e] = s;
}

__global__ __launch_bounds__(256)
void head_kernel(const float* __restrict__ pool, const float* __restrict__ g,
                 const float* __restrict__ bb, const float* __restrict__ Wc,
                 const float* __restrict__ bc, float* __restrict__ out) {
    int b = blockIdx.x, e = threadIdx.x;
    float s = 0.f;
#pragma unroll
    for (int i = 0; i < 8; i++) s += pool[((size_t)b * 8 + i) * EMB_ + e];
    float pooled = s * (1.f / NTOK);
    __shared__ float red[256];
    red[e] = pooled; __syncthreads();
    for (int st = 128; st > 0; st >>= 1) { if (e < st) red[e] += red[e + st]; __syncthreads(); }
    float mean = red[0] * (1.f / EMB_);
    __syncthreads();
    float d = pooled - mean;
    red[e] = d * d; __syncthreads();
    for (int st = 128; st > 0; st >>= 1) { if (e < st) red[e] += red[e + st]; __syncthreads(); }
    float var = red[0] * (1.f / EMB_);
    __syncthreads();
    float nv = d * rsqrtf(var + 1e-5f) * g[e] + bb[e];
    red[e] = nv * Wc[e * 2 + 0]; __syncthreads();
    for (int st = 128; st > 0; st >>= 1) { if (e < st) red[e] += red[e + st]; __syncthreads(); }
    float l0 = red[0] + bc[0];
    __syncthreads();
    red[e] = nv * Wc[e * 2 + 1]; __syncthreads();
    for (int st = 128; st > 0; st >>= 1) { if (e < st) red[e] += red[e + st]; __syncthreads(); }
    float l1 = red[0] + bc[1];
    if (e == 0) {
        float mx = fmaxf(l0, l1);
        float lse = mx + logf(expf(l0 - mx) + expf(l1 - mx));
        out[b * 2 + 0] = l0 - lse;
        out[b * 2 + 1] = l1 - lse;
    }
}

// ---------------- launch --------------------------------------------------------
extern "C" void kernel_launch(void* const* d_in, const int* in_sizes, int n_in,
                              void* d_out, int out_size) {
    const float* x     = (const float*)d_in[0];
    const float* W1    = (const float*)d_in[1];
    const float* b1    = (const float*)d_in[2];
    const float* cls1  = (const float*)d_in[3];
    const float* W2    = (const float*)d_in[4];
    const float* b2    = (const float*)d_in[5];
    const float* cls2  = (const float*)d_in[6];
    const float* ln1_g = (const float*)d_in[7];
    const float* ln1_b = (const float*)d_in[8];
    const float* Wq    = (const float*)d_in[9];
    const float* bq    = (const float*)d_in[10];
    const float* Wk    = (const float*)d_in[11];
    const float* bk    = (const float*)d_in[12];
    const float* Wv    = (const float*)d_in[13];
    const float* bv    = (const float*)d_in[14];
    const float* Wp    = (const float*)d_in[15];
    const float* bp    = (const float*)d_in[16];
    const float* ln2_g = (const float*)d_in[17];
    const float* ln2_b = (const float*)d_in[18];
    const float* lnc_g = (const float*)d_in[19];
    const float* lnc_b = (const float*)d_in[20];
    const float* Wc    = (const float*)d_in[21];
    const float* bc    = (const float*)d_in[22];
    float* out = (float*)d_out;

    static int inited = 0;
    if (!inited) {
        cudaFuncSetAttribute(gemm_nn,  cudaFuncAttributeMaxDynamicSharedMemorySize, SMEM_NN);
        cudaFuncSetAttribute(gemm_pe1, cudaFuncAttributeMaxDynamicSharedMemorySize, SMEM_NN);
        cudaFuncSetAttribute(flash_attn, cudaFuncAttributeMaxDynamicSharedMemorySize, FA_SMEM);
        inited = 1;
    }

    float *T2, *Wt, *bqkv, *z, *h, *qkv, *o, *pool;
    cudaGetSymbolAddress((void**)&T2, g_T2);
    cudaGetSymbolAddress((void**)&Wt, g_Wt);
    cudaGetSymbolAddress((void**)&bqkv, g_bqkv);
    cudaGetSymbolAddress((void**)&z,  g_z);
    cudaGetSymbolAddress((void**)&h,  g_h);
    cudaGetSymbolAddress((void**)&qkv, g_qkv);
    cudaGetSymbolAddress((void**)&o,  g_o);
    cudaGetSymbolAddress((void**)&pool, g_pool);

    prep_w<<<(PREP_N + 255) / 256, 256>>>(W1, W2, Wq, Wk, Wv, Wp, bq, bk, bv, Wt, bqkv);
    im2col2<<<dim3(196, B_), 192>>>(x, T2);
    cls_fill<<<B_, 256>>>(cls1, cls2, z);

    gemm_pe1<<<dim3(2, 196), 256, SMEM_NN>>>(x, Wt + OFF_W1P, b1, z);
    gemm_nn<<<dim3(2, 196), 256, SMEM_NN>>>(T2, Wt + OFF_W2, b2, z, MPE, 256, 192, 2);

    ln_kernel<<<MTOK, 256>>>(z, ln1_g, ln1_b, h, nullptr, 1);

    gemm_nn<<<dim3(6, 394), 256, SMEM_NN>>>(h, Wt + OFF_WQKV, bqkv, qkv, MTOK, 768, 256, 5);

    flash_attn<<<dim3(FA_NKT, 256), 256, FA_SMEM>>>(qkv, qkv + (size_t)MTOK * EMB_,
                                                    qkv + 2 * (size_t)MTOK * EMB_, o);

    gemm_nn<<<dim3(2, 394), 256, SMEM_NN>>>(o, Wt + OFF_WP, bp, h, MTOK, 256, 256, 0);
    ln_kernel<<<MTOK, 256>>>(h, ln2_g, ln2_b, z, z, 0);

    pool_partial<<<dim3(B_, 8), 256>>>(z, pool);
    head_kernel<<<B_, 256>>>(pool, lnc_g, lnc_b, Wc, bc, out);
}

// round 10
// speedup vs baseline: 1.0746x; 1.0003x over previous
#include <cuda_runtime.h>
#include <math.h>

#define B_      128
#define EMB_    256
#define NTOK    394
#define MTOK    (B_ * NTOK)          // 50432
#define MPE     (B_ * 196)           // 25088

#define KC      32
#define STG     3
#define ASTR    36
#define BSTR    136
#define SMEM_NN ((STG * (128 * ASTR + 32 * BSTR)) * 4)
#define FA_SMEM ((64*132 + 2*64*132 + 2*64*136 + 64*68 + 256) * 4)   // 189440
#define FA_NKT  7

// ---------------- scratch ---------------------------------------------------
__device__ float g_T2[MPE * 192];
__device__ float g_Wt[507904];       // W2 | Wp | W1perm | Wqkv (all tf32)
__device__ float g_bqkv[768];
__device__ float g_z [MTOK * EMB_];
__device__ float g_h [MTOK * EMB_];
__device__ float g_qkv[3 * MTOK * EMB_];
__device__ float g_o [MTOK * EMB_];
__device__ float g_pool[B_ * 8 * EMB_];

#define OFF_W2   0
#define OFF_WP   49152
#define OFF_W1P  114688
#define OFF_WQKV 311296
#define PREP_N   508672              // 507904 weights + 768 bias

// ---------------- helpers ----------------------------------------------------
__device__ __forceinline__ float f2tf_f(float f) {
    unsigned u; asm("cvt.rna.tf32.f32 %0, %1;" : "=r"(u) : "f"(f));
    return __uint_as_float(u);
}
__device__ __forceinline__ void mma8(float* acc, const unsigned* a, const unsigned* b) {
    asm volatile(
        "mma.sync.aligned.m16n8k8.row.col.f32.tf32.tf32.f32 "
        "{%0,%1,%2,%3}, {%4,%5,%6,%7}, {%8,%9}, {%0,%1,%2,%3};\n"
        : "+f"(acc[0]), "+f"(acc[1]), "+f"(acc[2]), "+f"(acc[3])
        : "r"(a[0]), "r"(a[1]), "r"(a[2]), "r"(a[3]), "r"(b[0]), "r"(b[1]));
}
__device__ __forceinline__ void cpa16(float* dst, const float* src, bool pred) {
    unsigned d = (unsigned)__cvta_generic_to_shared(dst);
    int sz = pred ? 16 : 0;
    asm volatile("cp.async.cg.shared.global [%0], [%1], 16, %2;\n"
                 :: "r"(d), "l"(src), "r"(sz));
}
__device__ __forceinline__ void cpa_commit() { asm volatile("cp.async.commit_group;\n"); }
template <int N>
__device__ __forceinline__ void cpa_wait() { asm volatile("cp.async.wait_group %0;\n" :: "n"(N)); }

// ---------------- weight prep (tf32 rounding + layout transforms) -----------
__global__ void prep_w(const float* __restrict__ W1, const float* __restrict__ W2,
                       const float* __restrict__ Wq, const float* __restrict__ Wk,
                       const float* __restrict__ Wv, const float* __restrict__ Wp,
                       const float* __restrict__ bq, const float* __restrict__ bk,
                       const float* __restrict__ bv,
                       float* __restrict__ out, float* __restrict__ bqkv) {
    int i = blockIdx.x * 256 + threadIdx.x;
    if (i >= PREP_N) return;
    if (i < OFF_WP) {
        out[i] = f2tf_f(W2[i]);
    } else if (i < OFF_W1P) {
        out[i] = f2tf_f(Wp[i - OFF_WP]);
    } else if (i < OFF_WQKV) {
        // W1 permuted: k' = c*256 + pi*16 + pj  ->  src row r = (pi*16+pj)*3 + c
        int idx = i - OFF_W1P;
        int kp = idx >> 8, n = idx & 255;
        int c = kp >> 8;                 // kp/256
        int rem = kp & 255;
        int pi = rem >> 4, pj = rem & 15;
        int r = (pi * 16 + pj) * 3 + c;
        out[i] = f2tf_f(W1[r * 256 + n]);
    } else if (i < OFF_WQKV + 196608) {
        // Wqkv[k][n], n in [0,768): which = n>>8
        int idx = i - OFF_WQKV;
        int k = idx / 768, n = idx % 768;
        int which = n >> 8, col = n & 255;
        const float* src = which == 0 ? Wq : which == 1 ? Wk : Wv;
        out[i] = f2tf_f(src[k * 256 + col]);
    } else {
        int j = i - 507904;              // < 768
        int which = j >> 8, col = j & 255;
        const float* src = which == 0 ? bq : which == 1 ? bk : bv;
        bqkv[j] = src[col];
    }
}

// ---------------- im2col (p=8 sampled patches only) --------------------------
__global__ void im2col2(const float* __restrict__ x, float* __restrict__ T) {
    __shared__ float buf[192];
    int i = blockIdx.x, b = blockIdx.y;
    int jdx = 4 * i + 3;
    int ph = jdx / 28, pw = jdx % 28;
    const float* xb = x + (size_t)b * 3 * 224 * 224 + (size_t)(ph * 8) * 224 + pw * 8;
    int t = threadIdx.x;
    int c = t >> 6, pos = t & 63;
    int pi = pos >> 3, pj = pos & 7;
    buf[pos * 3 + c] = f2tf_f(xb[((size_t)c * 224 + pi) * 224 + pj]);
    __syncthreads();
    T[((size_t)b * 196 + i) * 192 + t] = buf[t];
}
__global__ void cls_fill(const float* __restrict__ cls1,
                         const float* __restrict__ cls2,
                         float* __restrict__ z) {
    int b = blockIdx.x, e = threadIdx.x;
    z[((size_t)b * NTOK + 0)   * EMB_ + e] = cls2[e];
    z[((size_t)b * NTOK + 197) * EMB_ + e] = cls1[e];
}

// ---------------- patch1 GEMM, implicit im2col from x ------------------------
// C rows: m = b*196 + j -> z token 198+j.  K=768 channel-major (c,pi,pj).
__global__ __launch_bounds__(256)
void gemm_pe1(const float* __restrict__ x, const float* __restrict__ Bm,
              const float* __restrict__ bias, float* __restrict__ C) {
    extern __shared__ float smem[];
    float* As = smem;
    float* Bs = smem + STG * 128 * ASTR;
    int tid = threadIdx.x;
    int bm = blockIdx.y * 128, bn = blockIdx.x * 128;
    int wid = tid >> 5, lane = tid & 31;
    int wm = wid & 3, wn = wid >> 2;
    int gid = lane >> 2, tg = lane & 3;
    int aRow = tid >> 3, aC4 = (tid & 7) << 2;
    int pj0 = aC4 & 15, gsel = aC4 >> 4;       // which 16-group within KC

    size_t rowb[4];
#pragma unroll
    for (int i = 0; i < 4; i++) {
        int m = bm + aRow + i * 32;
        int b = m / 196, j = m % 196;
        int ph = j / 14, pw = j % 14;
        rowb[i] = (size_t)b * 150528 + (size_t)(ph * 16) * 224 + pw * 16;
    }

    auto loadA = [&](int s, int k0) {
        float* dst = As + s * 128 * ASTR;
        int gidx = (k0 >> 4) + gsel;           // 0..47
        int c = gidx >> 4, pi = gidx & 15;
        size_t off = (size_t)c * 50176 + pi * 224 + pj0;
#pragma unroll
        for (int i = 0; i < 4; i++)
            cpa16(dst + (aRow + i * 32) * ASTR + aC4, x + rowb[i] + off, true);
    };
    auto loadB = [&](int s, int k0) {
        float* dst = Bs + s * 32 * BSTR;
#pragma unroll
        for (int i = 0; i < 4; i++) {
            int idx = tid + i * 256;
            int kr = idx >> 5, c4 = (idx & 31) << 2;
            cpa16(dst + kr * BSTR + c4, Bm + (size_t)(k0 + kr) * 256 + bn + c4, true);
        }
    };

    float acc[2][8][4] = {};
    const int nk = 768 / KC;                   // 24
#pragma unroll
    for (int s = 0; s < STG - 1; s++) { loadA(s, s * KC); loadB(s, s * KC); cpa_commit(); }

    for (int it = 0; it < nk; it++) {
        cpa_wait<STG - 2>();
        __syncthreads();
        int nxt = it + STG - 1;
        if (nxt < nk) { loadA(nxt % STG, nxt * KC); loadB(nxt % STG, nxt * KC); }
        cpa_commit();
        int s = it % STG;
        const float* ap = As + s * 128 * ASTR + (wm * 32 + gid) * ASTR + tg;
        const float* bp = Bs + s * 32 * BSTR + tg * BSTR + wn * 64 + gid;
#pragma unroll
        for (int kk = 0; kk < KC; kk += 8) {
            unsigned af[2][4], bf[8][2];
#pragma unroll
            for (int mt = 0; mt < 2; mt++) {
                af[mt][0] = __float_as_uint(ap[mt * 16 * ASTR + kk]);
                af[mt][1] = __float_as_uint(ap[(mt * 16 + 8) * ASTR + kk]);
                af[mt][2] = __float_as_uint(ap[mt * 16 * ASTR + kk + 4]);
                af[mt][3] = __float_as_uint(ap[(mt * 16 + 8) * ASTR + kk + 4]);
            }
#pragma unroll
            for (int nt = 0; nt < 8; nt++) {
                bf[nt][0] = __float_as_uint(bp[kk * BSTR + nt * 8]);
                bf[nt][1] = __float_as_uint(bp[(kk + 4) * BSTR + nt * 8]);
            }
#pragma unroll
            for (int mt = 0; mt < 2; mt++)
#pragma unroll
                for (int nt = 0; nt < 8; nt++)
                    mma8(acc[mt][nt], af[mt], bf[nt]);
        }
        __syncthreads();
    }

#pragma unroll
    for (int mt = 0; mt < 2; mt++)
#pragma unroll
        for (int nt = 0; nt < 8; nt++) {
            int n = bn + wn * 64 + nt * 8 + tg * 2;
            float bv0 = bias[n], bv1 = bias[n + 1];
#pragma unroll
            for (int half = 0; half < 2; half++) {
                int m = bm + wm * 32 + mt * 16 + gid + half * 8;
                int b = m / 196, jj = m % 196;
                *(float2*)&C[((size_t)b * NTOK + 198 + jj) * EMB_ + n] =
                    make_float2(acc[mt][nt][half * 2] + bv0,
                                acc[mt][nt][half * 2 + 1] + bv1);
            }
        }
}

// ---------------- NN GEMM (cp.async 3-stage, 128x128 tile) -------------------
// mode 0: plain   mode 2: patch2->z   mode 5: fused qkv (cvt)
__global__ __launch_bounds__(256)
void gemm_nn(const float* __restrict__ A, const float* __restrict__ Bm,
             const float* __restrict__ bias, float* __restrict__ C,
             int M, int N, int K, int mode) {
    extern __shared__ float smem[];
    float* As = smem;
    float* Bs = smem + STG * 128 * ASTR;
    int tid = threadIdx.x;
    int bm = blockIdx.y * 128, bn = blockIdx.x * 128;
    int wid = tid >> 5, lane = tid & 31;
    int wm = wid & 3, wn = wid >> 2;
    int gid = lane >> 2, tg = lane & 3;
    int aRow = tid >> 3, aC4 = (tid & 7) << 2;

    auto loadA = [&](int s, int k0) {
        float* dst = As + s * 128 * ASTR;
#pragma unroll
        for (int i = 0; i < 4; i++) {
            int row = aRow + i * 32;
            bool p = (bm + row) < M;
            const float* src = A + (size_t)(p ? bm + row : bm) * K + k0 + aC4;
            cpa16(dst + row * ASTR + aC4, src, p);
        }
    };
    auto loadB = [&](int s, int k0) {
        float* dst = Bs + s * 32 * BSTR;
#pragma unroll
        for (int i = 0; i < 4; i++) {
            int idx = tid + i * 256;
            int kr = idx >> 5, c4 = (idx & 31) << 2;
            bool p = (k0 + kr) < K;
            const float* src = Bm + (size_t)(p ? k0 + kr : 0) * N + bn + c4;
            cpa16(dst + kr * BSTR + c4, src, p);
        }
    };

    float acc[2][8][4] = {};
    int nk = K / KC;
#pragma unroll
    for (int s = 0; s < STG - 1; s++) { loadA(s, s * KC); loadB(s, s * KC); cpa_commit(); }

    for (int it = 0; it < nk; it++) {
        cpa_wait<STG - 2>();
        __syncthreads();
        int nxt = it + STG - 1;
        if (nxt < nk) { loadA(nxt % STG, nxt * KC); loadB(nxt % STG, nxt * KC); }
        cpa_commit();
        int s = it % STG;
        const float* ap = As + s * 128 * ASTR + (wm * 32 + gid) * ASTR + tg;
        const float* bp = Bs + s * 32 * BSTR + tg * BSTR + wn * 64 + gid;
#pragma unroll
        for (int kk = 0; kk < KC; kk += 8) {
            unsigned af[2][4], bf[8][2];
#pragma unroll
            for (int mt = 0; mt < 2; mt++) {
                af[mt][0] = __float_as_uint(ap[mt * 16 * ASTR + kk]);
                af[mt][1] = __float_as_uint(ap[(mt * 16 + 8) * ASTR + kk]);
                af[mt][2] = __float_as_uint(ap[mt * 16 * ASTR + kk + 4]);
                af[mt][3] = __float_as_uint(ap[(mt * 16 + 8) * ASTR + kk + 4]);
            }
#pragma unroll
            for (int nt = 0; nt < 8; nt++) {
                bf[nt][0] = __float_as_uint(bp[kk * BSTR + nt * 8]);
                bf[nt][1] = __float_as_uint(bp[(kk + 4) * BSTR + nt * 8]);
            }
#pragma unroll
            for (int mt = 0; mt < 2; mt++)
#pragma unroll
                for (int nt = 0; nt < 8; nt++)
                    mma8(acc[mt][nt], af[mt], bf[nt]);
        }
        __syncthreads();
    }

#pragma unroll
    for (int mt = 0; mt < 2; mt++) {
#pragma unroll
        for (int nt = 0; nt < 8; nt++) {
            int n = bn + wn * 64 + nt * 8 + tg * 2;
            float bv0 = bias ? bias[n] : 0.f;
            float bv1 = bias ? bias[n + 1] : 0.f;
#pragma unroll
            for (int half = 0; half < 2; half++) {
                int m = bm + wm * 32 + mt * 16 + gid + half * 8;
                if (m >= M) continue;
                float v0 = acc[mt][nt][half * 2 + 0] + bv0;
                float v1 = acc[mt][nt][half * 2 + 1] + bv1;
                if (mode == 5) { v0 = f2tf_f(v0); v1 = f2tf_f(v1); }
                float2 val = make_float2(v0, v1);
                if (mode == 0) {
                    *(float2*)&C[(size_t)m * N + n] = val;
                } else if (mode == 2) {
                    int b = m / 196, jj = m % 196;
                    *(float2*)&C[((size_t)b * NTOK + 1 + jj) * EMB_ + n] = val;
                } else {
                    // fused qkv: which = n>>8, then (b, h, t, d) layout
                    int b = m / NTOK, t = m % NTOK;
                    int which = n >> 8, d2 = n & 255;
                    int hh = d2 >> 7, dd = d2 & 127;
                    *(float2*)&C[(size_t)which * (MTOK * EMB_) +
                                 (((size_t)b * 2 + hh) * NTOK + t) * 128 + dd] = val;
                }
            }
        }
    }
}

// ---------------- flash attention (cross-warp-correct online softmax) --------
__global__ __launch_bounds__(256)
void flash_attn(const float* __restrict__ Qg, const float* __restrict__ Kg,
                const float* __restrict__ Vg, float* __restrict__ Og) {
    extern __shared__ float smem[];
    float* Qs = smem;                       // [64][132]
    float* Ks = Qs + 64 * 132;              // [2][64][132]
    float* Vs = Ks + 2 * 64 * 132;          // [2][64][136]
    float* Ps = Vs + 2 * 64 * 136;          // [64][68]
    float* redM = Ps + 64 * 68;             // [64][2]
    float* redS = redM + 128;               // [64][2]
    int tid = threadIdx.x, lane = tid & 31, wid = tid >> 5;
    int wm = wid & 3, wn = wid >> 2;
    int gid = lane >> 2, tg = lane & 3;
    int qt = blockIdx.x, bh = blockIdx.y;
    const float* Qb = Qg + (size_t)bh * 394 * 128;
    const float* Kb = Kg + (size_t)bh * 394 * 128;
    const float* Vb = Vg + (size_t)bh * 394 * 128;
    float* Ob = Og + (size_t)(bh >> 1) * NTOK * EMB_ + (bh & 1) * 128;
    int qbase = qt * 64;
    int r0 = wm * 16 + gid, r1 = r0 + 8;

    auto loadQ = [&]() {
#pragma unroll
        for (int i = 0; i < 8; i++) {
            int idx = tid + i * 256; int row = idx >> 5; int cc = (idx & 31) << 2;
            bool p = (qbase + row) < 394;
            cpa16(Qs + row * 132 + cc, Qb + (size_t)(p ? qbase + row : 0) * 128 + cc, p);
        }
    };
    auto loadK = [&](int st, int kt) {
        float* dst = Ks + st * 64 * 132;
#pragma unroll
        for (int i = 0; i < 8; i++) {
            int idx = tid + i * 256; int row = idx >> 5; int cc = (idx & 31) << 2;
            bool p = (kt * 64 + row) < 394;
            cpa16(dst + row * 132 + cc, Kb + (size_t)(p ? kt * 64 + row : 0) * 128 + cc, p);
        }
    };
    auto loadV = [&](int st, int kt) {
        float* dst = Vs + st * 64 * 136;
#pragma unroll
        for (int i = 0; i < 8; i++) {
            int idx = tid + i * 256; int row = idx >> 5; int cc = (idx & 31) << 2;
            bool p = (kt * 64 + row) < 394;
            cpa16(dst + row * 136 + cc, Vb + (size_t)(p ? kt * 64 + row : 0) * 128 + cc, p);
        }
    };

    loadQ(); loadK(0, 0); loadV(0, 0); cpa_commit();
    loadK(1, 1); loadV(1, 1); cpa_commit();

    float accO[8][4] = {};
    float m0 = -1e30f, m1 = -1e30f, l0 = 0.f, l1 = 0.f;

    for (int kt = 0; kt < FA_NKT; kt++) {
        int st = kt & 1;
        cpa_wait<1>();
        __syncthreads();

        float accS[4][4] = {};
        const float* qp = Qs + r0 * 132 + tg;
        const float* kp = Ks + st * 64 * 132 + (wn * 32 + gid) * 132 + tg;
#pragma unroll
        for (int kk = 0; kk < 128; kk += 8) {
            unsigned af[4];
            af[0] = __float_as_uint(qp[kk]);
            af[1] = __float_as_uint(qp[8 * 132 + kk]);
            af[2] = __float_as_uint(qp[kk + 4]);
            af[3] = __float_as_uint(qp[8 * 132 + kk + 4]);
#pragma unroll
            for (int nt = 0; nt < 4; nt++) {
                unsigned bf[2];
                bf[0] = __float_as_uint(kp[nt * 8 * 132 + kk]);
                bf[1] = __float_as_uint(kp[nt * 8 * 132 + kk + 4]);
                mma8(accS[nt], af, bf);
            }
        }
        int cbase = kt * 64 + wn * 32 + tg * 2;
#pragma unroll
        for (int nt = 0; nt < 4; nt++) {
            int c0 = cbase + nt * 8;
            if (c0 >= 394)     { accS[nt][0] = -1e30f; accS[nt][2] = -1e30f; }
            if (c0 + 1 >= 394) { accS[nt][1] = -1e30f; accS[nt][3] = -1e30f; }
        }
        float rm0 = -1e30f, rm1 = -1e30f;
#pragma unroll
        for (int nt = 0; nt < 4; nt++) {
            rm0 = fmaxf(rm0, fmaxf(accS[nt][0], accS[nt][1]));
            rm1 = fmaxf(rm1, fmaxf(accS[nt][2], accS[nt][3]));
        }
        rm0 = fmaxf(rm0, __shfl_xor_sync(0xffffffff, rm0, 1));
        rm0 = fmaxf(rm0, __shfl_xor_sync(0xffffffff, rm0, 2));
        rm1 = fmaxf(rm1, __shfl_xor_sync(0xffffffff, rm1, 1));
        rm1 = fmaxf(rm1, __shfl_xor_sync(0xffffffff, rm1, 2));
        float rs0 = 0.f, rs1 = 0.f;
#pragma unroll
        for (int nt = 0; nt < 4; nt++) {
            accS[nt][0] = __expf(accS[nt][0] - rm0);
            accS[nt][1] = __expf(accS[nt][1] - rm0);
            accS[nt][2] = __expf(accS[nt][2] - rm1);
            accS[nt][3] = __expf(accS[nt][3] - rm1);
            rs0 += accS[nt][0] + accS[nt][1];
            rs1 += accS[nt][2] + accS[nt][3];
        }
        rs0 += __shfl_xor_sync(0xffffffff, rs0, 1);
        rs0 += __shfl_xor_sync(0xffffffff, rs0, 2);
        rs1 += __shfl_xor_sync(0xffffffff, rs1, 1);
        rs1 += __shfl_xor_sync(0xffffffff, rs1, 2);
        if (tg == 0) {
            redM[r0 * 2 + wn] = rm0;  redS[r0 * 2 + wn] = rs0;
            redM[r1 * 2 + wn] = rm1;  redS[r1 * 2 + wn] = rs1;
        }
        __syncthreads();
        float a0 = redM[r0 * 2], a1 = redM[r0 * 2 + 1];
        float gm0 = fmaxf(a0, a1);
        float gs0 = redS[r0 * 2] * __expf(a0 - gm0) + redS[r0 * 2 + 1] * __expf(a1 - gm0);
        float b0v = redM[r1 * 2], b1v = redM[r1 * 2 + 1];
        float gm1 = fmaxf(b0v, b1v);
        float gs1 = redS[r1 * 2] * __expf(b0v - gm1) + redS[r1 * 2 + 1] * __expf(b1v - gm1);
        float mn0 = fmaxf(m0, gm0), mn1 = fmaxf(m1, gm1);
        float sc0 = __expf(m0 - mn0), sc1 = __expf(m1 - mn1);
        l0 = l0 * sc0 + gs0 * __expf(gm0 - mn0);
        l1 = l1 * sc1 + gs1 * __expf(gm1 - mn1);
        m0 = mn0;  m1 = mn1;
        float fw0 = __expf(rm0 - mn0), fw1 = __expf(rm1 - mn1);
#pragma unroll
        for (int nt = 0; nt < 8; nt++) {
            accO[nt][0] *= sc0; accO[nt][1] *= sc0;
            accO[nt][2] *= sc1; accO[nt][3] *= sc1;
        }
        float* pw = Ps + r0 * 68 + wn * 32 + tg * 2;
#pragma unroll
        for (int nt = 0; nt < 4; nt++) {
            *(float2*)&pw[nt * 8] =
                make_float2(f2tf_f(accS[nt][0] * fw0), f2tf_f(accS[nt][1] * fw0));
            *(float2*)&pw[8 * 68 + nt * 8] =
                make_float2(f2tf_f(accS[nt][2] * fw1), f2tf_f(accS[nt][3] * fw1));
        }
        __syncthreads();
        const float* pp = Ps + r0 * 68 + tg;
        const float* vp = Vs + st * 64 * 136 + tg * 136 + wn * 64 + gid;
#pragma unroll
        for (int kk = 0; kk < 64; kk += 8) {
            unsigned af[4];
            af[0] = __float_as_uint(pp[kk]);
            af[1] = __float_as_uint(pp[8 * 68 + kk]);
            af[2] = __float_as_uint(pp[kk + 4]);
            af[3] = __float_as_uint(pp[8 * 68 + kk + 4]);
#pragma unroll
            for (int nt = 0; nt < 8; nt++) {
                unsigned bf[2];
                bf[0] = __float_as_uint(vp[kk * 136 + nt * 8]);
                bf[1] = __float_as_uint(vp[(kk + 4) * 136 + nt * 8]);
                mma8(accO[nt], af, bf);
            }
        }
        __syncthreads();
        if (kt + 2 < FA_NKT) { loadK(st, kt + 2); loadV(st, kt + 2); }
        cpa_commit();
    }

    float inv0 = 1.f / (l0 * 16.f), inv1 = 1.f / (l1 * 16.f);
    int gr0 = qbase + r0, gr1 = qbase + r1;
#pragma unroll
    for (int nt = 0; nt < 8; nt++) {
        int col = wn * 64 + nt * 8 + tg * 2;
        if (gr0 < 394)
            *(float2*)&Ob[(size_t)gr0 * EMB_ + col] =
                make_float2(f2tf_f(accO[nt][0] * inv0), f2tf_f(accO[nt][1] * inv0));
        if (gr1 < 394)
            *(float2*)&Ob[(size_t)gr1 * EMB_ + col] =
                make_float2(f2tf_f(accO[nt][2] * inv1), f2tf_f(accO[nt][3] * inv1));
    }
}

// ---------------- layer norm --------------------------------------------------
__global__ __launch_bounds__(256)
void ln_kernel(const float* __restrict__ in, const float* __restrict__ g,
               const float* __restrict__ b, float* __restrict__ out,
               const float* __restrict__ addsrc, int docvt) {
    int r = blockIdx.x, e = threadIdx.x;
    size_t idx = (size_t)r * EMB_ + e;
    float v = in[idx];
    float s = v, s2 = v * v;
#pragma unroll
    for (int off = 16; off > 0; off >>= 1) {
        s  += __shfl_xor_sync(0xffffffff, s,  off);
        s2 += __shfl_xor_sync(0xffffffff, s2, off);
    }
    __shared__ float ss[8], ss2[8];
    if ((e & 31) == 0) { ss[e >> 5] = s; ss2[e >> 5] = s2; }
    __syncthreads();
    float tot = 0.f, tot2 = 0.f;
#pragma unroll
    for (int i = 0; i < 8; i++) { tot += ss[i]; tot2 += ss2[i]; }
    float mean = tot * (1.f / EMB_);
    float var = tot2 * (1.f / EMB_) - mean * mean;
    float nv = (v - mean) * rsqrtf(var + 1e-5f) * g[e] + b[e];
    if (docvt) nv = f2tf_f(nv);
    out[idx] = addsrc ? (addsrc[idx] + nv) : nv;
}

// ---------------- two-stage pool + head ---------------------------------------
__global__ __launch_bounds__(256)
void pool_partial(const float* __restrict__ z, float* __restrict__ pool) {
    int b = blockIdx.x, seg = blockIdx.y, e = threadIdx.x;
    int t0 = seg * 50;
    int t1 = t0 + 50; if (t1 > 394) t1 = 394;
    const float* zb = z + (size_t)b * NTOK * EMB_;
    float s = 0.f;
    for (int t = t0; t < t1; t++) s += zb[(size_t)t * EMB_ + e];
    pool[((size_t)b * 8 + seg) * EMB_ + e] = s;
}

__global__ __launch_bounds__(256)
void head_kernel(const float* __restrict__ pool, const float* __restrict__ g,
                 const float* __restrict__ bb, const float* __restrict__ Wc,
                 const float* __restrict__ bc, float* __restrict__ out) {
    int b = blockIdx.x, e = threadIdx.x;
    float s = 0.f;
#pragma unroll
    for (int i = 0; i < 8; i++) s += pool[((size_t)b * 8 + i) * EMB_ + e];
    float pooled = s * (1.f / NTOK);
    __shared__ float red[256];
    red[e] = pooled; __syncthreads();
    for (int st = 128; st > 0; st >>= 1) { if (e < st) red[e] += red[e + st]; __syncthreads(); }
    float mean = red[0] * (1.f / EMB_);
    __syncthreads();
    float d = pooled - mean;
    red[e] = d * d; __syncthreads();
    for (int st = 128; st > 0; st >>= 1) { if (e < st) red[e] += red[e + st]; __syncthreads(); }
    float var = red[0] * (1.f / EMB_);
    __syncthreads();
    float nv = d * rsqrtf(var + 1e-5f) * g[e] + bb[e];
    red[e] = nv * Wc[e * 2 + 0]; __syncthreads();
    for (int st = 128; st > 0; st >>= 1) { if (e < st) red[e] += red[e + st]; __syncthreads(); }
    float l0 = red[0] + bc[0];
    __syncthreads();
    red[e] = nv * Wc[e * 2 + 1]; __syncthreads();
    for (int st = 128; st > 0; st >>= 1) { if (e < st) red[e] += red[e + st]; __syncthreads(); }
    float l1 = red[0] + bc[1];
    if (e == 0) {
        float mx = fmaxf(l0, l1);
        float lse = mx + logf(expf(l0 - mx) + expf(l1 - mx));
        out[b * 2 + 0] = l0 - lse;
        out[b * 2 + 1] = l1 - lse;
    }
}

// ---------------- launch --------------------------------------------------------
extern "C" void kernel_launch(void* const* d_in, const int* in_sizes, int n_in,
                              void* d_out, int out_size) {
    const float* x     = (const float*)d_in[0];
    const float* W1    = (const float*)d_in[1];
    const float* b1    = (const float*)d_in[2];
    const float* cls1  = (const float*)d_in[3];
    const float* W2    = (const float*)d_in[4];
    const float* b2    = (const float*)d_in[5];
    const float* cls2  = (const float*)d_in[6];
    const float* ln1_g = (const float*)d_in[7];
    const float* ln1_b = (const float*)d_in[8];
    const float* Wq    = (const float*)d_in[9];
    const float* bq    = (const float*)d_in[10];
    const float* Wk    = (const float*)d_in[11];
    const float* bk    = (const float*)d_in[12];
    const float* Wv    = (const float*)d_in[13];
    const float* bv    = (const float*)d_in[14];
    const float* Wp    = (const float*)d_in[15];
    const float* bp    = (const float*)d_in[16];
    const float* ln2_g = (const float*)d_in[17];
    const float* ln2_b = (const float*)d_in[18];
    const float* lnc_g = (const float*)d_in[19];
    const float* lnc_b = (const float*)d_in[20];
    const float* Wc    = (const float*)d_in[21];
    const float* bc    = (const float*)d_in[22];
    float* out = (float*)d_out;

    static int inited = 0;
    if (!inited) {
        cudaFuncSetAttribute(gemm_nn,  cudaFuncAttributeMaxDynamicSharedMemorySize, SMEM_NN);
        cudaFuncSetAttribute(gemm_pe1, cudaFuncAttributeMaxDynamicSharedMemorySize, SMEM_NN);
        cudaFuncSetAttribute(flash_attn, cudaFuncAttributeMaxDynamicSharedMemorySize, FA_SMEM);
        inited = 1;
    }

    float *T2, *Wt, *bqkv, *z, *h, *qkv, *o, *pool;
    cudaGetSymbolAddress((void**)&T2, g_T2);
    cudaGetSymbolAddress((void**)&Wt, g_Wt);
    cudaGetSymbolAddress((void**)&bqkv, g_bqkv);
    cudaGetSymbolAddress((void**)&z,  g_z);
    cudaGetSymbolAddress((void**)&h,  g_h);
    cudaGetSymbolAddress((void**)&qkv, g_qkv);
    cudaGetSymbolAddress((void**)&o,  g_o);
    cudaGetSymbolAddress((void**)&pool, g_pool);

    prep_w<<<(PREP_N + 255) / 256, 256>>>(W1, W2, Wq, Wk, Wv, Wp, bq, bk, bv, Wt, bqkv);
    im2col2<<<dim3(196, B_), 192>>>(x, T2);
    cls_fill<<<B_, 256>>>(cls1, cls2, z);

    gemm_pe1<<<dim3(2, 196), 256, SMEM_NN>>>(x, Wt + OFF_W1P, b1, z);
    gemm_nn<<<dim3(2, 196), 256, SMEM_NN>>>(T2, Wt + OFF_W2, b2, z, MPE, 256, 192, 2);

    ln_kernel<<<MTOK, 256>>>(z, ln1_g, ln1_b, h, nullptr, 1);

    gemm_nn<<<dim3(6, 394), 256, SMEM_NN>>>(h, Wt + OFF_WQKV, bqkv, qkv, MTOK, 768, 256, 5);

    flash_attn<<<dim3(FA_NKT, 256), 256, FA_SMEM>>>(qkv, qkv + (size_t)MTOK * EMB_,
                                                    qkv + 2 * (size_t)MTOK * EMB_, o);

    gemm_nn<<<dim3(2, 394), 256, SMEM_NN>>>(o, Wt + OFF_WP, bp, h, MTOK, 256, 256, 0);
    ln_kernel<<<MTOK, 256>>>(h, ln2_g, ln2_b, z, z, 0);

    pool_partial<<<dim3(B_, 8), 256>>>(z, pool);
    head_kernel<<<B_, 256>>>(pool, lnc_g, lnc_b, Wc, bc, out);
}

// round 11
// speedup vs baseline: 1.1117x; 1.0345x over previous
#include <cuda_runtime.h>
#include <math.h>

#define B_      128
#define EMB_    256
#define NTOK    394
#define MTOK    (B_ * NTOK)          // 50432
#define MPE     (B_ * 196)           // 25088

#define KC      32
#define ASTR    36
#define BSTR    136
#define SMEM_NN ((2 * (128 * ASTR + 32 * BSTR)) * 4)          // 71680
#define FA_SMEM ((128*132 + 2*64*132 + 2*64*136) * 4)          // 204800
#define FA_NKT  7

// ---------------- scratch ---------------------------------------------------
__device__ float g_T2[MPE * 192];
__device__ float g_Wt[507904];       // W2 | Wp | W1perm | Wqkv (all tf32)
__device__ float g_bqkv[768];
__device__ float g_z [MTOK * EMB_];
__device__ float g_h [MTOK * EMB_];
__device__ float g_qkv[3 * MTOK * EMB_];
__device__ float g_o [MTOK * EMB_];
__device__ float g_pool[B_ * 8 * EMB_];

#define OFF_W2   0
#define OFF_WP   49152
#define OFF_W1P  114688
#define OFF_WQKV 311296
#define PREP_N   508672

// ---------------- helpers ----------------------------------------------------
__device__ __forceinline__ float f2tf_f(float f) {
    unsigned u; asm("cvt.rna.tf32.f32 %0, %1;" : "=r"(u) : "f"(f));
    return __uint_as_float(u);
}
__device__ __forceinline__ void mma8(float* acc, const unsigned* a, const unsigned* b) {
    asm volatile(
        "mma.sync.aligned.m16n8k8.row.col.f32.tf32.tf32.f32 "
        "{%0,%1,%2,%3}, {%4,%5,%6,%7}, {%8,%9}, {%0,%1,%2,%3};\n"
        : "+f"(acc[0]), "+f"(acc[1]), "+f"(acc[2]), "+f"(acc[3])
        : "r"(a[0]), "r"(a[1]), "r"(a[2]), "r"(a[3]), "r"(b[0]), "r"(b[1]));
}
__device__ __forceinline__ void cpa16(float* dst, const float* src, bool pred) {
    unsigned d = (unsigned)__cvta_generic_to_shared(dst);
    int sz = pred ? 16 : 0;
    asm volatile("cp.async.cg.shared.global [%0], [%1], 16, %2;\n"
                 :: "r"(d), "l"(src), "r"(sz));
}
__device__ __forceinline__ void cpa_commit() { asm volatile("cp.async.commit_group;\n"); }
template <int N>
__device__ __forceinline__ void cpa_wait() { asm volatile("cp.async.wait_group %0;\n" :: "n"(N)); }

// ---------------- weight prep ------------------------------------------------
__global__ void prep_w(const float* __restrict__ W1, const float* __restrict__ W2,
                       const float* __restrict__ Wq, const float* __restrict__ Wk,
                       const float* __restrict__ Wv, const float* __restrict__ Wp,
                       const float* __restrict__ bq, const float* __restrict__ bk,
                       const float* __restrict__ bv,
                       float* __restrict__ out, float* __restrict__ bqkv) {
    int i = blockIdx.x * 256 + threadIdx.x;
    if (i >= PREP_N) return;
    if (i < OFF_WP) {
        out[i] = f2tf_f(W2[i]);
    } else if (i < OFF_W1P) {
        out[i] = f2tf_f(Wp[i - OFF_WP]);
    } else if (i < OFF_WQKV) {
        int idx = i - OFF_W1P;
        int kp = idx >> 8, n = idx & 255;
        int c = kp >> 8;
        int rem = kp & 255;
        int pi = rem >> 4, pj = rem & 15;
        int r = (pi * 16 + pj) * 3 + c;
        out[i] = f2tf_f(W1[r * 256 + n]);
    } else if (i < OFF_WQKV + 196608) {
        int idx = i - OFF_WQKV;
        int k = idx / 768, n = idx % 768;
        int which = n >> 8, col = n & 255;
        const float* src = which == 0 ? Wq : which == 1 ? Wk : Wv;
        out[i] = f2tf_f(src[k * 256 + col]);
    } else {
        int j = i - 507904;
        int which = j >> 8, col = j & 255;
        const float* src = which == 0 ? bq : which == 1 ? bk : bv;
        bqkv[j] = src[col];
    }
}

// ---------------- im2col (p=8 sampled patches only) --------------------------
__global__ void im2col2(const float* __restrict__ x, float* __restrict__ T) {
    __shared__ float buf[192];
    int i = blockIdx.x, b = blockIdx.y;
    int jdx = 4 * i + 3;
    int ph = jdx / 28, pw = jdx % 28;
    const float* xb = x + (size_t)b * 3 * 224 * 224 + (size_t)(ph * 8) * 224 + pw * 8;
    int t = threadIdx.x;
    int c = t >> 6, pos = t & 63;
    int pi = pos >> 3, pj = pos & 7;
    buf[pos * 3 + c] = f2tf_f(xb[((size_t)c * 224 + pi) * 224 + pj]);
    __syncthreads();
    T[((size_t)b * 196 + i) * 192 + t] = buf[t];
}
__global__ void cls_fill(const float* __restrict__ cls1,
                         const float* __restrict__ cls2,
                         float* __restrict__ z) {
    int b = blockIdx.x, e = threadIdx.x;
    z[((size_t)b * NTOK + 0)   * EMB_ + e] = cls2[e];
    z[((size_t)b * NTOK + 197) * EMB_ + e] = cls1[e];
}

// ---------------- patch1 GEMM, implicit im2col from x (2-stage) --------------
__global__ __launch_bounds__(256, 2)
void gemm_pe1(const float* __restrict__ x, const float* __restrict__ Bm,
              const float* __restrict__ bias, float* __restrict__ C) {
    extern __shared__ float smem[];
    float* As = smem;
    float* Bs = smem + 2 * 128 * ASTR;
    int tid = threadIdx.x;
    int bm = blockIdx.y * 128, bn = blockIdx.x * 128;
    int wid = tid >> 5, lane = tid & 31;
    int wm = wid & 3, wn = wid >> 2;
    int gid = lane >> 2, tg = lane & 3;
    int aRow = tid >> 3, aC4 = (tid & 7) << 2;
    int pj0 = aC4 & 15, gsel = aC4 >> 4;

    size_t rowb[4];
#pragma unroll
    for (int i = 0; i < 4; i++) {
        int m = bm + aRow + i * 32;
        int b = m / 196, j = m % 196;
        int ph = j / 14, pw = j % 14;
        rowb[i] = (size_t)b * 150528 + (size_t)(ph * 16) * 224 + pw * 16;
    }

    auto loadA = [&](int s, int k0) {
        float* dst = As + s * 128 * ASTR;
        int gidx = (k0 >> 4) + gsel;
        int c = gidx >> 4, pi = gidx & 15;
        size_t off = (size_t)c * 50176 + pi * 224 + pj0;
#pragma unroll
        for (int i = 0; i < 4; i++)
            cpa16(dst + (aRow + i * 32) * ASTR + aC4, x + rowb[i] + off, true);
    };
    auto loadB = [&](int s, int k0) {
        float* dst = Bs + s * 32 * BSTR;
#pragma unroll
        for (int i = 0; i < 4; i++) {
            int idx = tid + i * 256;
            int kr = idx >> 5, c4 = (idx & 31) << 2;
            cpa16(dst + kr * BSTR + c4, Bm + (size_t)(k0 + kr) * 256 + bn + c4, true);
        }
    };

    float acc[2][8][4] = {};
    const int nk = 768 / KC;
    loadA(0, 0); loadB(0, 0); cpa_commit();

    for (int it = 0; it < nk; it++) {
        int nxt = it + 1;
        if (nxt < nk) { loadA(nxt & 1, nxt * KC); loadB(nxt & 1, nxt * KC); }
        cpa_commit();
        cpa_wait<1>();
        __syncthreads();
        int s = it & 1;
        const float* ap = As + s * 128 * ASTR + (wm * 32 + gid) * ASTR + tg;
        const float* bp = Bs + s * 32 * BSTR + tg * BSTR + wn * 64 + gid;
#pragma unroll
        for (int kk = 0; kk < KC; kk += 8) {
            unsigned af[2][4], bf[8][2];
#pragma unroll
            for (int mt = 0; mt < 2; mt++) {
                af[mt][0] = __float_as_uint(ap[mt * 16 * ASTR + kk]);
                af[mt][1] = __float_as_uint(ap[(mt * 16 + 8) * ASTR + kk]);
                af[mt][2] = __float_as_uint(ap[mt * 16 * ASTR + kk + 4]);
                af[mt][3] = __float_as_uint(ap[(mt * 16 + 8) * ASTR + kk + 4]);
            }
#pragma unroll
            for (int nt = 0; nt < 8; nt++) {
                bf[nt][0] = __float_as_uint(bp[kk * BSTR + nt * 8]);
                bf[nt][1] = __float_as_uint(bp[(kk + 4) * BSTR + nt * 8]);
            }
#pragma unroll
            for (int mt = 0; mt < 2; mt++)
#pragma unroll
                for (int nt = 0; nt < 8; nt++)
                    mma8(acc[mt][nt], af[mt], bf[nt]);
        }
        __syncthreads();
    }

#pragma unroll
    for (int mt = 0; mt < 2; mt++)
#pragma unroll
        for (int nt = 0; nt < 8; nt++) {
            int n = bn + wn * 64 + nt * 8 + tg * 2;
            float bv0 = bias[n], bv1 = bias[n + 1];
#pragma unroll
            for (int half = 0; half < 2; half++) {
                int m = bm + wm * 32 + mt * 16 + gid + half * 8;
                int b = m / 196, jj = m % 196;
                *(float2*)&C[((size_t)b * NTOK + 198 + jj) * EMB_ + n] =
                    make_float2(acc[mt][nt][half * 2] + bv0,
                                acc[mt][nt][half * 2 + 1] + bv1);
            }
        }
}

// ---------------- NN GEMM (2-stage, 128x128, 2 CTAs/SM) ----------------------
// mode 0: plain   mode 2: patch2->z   mode 5: fused qkv (cvt)
__global__ __launch_bounds__(256, 2)
void gemm_nn(const float* __restrict__ A, const float* __restrict__ Bm,
             const float* __restrict__ bias, float* __restrict__ C,
             int M, int N, int K, int mode) {
    extern __shared__ float smem[];
    float* As = smem;
    float* Bs = smem + 2 * 128 * ASTR;
    int tid = threadIdx.x;
    int bm = blockIdx.y * 128, bn = blockIdx.x * 128;
    int wid = tid >> 5, lane = tid & 31;
    int wm = wid & 3, wn = wid >> 2;
    int gid = lane >> 2, tg = lane & 3;
    int aRow = tid >> 3, aC4 = (tid & 7) << 2;

    auto loadA = [&](int s, int k0) {
        float* dst = As + s * 128 * ASTR;
#pragma unroll
        for (int i = 0; i < 4; i++) {
            int row = aRow + i * 32;
            bool p = (bm + row) < M;
            const float* src = A + (size_t)(p ? bm + row : bm) * K + k0 + aC4;
            cpa16(dst + row * ASTR + aC4, src, p);
        }
    };
    auto loadB = [&](int s, int k0) {
        float* dst = Bs + s * 32 * BSTR;
#pragma unroll
        for (int i = 0; i < 4; i++) {
            int idx = tid + i * 256;
            int kr = idx >> 5, c4 = (idx & 31) << 2;
            bool p = (k0 + kr) < K;
            const float* src = Bm + (size_t)(p ? k0 + kr : 0) * N + bn + c4;
            cpa16(dst + kr * BSTR + c4, src, p);
        }
    };

    float acc[2][8][4] = {};
    int nk = K / KC;
    loadA(0, 0); loadB(0, 0); cpa_commit();

    for (int it = 0; it < nk; it++) {
        int nxt = it + 1;
        if (nxt < nk) { loadA(nxt & 1, nxt * KC); loadB(nxt & 1, nxt * KC); }
        cpa_commit();
        cpa_wait<1>();
        __syncthreads();
        int s = it & 1;
        const float* ap = As + s * 128 * ASTR + (wm * 32 + gid) * ASTR + tg;
        const float* bp = Bs + s * 32 * BSTR + tg * BSTR + wn * 64 + gid;
#pragma unroll
        for (int kk = 0; kk < KC; kk += 8) {
            unsigned af[2][4], bf[8][2];
#pragma unroll
            for (int mt = 0; mt < 2; mt++) {
                af[mt][0] = __float_as_uint(ap[mt * 16 * ASTR + kk]);
                af[mt][1] = __float_as_uint(ap[(mt * 16 + 8) * ASTR + kk]);
                af[mt][2] = __float_as_uint(ap[mt * 16 * ASTR + kk + 4]);
                af[mt][3] = __float_as_uint(ap[(mt * 16 + 8) * ASTR + kk + 4]);
            }
#pragma unroll
            for (int nt = 0; nt < 8; nt++) {
                bf[nt][0] = __float_as_uint(bp[kk * BSTR + nt * 8]);
                bf[nt][1] = __float_as_uint(bp[(kk + 4) * BSTR + nt * 8]);
            }
#pragma unroll
            for (int mt = 0; mt < 2; mt++)
#pragma unroll
                for (int nt = 0; nt < 8; nt++)
                    mma8(acc[mt][nt], af[mt], bf[nt]);
        }
        __syncthreads();
    }

#pragma unroll
    for (int mt = 0; mt < 2; mt++) {
#pragma unroll
        for (int nt = 0; nt < 8; nt++) {
            int n = bn + wn * 64 + nt * 8 + tg * 2;
            float bv0 = bias ? bias[n] : 0.f;
            float bv1 = bias ? bias[n + 1] : 0.f;
#pragma unroll
            for (int half = 0; half < 2; half++) {
                int m = bm + wm * 32 + mt * 16 + gid + half * 8;
                if (m >= M) continue;
                float v0 = acc[mt][nt][half * 2 + 0] + bv0;
                float v1 = acc[mt][nt][half * 2 + 1] + bv1;
                if (mode == 5) { v0 = f2tf_f(v0); v1 = f2tf_f(v1); }
                float2 val = make_float2(v0, v1);
                if (mode == 0) {
                    *(float2*)&C[(size_t)m * N + n] = val;
                } else if (mode == 2) {
                    int b = m / 196, jj = m % 196;
                    *(float2*)&C[((size_t)b * NTOK + 1 + jj) * EMB_ + n] = val;
                } else {
                    int b = m / NTOK, t = m % NTOK;
                    int which = n >> 8, d2 = n & 255;
                    int hh = d2 >> 7, dd = d2 & 127;
                    *(float2*)&C[(size_t)which * (MTOK * EMB_) +
                                 (((size_t)b * 2 + hh) * NTOK + t) * 128 + dd] = val;
                }
            }
        }
    }
}

// ---------------- flash attention v2: warp-per-row-strip, register refrag ----
__global__ __launch_bounds__(256)
void flash_attn(const float* __restrict__ Qg, const float* __restrict__ Kg,
                const float* __restrict__ Vg, float* __restrict__ Og) {
    extern __shared__ float smem[];
    float* Qs = smem;                       // [128][132]
    float* Ks = Qs + 128 * 132;             // [2][64][132]
    float* Vs = Ks + 2 * 64 * 132;          // [2][64][136]
    int tid = threadIdx.x, lane = tid & 31, wid = tid >> 5;
    int gid = lane >> 2, tg = lane & 3;
    int qt = blockIdx.x, bh = blockIdx.y;
    const float* Qb = Qg + (size_t)bh * 394 * 128;
    const float* Kb = Kg + (size_t)bh * 394 * 128;
    const float* Vb = Vg + (size_t)bh * 394 * 128;
    float* Ob = Og + (size_t)(bh >> 1) * NTOK * EMB_ + (bh & 1) * 128;
    int qbase = qt * 128;
    int r0 = wid * 16 + gid;                // warp-strip row; r1 = r0 + 8

    auto loadQ = [&]() {
#pragma unroll
        for (int i = 0; i < 16; i++) {
            int idx = tid + i * 256; int row = idx >> 5; int cc = (idx & 31) << 2;
            bool p = (qbase + row) < 394;
            cpa16(Qs + row * 132 + cc, Qb + (size_t)(p ? qbase + row : 0) * 128 + cc, p);
        }
    };
    auto loadK = [&](int st, int kt) {
        float* dst = Ks + st * 64 * 132;
#pragma unroll
        for (int i = 0; i < 8; i++) {
            int idx = tid + i * 256; int row = idx >> 5; int cc = (idx & 31) << 2;
            bool p = (kt * 64 + row) < 394;
            cpa16(dst + row * 132 + cc, Kb + (size_t)(p ? kt * 64 + row : 0) * 128 + cc, p);
        }
    };
    auto loadV = [&](int st, int kt) {
        float* dst = Vs + st * 64 * 136;
#pragma unroll
        for (int i = 0; i < 8; i++) {
            int idx = tid + i * 256; int row = idx >> 5; int cc = (idx & 31) << 2;
            bool p = (kt * 64 + row) < 394;
            cpa16(dst + row * 136 + cc, Vb + (size_t)(p ? kt * 64 + row : 0) * 128 + cc, p);
        }
    };

    loadQ(); loadK(0, 0); loadV(0, 0); cpa_commit();
    loadK(1, 1); loadV(1, 1); cpa_commit();

    float accO[16][4] = {};
    float m0 = -1e30f, m1 = -1e30f, l0 = 0.f, l1 = 0.f;

    for (int kt = 0; kt < FA_NKT; kt++) {
        int st = kt & 1;
        cpa_wait<1>();
        __syncthreads();

        // ---- S = Q @ K^T : warp rows [wid*16,+16), ALL 64 kv cols ----
        float accS[8][4] = {};
        {
            const float* qp = Qs + r0 * 132 + tg;
            const float* kp = Ks + st * 64 * 132 + gid * 132 + tg;
#pragma unroll
            for (int kk = 0; kk < 128; kk += 8) {
                unsigned af[4];
                af[0] = __float_as_uint(qp[kk]);
                af[1] = __float_as_uint(qp[8 * 132 + kk]);
                af[2] = __float_as_uint(qp[kk + 4]);
                af[3] = __float_as_uint(qp[8 * 132 + kk + 4]);
#pragma unroll
                for (int nt = 0; nt < 8; nt++) {
                    unsigned bf[2];
                    bf[0] = __float_as_uint(kp[nt * 8 * 132 + kk]);
                    bf[1] = __float_as_uint(kp[nt * 8 * 132 + kk + 4]);
                    mma8(accS[nt], af, bf);
                }
            }
        }
        // ---- mask kv cols >= 394 ----
        int cb = kt * 64 + tg * 2;
#pragma unroll
        for (int nt = 0; nt < 8; nt++) {
            int c0 = cb + nt * 8;
            if (c0 >= 394)     { accS[nt][0] = -1e30f; accS[nt][2] = -1e30f; }
            if (c0 + 1 >= 394) { accS[nt][1] = -1e30f; accS[nt][3] = -1e30f; }
        }
        // ---- full-row softmax (quad shuffles only; no cross-warp) ----
        float rm0 = -1e30f, rm1 = -1e30f;
#pragma unroll
        for (int nt = 0; nt < 8; nt++) {
            rm0 = fmaxf(rm0, fmaxf(accS[nt][0], accS[nt][1]));
            rm1 = fmaxf(rm1, fmaxf(accS[nt][2], accS[nt][3]));
        }
        rm0 = fmaxf(rm0, __shfl_xor_sync(0xffffffffu, rm0, 1));
        rm0 = fmaxf(rm0, __shfl_xor_sync(0xffffffffu, rm0, 2));
        rm1 = fmaxf(rm1, __shfl_xor_sync(0xffffffffu, rm1, 1));
        rm1 = fmaxf(rm1, __shfl_xor_sync(0xffffffffu, rm1, 2));
        float mn0 = fmaxf(m0, rm0), mn1 = fmaxf(m1, rm1);
        float sc0 = __expf(m0 - mn0), sc1 = __expf(m1 - mn1);
        float rs0 = 0.f, rs1 = 0.f;
#pragma unroll
        for (int nt = 0; nt < 8; nt++) {
            accS[nt][0] = __expf(accS[nt][0] - mn0);
            accS[nt][1] = __expf(accS[nt][1] - mn0);
            accS[nt][2] = __expf(accS[nt][2] - mn1);
            accS[nt][3] = __expf(accS[nt][3] - mn1);
            rs0 += accS[nt][0] + accS[nt][1];
            rs1 += accS[nt][2] + accS[nt][3];
        }
        rs0 += __shfl_xor_sync(0xffffffffu, rs0, 1);
        rs0 += __shfl_xor_sync(0xffffffffu, rs0, 2);
        rs1 += __shfl_xor_sync(0xffffffffu, rs1, 1);
        rs1 += __shfl_xor_sync(0xffffffffu, rs1, 2);
        l0 = l0 * sc0 + rs0;  l1 = l1 * sc1 + rs1;
        m0 = mn0;  m1 = mn1;
#pragma unroll
        for (int nt = 0; nt < 16; nt++) {
            accO[nt][0] *= sc0; accO[nt][1] *= sc0;
            accO[nt][2] *= sc1; accO[nt][3] *= sc1;
        }
        // ---- O += P @ V : C-frag -> A-frag via quad shuffles, no smem ----
        {
            const float* vp = Vs + st * 64 * 136 + tg * 136 + gid;
            int s0l = (lane & ~3) | (tg >> 1);
            int s1l = s0l + 2;
            bool odd = (tg & 1);
#pragma unroll
            for (int j = 0; j < 8; j++) {
                float p00 = __shfl_sync(0xffffffffu, accS[j][0], s0l);
                float p01 = __shfl_sync(0xffffffffu, accS[j][1], s0l);
                float p10 = __shfl_sync(0xffffffffu, accS[j][2], s0l);
                float p11 = __shfl_sync(0xffffffffu, accS[j][3], s0l);
                float q00 = __shfl_sync(0xffffffffu, accS[j][0], s1l);
                float q01 = __shfl_sync(0xffffffffu, accS[j][1], s1l);
                float q10 = __shfl_sync(0xffffffffu, accS[j][2], s1l);
                float q11 = __shfl_sync(0xffffffffu, accS[j][3], s1l);
                unsigned a[4];
                a[0] = __float_as_uint(f2tf_f(odd ? p01 : p00));
                a[1] = __float_as_uint(f2tf_f(odd ? p11 : p10));
                a[2] = __float_as_uint(f2tf_f(odd ? q01 : q00));
                a[3] = __float_as_uint(f2tf_f(odd ? q11 : q10));
                const float* vj = vp + j * 8 * 136;
#pragma unroll
                for (int nt = 0; nt < 16; nt++) {
                    unsigned bf[2];
                    bf[0] = __float_as_uint(vj[nt * 8]);
                    bf[1] = __float_as_uint(vj[4 * 136 + nt * 8]);
                    mma8(accO[nt], a, bf);
                }
            }
        }
        __syncthreads();
        if (kt + 2 < FA_NKT) { loadK(st, kt + 2); loadV(st, kt + 2); }
        cpa_commit();
    }

    float inv0 = 1.f / (l0 * 16.f), inv1 = 1.f / (l1 * 16.f);
    int gr0 = qbase + r0, gr1 = gr0 + 8;
#pragma unroll
    for (int nt = 0; nt < 16; nt++) {
        int col = nt * 8 + tg * 2;
        if (gr0 < 394)
            *(float2*)&Ob[(size_t)gr0 * EMB_ + col] =
                make_float2(f2tf_f(accO[nt][0] * inv0), f2tf_f(accO[nt][1] * inv0));
        if (gr1 < 394)
            *(float2*)&Ob[(size_t)gr1 * EMB_ + col] =
                make_float2(f2tf_f(accO[nt][2] * inv1), f2tf_f(accO[nt][3] * inv1));
    }
}

// ---------------- layer norm --------------------------------------------------
__global__ __launch_bounds__(256)
void ln_kernel(const float* __restrict__ in, const float* __restrict__ g,
               const float* __restrict__ b, float* __restrict__ out,
               const float* __restrict__ addsrc, int docvt) {
    int r = blockIdx.x, e = threadIdx.x;
    size_t idx = (size_t)r * EMB_ + e;
    float v = in[idx];
    float s = v, s2 = v * v;
#pragma unroll
    for (int off = 16; off > 0; off >>= 1) {
        s  += __shfl_xor_sync(0xffffffff, s,  off);
        s2 += __shfl_xor_sync(0xffffffff, s2, off);
    }
    __shared__ float ss[8], ss2[8];
    if ((e & 31) == 0) { ss[e >> 5] = s; ss2[e >> 5] = s2; }
    __syncthreads();
    float tot = 0.f, tot2 = 0.f;
#pragma unroll
    for (int i = 0; i < 8; i++) { tot += ss[i]; tot2 += ss2[i]; }
    float mean = tot * (1.f / EMB_);
    float var = tot2 * (1.f / EMB_) - mean * mean;
    float nv = (v - mean) * rsqrtf(var + 1e-5f) * g[e] + b[e];
    if (docvt) nv = f2tf_f(nv);
    out[idx] = addsrc ? (addsrc[idx] + nv) : nv;
}

// ---------------- two-stage pool + head ---------------------------------------
__global__ __launch_bounds__(256)
void pool_partial(const float* __restrict__ z, float* __restrict__ pool) {
    int b = blockIdx.x, seg = blockIdx.y, e = threadIdx.x;
    int t0 = seg * 50;
    int t1 = t0 + 50; if (t1 > 394) t1 = 394;
    const float* zb = z + (size_t)b * NTOK * EMB_;
    float s = 0.f;
    for (int t = t0; t < t1; t++) s += zb[(size_t)t * EMB_ + e];
    pool[((size_t)b * 8 + seg) * EMB_ + e] = s;
}

__global__ __launch_bounds__(256)
void head_kernel(const float* __restrict__ pool, const float* __restrict__ g,
                 const float* __restrict__ bb, const float* __restrict__ Wc,
                 const float* __restrict__ bc, float* __restrict__ out) {
    int b = blockIdx.x, e = threadIdx.x;
    float s = 0.f;
#pragma unroll
    for (int i = 0; i < 8; i++) s += pool[((size_t)b * 8 + i) * EMB_ + e];
    float pooled = s * (1.f / NTOK);
    __shared__ float red[256];
    red[e] = pooled; __syncthreads();
    for (int st = 128; st > 0; st >>= 1) { if (e < st) red[e] += red[e + st]; __syncthreads(); }
    float mean = red[0] * (1.f / EMB_);
    __syncthreads();
    float d = pooled - mean;
    red[e] = d * d; __syncthreads();
    for (int st = 128; st > 0; st >>= 1) { if (e < st) red[e] += red[e + st]; __syncthreads(); }
    float var = red[0] * (1.f / EMB_);
    __syncthreads();
    float nv = d * rsqrtf(var + 1e-5f) * g[e] + bb[e];
    red[e] = nv * Wc[e * 2 + 0]; __syncthreads();
    for (int st = 128; st > 0; st >>= 1) { if (e < st) red[e] += red[e + st]; __syncthreads(); }
    float l0 = red[0] + bc[0];
    __syncthreads();
    red[e] = nv * Wc[e * 2 + 1]; __syncthreads();
    for (int st = 128; st > 0; st >>= 1) { if (e < st) red[e] += red[e + st]; __syncthreads(); }
    float l1 = red[0] + bc[1];
    if (e == 0) {
        float mx = fmaxf(l0, l1);
        float lse = mx + logf(expf(l0 - mx) + expf(l1 - mx));
        out[b * 2 + 0] = l0 - lse;
        out[b * 2 + 1] = l1 - lse;
    }
}

// ---------------- launch --------------------------------------------------------
extern "C" void kernel_launch(void* const* d_in, const int* in_sizes, int n_in,
                              void* d_out, int out_size) {
    const float* x     = (const float*)d_in[0];
    const float* W1    = (const float*)d_in[1];
    const float* b1    = (const float*)d_in[2];
    const float* cls1  = (const float*)d_in[3];
    const float* W2    = (const float*)d_in[4];
    const float* b2    = (const float*)d_in[5];
    const float* cls2  = (const float*)d_in[6];
    const float* ln1_g = (const float*)d_in[7];
    const float* ln1_b = (const float*)d_in[8];
    const float* Wq    = (const float*)d_in[9];
    const float* bq    = (const float*)d_in[10];
    const float* Wk    = (const float*)d_in[11];
    const float* bk    = (const float*)d_in[12];
    const float* Wv    = (const float*)d_in[13];
    const float* bv    = (const float*)d_in[14];
    const float* Wp    = (const float*)d_in[15];
    const float* bp    = (const float*)d_in[16];
    const float* ln2_g = (const float*)d_in[17];
    const float* ln2_b = (const float*)d_in[18];
    const float* lnc_g = (const float*)d_in[19];
    const float* lnc_b = (const float*)d_in[20];
    const float* Wc    = (const float*)d_in[21];
    const float* bc    = (const float*)d_in[22];
    float* out = (float*)d_out;

    static int inited = 0;
    if (!inited) {
        cudaFuncSetAttribute(gemm_nn,  cudaFuncAttributeMaxDynamicSharedMemorySize, SMEM_NN);
        cudaFuncSetAttribute(gemm_pe1, cudaFuncAttributeMaxDynamicSharedMemorySize, SMEM_NN);
        cudaFuncSetAttribute(flash_attn, cudaFuncAttributeMaxDynamicSharedMemorySize, FA_SMEM);
        inited = 1;
    }

    float *T2, *Wt, *bqkv, *z, *h, *qkv, *o, *pool;
    cudaGetSymbolAddress((void**)&T2, g_T2);
    cudaGetSymbolAddress((void**)&Wt, g_Wt);
    cudaGetSymbolAddress((void**)&bqkv, g_bqkv);
    cudaGetSymbolAddress((void**)&z,  g_z);
    cudaGetSymbolAddress((void**)&h,  g_h);
    cudaGetSymbolAddress((void**)&qkv, g_qkv);
    cudaGetSymbolAddress((void**)&o,  g_o);
    cudaGetSymbolAddress((void**)&pool, g_pool);

    prep_w<<<(PREP_N + 255) / 256, 256>>>(W1, W2, Wq, Wk, Wv, Wp, bq, bk, bv, Wt, bqkv);
    im2col2<<<dim3(196, B_), 192>>>(x, T2);
    cls_fill<<<B_, 256>>>(cls1, cls2, z);

    gemm_pe1<<<dim3(2, 196), 256, SMEM_NN>>>(x, Wt + OFF_W1P, b1, z);
    gemm_nn<<<dim3(2, 196), 256, SMEM_NN>>>(T2, Wt + OFF_W2, b2, z, MPE, 256, 192, 2);

    ln_kernel<<<MTOK, 256>>>(z, ln1_g, ln1_b, h, nullptr, 1);

    gemm_nn<<<dim3(6, 394), 256, SMEM_NN>>>(h, Wt + OFF_WQKV, bqkv, qkv, MTOK, 768, 256, 5);

    flash_attn<<<dim3(4, 256), 256, FA_SMEM>>>(qkv, qkv + (size_t)MTOK * EMB_,
                                               qkv + 2 * (size_t)MTOK * EMB_, o);

    gemm_nn<<<dim3(2, 394), 256, SMEM_NN>>>(o, Wt + OFF_WP, bp, h, MTOK, 256, 256, 0);
    ln_kernel<<<MTOK, 256>>>(h, ln2_g, ln2_b, z, z, 0);

    pool_partial<<<dim3(B_, 8), 256>>>(z, pool);
    head_kernel<<<B_, 256>>>(pool, lnc_g, lnc_b, Wc, bc, out);
}

// round 12
// speedup vs baseline: 1.1211x; 1.0085x over previous
#include <cuda_runtime.h>
#include <math.h>

#define B_      128
#define EMB_    256
#define NTOK    394
#define MTOK    (B_ * NTOK)          // 50432
#define MPE     (B_ * 196)           // 25088

#define KC      32
#define ASTR    36
#define BSTR    136
#define SMEM_NN ((3 * (128 * ASTR + 32 * BSTR)) * 4)           // 107520
#define FA_SMEM ((128*132 + 2*64*132 + 2*64*136) * 4)          // 204800
#define FA_NKT  7

// ---------------- scratch ---------------------------------------------------
__device__ float g_T2[MPE * 192];
__device__ float g_Wt[507904];       // W2 | Wp | W1perm | Wqkv (all tf32)
__device__ float g_bqkv[768];
__device__ float g_z [MTOK * EMB_];
__device__ float g_h [MTOK * EMB_];
__device__ float g_qkv[3 * MTOK * EMB_];
__device__ float g_o [MTOK * EMB_];
__device__ float g_pool[B_ * 8 * EMB_];

#define OFF_W2   0
#define OFF_WP   49152
#define OFF_W1P  114688
#define OFF_WQKV 311296
#define PREP_N   508672

// ---------------- helpers ----------------------------------------------------
__device__ __forceinline__ float f2tf_f(float f) {
    unsigned u; asm("cvt.rna.tf32.f32 %0, %1;" : "=r"(u) : "f"(f));
    return __uint_as_float(u);
}
__device__ __forceinline__ void mma8(float* acc, const unsigned* a, const unsigned* b) {
    asm volatile(
        "mma.sync.aligned.m16n8k8.row.col.f32.tf32.tf32.f32 "
        "{%0,%1,%2,%3}, {%4,%5,%6,%7}, {%8,%9}, {%0,%1,%2,%3};\n"
        : "+f"(acc[0]), "+f"(acc[1]), "+f"(acc[2]), "+f"(acc[3])
        : "r"(a[0]), "r"(a[1]), "r"(a[2]), "r"(a[3]), "r"(b[0]), "r"(b[1]));
}
__device__ __forceinline__ void cpa16(float* dst, const float* src, bool pred) {
    unsigned d = (unsigned)__cvta_generic_to_shared(dst);
    int sz = pred ? 16 : 0;
    asm volatile("cp.async.cg.shared.global [%0], [%1], 16, %2;\n"
                 :: "r"(d), "l"(src), "r"(sz));
}
__device__ __forceinline__ void cpa_commit() { asm volatile("cp.async.commit_group;\n"); }
template <int N>
__device__ __forceinline__ void cpa_wait() { asm volatile("cp.async.wait_group %0;\n" :: "n"(N)); }

// ---------------- weight prep ------------------------------------------------
__global__ void prep_w(const float* __restrict__ W1, const float* __restrict__ W2,
                       const float* __restrict__ Wq, const float* __restrict__ Wk,
                       const float* __restrict__ Wv, const float* __restrict__ Wp,
                       const float* __restrict__ bq, const float* __restrict__ bk,
                       const float* __restrict__ bv,
                       float* __restrict__ out, float* __restrict__ bqkv) {
    int i = blockIdx.x * 256 + threadIdx.x;
    if (i >= PREP_N) return;
    if (i < OFF_WP) {
        out[i] = f2tf_f(W2[i]);
    } else if (i < OFF_W1P) {
        out[i] = f2tf_f(Wp[i - OFF_WP]);
    } else if (i < OFF_WQKV) {
        int idx = i - OFF_W1P;
        int kp = idx >> 8, n = idx & 255;
        int c = kp >> 8;
        int rem = kp & 255;
        int pi = rem >> 4, pj = rem & 15;
        int r = (pi * 16 + pj) * 3 + c;
        out[i] = f2tf_f(W1[r * 256 + n]);
    } else if (i < OFF_WQKV + 196608) {
        int idx = i - OFF_WQKV;
        int k = idx / 768, n = idx % 768;
        int which = n >> 8, col = n & 255;
        const float* src = which == 0 ? Wq : which == 1 ? Wk : Wv;
        out[i] = f2tf_f(src[k * 256 + col]);
    } else {
        int j = i - 507904;
        int which = j >> 8, col = j & 255;
        const float* src = which == 0 ? bq : which == 1 ? bk : bv;
        bqkv[j] = src[col];
    }
}

// ---------------- im2col (p=8 sampled patches only) --------------------------
__global__ void im2col2(const float* __restrict__ x, float* __restrict__ T) {
    __shared__ float buf[192];
    int i = blockIdx.x, b = blockIdx.y;
    int jdx = 4 * i + 3;
    int ph = jdx / 28, pw = jdx % 28;
    const float* xb = x + (size_t)b * 3 * 224 * 224 + (size_t)(ph * 8) * 224 + pw * 8;
    int t = threadIdx.x;
    int c = t >> 6, pos = t & 63;
    int pi = pos >> 3, pj = pos & 7;
    buf[pos * 3 + c] = f2tf_f(xb[((size_t)c * 224 + pi) * 224 + pj]);
    __syncthreads();
    T[((size_t)b * 196 + i) * 192 + t] = buf[t];
}
__global__ void cls_fill(const float* __restrict__ cls1,
                         const float* __restrict__ cls2,
                         float* __restrict__ z) {
    int b = blockIdx.x, e = threadIdx.x;
    z[((size_t)b * NTOK + 0)   * EMB_ + e] = cls2[e];
    z[((size_t)b * NTOK + 197) * EMB_ + e] = cls1[e];
}

// ---------------- patch1 GEMM: implicit im2col, 3-stage, frag double-buffer --
__global__ __launch_bounds__(256)
void gemm_pe1(const float* __restrict__ x, const float* __restrict__ Bm,
              const float* __restrict__ bias, float* __restrict__ C) {
    extern __shared__ float smem[];
    float* As = smem;                         // [3][128*ASTR]
    float* Bs = smem + 3 * 128 * ASTR;        // [3][32*BSTR]
    int tid = threadIdx.x;
    int bm = blockIdx.y * 128, bn = blockIdx.x * 128;
    int wid = tid >> 5, lane = tid & 31;
    int wm = wid & 3, wn = wid >> 2;
    int gid = lane >> 2, tg = lane & 3;
    int aRow = tid >> 3, aC4 = (tid & 7) << 2;
    int pj0 = aC4 & 15, gsel = aC4 >> 4;
    int arow = (wm * 32 + gid) * ASTR + tg;
    int brow = tg * BSTR + wn * 64 + gid;

    size_t rowb[4];
#pragma unroll
    for (int i = 0; i < 4; i++) {
        int m = bm + aRow + i * 32;
        int b = m / 196, j = m % 196;
        int ph = j / 14, pw = j % 14;
        rowb[i] = (size_t)b * 150528 + (size_t)(ph * 16) * 224 + pw * 16;
    }

    auto loadA = [&](int s, int k0) {
        float* dst = As + s * 128 * ASTR;
        int gidx = (k0 >> 4) + gsel;
        int c = gidx >> 4, pi = gidx & 15;
        size_t off = (size_t)c * 50176 + pi * 224 + pj0;
#pragma unroll
        for (int i = 0; i < 4; i++)
            cpa16(dst + (aRow + i * 32) * ASTR + aC4, x + rowb[i] + off, true);
    };
    auto loadB = [&](int s, int k0) {
        float* dst = Bs + s * 32 * BSTR;
#pragma unroll
        for (int i = 0; i < 4; i++) {
            int idx = tid + i * 256;
            int kr = idx >> 5, c4 = (idx & 31) << 2;
            cpa16(dst + kr * BSTR + c4, Bm + (size_t)(k0 + kr) * 256 + bn + c4, true);
        }
    };
    auto ldfA = [&](unsigned (&dst)[2][4], const float* aST, int kk) {
        const float* ap = aST + arow + kk;
#pragma unroll
        for (int mt = 0; mt < 2; mt++) {
            dst[mt][0] = __float_as_uint(ap[mt * 16 * ASTR]);
            dst[mt][1] = __float_as_uint(ap[(mt * 16 + 8) * ASTR]);
            dst[mt][2] = __float_as_uint(ap[mt * 16 * ASTR + 4]);
            dst[mt][3] = __float_as_uint(ap[(mt * 16 + 8) * ASTR + 4]);
        }
    };
    auto ldfB = [&](unsigned (&dst)[8][2], const float* bST, int kk) {
        const float* bp = bST + brow + kk * BSTR;
#pragma unroll
        for (int nt = 0; nt < 8; nt++) {
            dst[nt][0] = __float_as_uint(bp[nt * 8]);
            dst[nt][1] = __float_as_uint(bp[4 * BSTR + nt * 8]);
        }
    };

    float acc[2][8][4] = {};
    unsigned afb[2][2][4], bfb[2][8][2];
    const int nk = 768 / KC;                  // 24

    loadA(0, 0); loadB(0, 0); cpa_commit();
    loadA(1, KC); loadB(1, KC); cpa_commit();
    cpa_wait<1>(); __syncthreads();
    ldfA(afb[0], As, 0); ldfB(bfb[0], Bs, 0);

    for (int it = 0; it < nk; it++) {
        int s = it % 3;
        int s2 = (it + 2) % 3;
        if (it + 2 < nk) { loadA(s2, (it + 2) * KC); loadB(s2, (it + 2) * KC); }
        cpa_commit();
        const float* aST = As + s * 128 * ASTR;
        const float* bST = Bs + s * 32 * BSTR;
#pragma unroll
        for (int kk = 0; kk < KC; kk += 8) {
            int cb = (kk >> 3) & 1, nb = cb ^ 1;
            if (kk < KC - 8) {
                ldfA(afb[nb], aST, kk + 8); ldfB(bfb[nb], bST, kk + 8);
            } else if (it + 1 < nk) {
                cpa_wait<1>(); __syncthreads();
                int s1 = (it + 1) % 3;
                ldfA(afb[nb], As + s1 * 128 * ASTR, 0);
                ldfB(bfb[nb], Bs + s1 * 32 * BSTR, 0);
            }
#pragma unroll
            for (int mt = 0; mt < 2; mt++)
#pragma unroll
                for (int nt = 0; nt < 8; nt++)
                    mma8(acc[mt][nt], afb[cb][mt], bfb[cb][nt]);
        }
    }

#pragma unroll
    for (int mt = 0; mt < 2; mt++)
#pragma unroll
        for (int nt = 0; nt < 8; nt++) {
            int n = bn + wn * 64 + nt * 8 + tg * 2;
            float bv0 = bias[n], bv1 = bias[n + 1];
#pragma unroll
            for (int half = 0; half < 2; half++) {
                int m = bm + wm * 32 + mt * 16 + gid + half * 8;
                int b = m / 196, jj = m % 196;
                *(float2*)&C[((size_t)b * NTOK + 198 + jj) * EMB_ + n] =
                    make_float2(acc[mt][nt][half * 2] + bv0,
                                acc[mt][nt][half * 2 + 1] + bv1);
            }
        }
}

// ---------------- NN GEMM: 3-stage cp.async + fragment double-buffer ---------
// mode 0: plain   mode 2: patch2->z   mode 5: fused qkv (cvt)
__global__ __launch_bounds__(256)
void gemm_nn(const float* __restrict__ A, const float* __restrict__ Bm,
             const float* __restrict__ bias, float* __restrict__ C,
             int M, int N, int K, int mode) {
    extern __shared__ float smem[];
    float* As = smem;
    float* Bs = smem + 3 * 128 * ASTR;
    int tid = threadIdx.x;
    int bm = blockIdx.y * 128, bn = blockIdx.x * 128;
    int wid = tid >> 5, lane = tid & 31;
    int wm = wid & 3, wn = wid >> 2;
    int gid = lane >> 2, tg = lane & 3;
    int aRow = tid >> 3, aC4 = (tid & 7) << 2;
    int arow = (wm * 32 + gid) * ASTR + tg;
    int brow = tg * BSTR + wn * 64 + gid;

    auto loadA = [&](int s, int k0) {
        float* dst = As + s * 128 * ASTR;
#pragma unroll
        for (int i = 0; i < 4; i++) {
            int row = aRow + i * 32;
            bool p = (bm + row) < M;
            const float* src = A + (size_t)(p ? bm + row : bm) * K + k0 + aC4;
            cpa16(dst + row * ASTR + aC4, src, p);
        }
    };
    auto loadB = [&](int s, int k0) {
        float* dst = Bs + s * 32 * BSTR;
#pragma unroll
        for (int i = 0; i < 4; i++) {
            int idx = tid + i * 256;
            int kr = idx >> 5, c4 = (idx & 31) << 2;
            bool p = (k0 + kr) < K;
            const float* src = Bm + (size_t)(p ? k0 + kr : 0) * N + bn + c4;
            cpa16(dst + kr * BSTR + c4, src, p);
        }
    };
    auto ldfA = [&](unsigned (&dst)[2][4], const float* aST, int kk) {
        const float* ap = aST + arow + kk;
#pragma unroll
        for (int mt = 0; mt < 2; mt++) {
            dst[mt][0] = __float_as_uint(ap[mt * 16 * ASTR]);
            dst[mt][1] = __float_as_uint(ap[(mt * 16 + 8) * ASTR]);
            dst[mt][2] = __float_as_uint(ap[mt * 16 * ASTR + 4]);
            dst[mt][3] = __float_as_uint(ap[(mt * 16 + 8) * ASTR + 4]);
        }
    };
    auto ldfB = [&](unsigned (&dst)[8][2], const float* bST, int kk) {
        const float* bp = bST + brow + kk * BSTR;
#pragma unroll
        for (int nt = 0; nt < 8; nt++) {
            dst[nt][0] = __float_as_uint(bp[nt * 8]);
            dst[nt][1] = __float_as_uint(bp[4 * BSTR + nt * 8]);
        }
    };

    float acc[2][8][4] = {};
    unsigned afb[2][2][4], bfb[2][8][2];
    int nk = K / KC;

    loadA(0, 0); loadB(0, 0); cpa_commit();
    loadA(1, KC); loadB(1, KC); cpa_commit();
    cpa_wait<1>(); __syncthreads();
    ldfA(afb[0], As, 0); ldfB(bfb[0], Bs, 0);

    for (int it = 0; it < nk; it++) {
        int s = it % 3;
        int s2 = (it + 2) % 3;
        if (it + 2 < nk) { loadA(s2, (it + 2) * KC); loadB(s2, (it + 2) * KC); }
        cpa_commit();
        const float* aST = As + s * 128 * ASTR;
        const float* bST = Bs + s * 32 * BSTR;
#pragma unroll
        for (int kk = 0; kk < KC; kk += 8) {
            int cb = (kk >> 3) & 1, nb = cb ^ 1;
            if (kk < KC - 8) {
                ldfA(afb[nb], aST, kk + 8); ldfB(bfb[nb], bST, kk + 8);
            } else if (it + 1 < nk) {
                cpa_wait<1>(); __syncthreads();
                int s1 = (it + 1) % 3;
                ldfA(afb[nb], As + s1 * 128 * ASTR, 0);
                ldfB(bfb[nb], Bs + s1 * 32 * BSTR, 0);
            }
#pragma unroll
            for (int mt = 0; mt < 2; mt++)
#pragma unroll
                for (int nt = 0; nt < 8; nt++)
                    mma8(acc[mt][nt], afb[cb][mt], bfb[cb][nt]);
        }
    }

#pragma unroll
    for (int mt = 0; mt < 2; mt++) {
#pragma unroll
        for (int nt = 0; nt < 8; nt++) {
            int n = bn + wn * 64 + nt * 8 + tg * 2;
            float bv0 = bias ? bias[n] : 0.f;
            float bv1 = bias ? bias[n + 1] : 0.f;
#pragma unroll
            for (int half = 0; half < 2; half++) {
                int m = bm + wm * 32 + mt * 16 + gid + half * 8;
                if (m >= M) continue;
                float v0 = acc[mt][nt][half * 2 + 0] + bv0;
                float v1 = acc[mt][nt][half * 2 + 1] + bv1;
                if (mode == 5) { v0 = f2tf_f(v0); v1 = f2tf_f(v1); }
                float2 val = make_float2(v0, v1);
                if (mode == 0) {
                    *(float2*)&C[(size_t)m * N + n] = val;
                } else if (mode == 2) {
                    int b = m / 196, jj = m % 196;
                    *(float2*)&C[((size_t)b * NTOK + 1 + jj) * EMB_ + n] = val;
                } else {
                    int b = m / NTOK, t = m % NTOK;
                    int which = n >> 8, d2 = n & 255;
                    int hh = d2 >> 7, dd = d2 & 127;
                    *(float2*)&C[(size_t)which * (MTOK * EMB_) +
                                 (((size_t)b * 2 + hh) * NTOK + t) * 128 + dd] = val;
                }
            }
        }
    }
}

// ---------------- flash attention v2 (unchanged from R10) --------------------
__global__ __launch_bounds__(256)
void flash_attn(const float* __restrict__ Qg, const float* __restrict__ Kg,
                const float* __restrict__ Vg, float* __restrict__ Og) {
    extern __shared__ float smem[];
    float* Qs = smem;                       // [128][132]
    float* Ks = Qs + 128 * 132;             // [2][64][132]
    float* Vs = Ks + 2 * 64 * 132;          // [2][64][136]
    int tid = threadIdx.x, lane = tid & 31, wid = tid >> 5;
    int gid = lane >> 2, tg = lane & 3;
    int qt = blockIdx.x, bh = blockIdx.y;
    const float* Qb = Qg + (size_t)bh * 394 * 128;
    const float* Kb = Kg + (size_t)bh * 394 * 128;
    const float* Vb = Vg + (size_t)bh * 394 * 128;
    float* Ob = Og + (size_t)(bh >> 1) * NTOK * EMB_ + (bh & 1) * 128;
    int qbase = qt * 128;
    int r0 = wid * 16 + gid;

    auto loadQ = [&]() {
#pragma unroll
        for (int i = 0; i < 16; i++) {
            int idx = tid + i * 256; int row = idx >> 5; int cc = (idx & 31) << 2;
            bool p = (qbase + row) < 394;
            cpa16(Qs + row * 132 + cc, Qb + (size_t)(p ? qbase + row : 0) * 128 + cc, p);
        }
    };
    auto loadK = [&](int st, int kt) {
        float* dst = Ks + st * 64 * 132;
#pragma unroll
        for (int i = 0; i < 8; i++) {
            int idx = tid + i * 256; int row = idx >> 5; int cc = (idx & 31) << 2;
            bool p = (kt * 64 + row) < 394;
            cpa16(dst + row * 132 + cc, Kb + (size_t)(p ? kt * 64 + row : 0) * 128 + cc, p);
        }
    };
    auto loadV = [&](int st, int kt) {
        float* dst = Vs + st * 64 * 136;
#pragma unroll
        for (int i = 0; i < 8; i++) {
            int idx = tid + i * 256; int row = idx >> 5; int cc = (idx & 31) << 2;
            bool p = (kt * 64 + row) < 394;
            cpa16(dst + row * 136 + cc, Vb + (size_t)(p ? kt * 64 + row : 0) * 128 + cc, p);
        }
    };

    loadQ(); loadK(0, 0); loadV(0, 0); cpa_commit();
    loadK(1, 1); loadV(1, 1); cpa_commit();

    float accO[16][4] = {};
    float m0 = -1e30f, m1 = -1e30f, l0 = 0.f, l1 = 0.f;

    for (int kt = 0; kt < FA_NKT; kt++) {
        int st = kt & 1;
        cpa_wait<1>();
        __syncthreads();

        float accS[8][4] = {};
        {
            const float* qp = Qs + r0 * 132 + tg;
            const float* kp = Ks + st * 64 * 132 + gid * 132 + tg;
#pragma unroll
            for (int kk = 0; kk < 128; kk += 8) {
                unsigned af[4];
                af[0] = __float_as_uint(qp[kk]);
                af[1] = __float_as_uint(qp[8 * 132 + kk]);
                af[2] = __float_as_uint(qp[kk + 4]);
                af[3] = __float_as_uint(qp[8 * 132 + kk + 4]);
#pragma unroll
                for (int nt = 0; nt < 8; nt++) {
                    unsigned bf[2];
                    bf[0] = __float_as_uint(kp[nt * 8 * 132 + kk]);
                    bf[1] = __float_as_uint(kp[nt * 8 * 132 + kk + 4]);
                    mma8(accS[nt], af, bf);
                }
            }
        }
        int cb = kt * 64 + tg * 2;
#pragma unroll
        for (int nt = 0; nt < 8; nt++) {
            int c0 = cb + nt * 8;
            if (c0 >= 394)     { accS[nt][0] = -1e30f; accS[nt][2] = -1e30f; }
            if (c0 + 1 >= 394) { accS[nt][1] = -1e30f; accS[nt][3] = -1e30f; }
        }
        float rm0 = -1e30f, rm1 = -1e30f;
#pragma unroll
        for (int nt = 0; nt < 8; nt++) {
            rm0 = fmaxf(rm0, fmaxf(accS[nt][0], accS[nt][1]));
            rm1 = fmaxf(rm1, fmaxf(accS[nt][2], accS[nt][3]));
        }
        rm0 = fmaxf(rm0, __shfl_xor_sync(0xffffffffu, rm0, 1));
        rm0 = fmaxf(rm0, __shfl_xor_sync(0xffffffffu, rm0, 2));
        rm1 = fmaxf(rm1, __shfl_xor_sync(0xffffffffu, rm1, 1));
        rm1 = fmaxf(rm1, __shfl_xor_sync(0xffffffffu, rm1, 2));
        float mn0 = fmaxf(m0, rm0), mn1 = fmaxf(m1, rm1);
        float sc0 = __expf(m0 - mn0), sc1 = __expf(m1 - mn1);
        float rs0 = 0.f, rs1 = 0.f;
#pragma unroll
        for (int nt = 0; nt < 8; nt++) {
            accS[nt][0] = __expf(accS[nt][0] - mn0);
            accS[nt][1] = __expf(accS[nt][1] - mn0);
            accS[nt][2] = __expf(accS[nt][2] - mn1);
            accS[nt][3] = __expf(accS[nt][3] - mn1);
            rs0 += accS[nt][0] + accS[nt][1];
            rs1 += accS[nt][2] + accS[nt][3];
        }
        rs0 += __shfl_xor_sync(0xffffffffu, rs0, 1);
        rs0 += __shfl_xor_sync(0xffffffffu, rs0, 2);
        rs1 += __shfl_xor_sync(0xffffffffu, rs1, 1);
        rs1 += __shfl_xor_sync(0xffffffffu, rs1, 2);
        l0 = l0 * sc0 + rs0;  l1 = l1 * sc1 + rs1;
        m0 = mn0;  m1 = mn1;
#pragma unroll
        for (int nt = 0; nt < 16; nt++) {
            accO[nt][0] *= sc0; accO[nt][1] *= sc0;
            accO[nt][2] *= sc1; accO[nt][3] *= sc1;
        }
        {
            const float* vp = Vs + st * 64 * 136 + tg * 136 + gid;
            int s0l = (lane & ~3) | (tg >> 1);
            int s1l = s0l + 2;
            bool odd = (tg & 1);
#pragma unroll
            for (int j = 0; j < 8; j++) {
                float p00 = __shfl_sync(0xffffffffu, accS[j][0], s0l);
                float p01 = __shfl_sync(0xffffffffu, accS[j][1], s0l);
                float p10 = __shfl_sync(0xffffffffu, accS[j][2], s0l);
                float p11 = __shfl_sync(0xffffffffu, accS[j][3], s0l);
                float q00 = __shfl_sync(0xffffffffu, accS[j][0], s1l);
                float q01 = __shfl_sync(0xffffffffu, accS[j][1], s1l);
                float q10 = __shfl_sync(0xffffffffu, accS[j][2], s1l);
                float q11 = __shfl_sync(0xffffffffu, accS[j][3], s1l);
                unsigned a[4];
                a[0] = __float_as_uint(f2tf_f(odd ? p01 : p00));
                a[1] = __float_as_uint(f2tf_f(odd ? p11 : p10));
                a[2] = __float_as_uint(f2tf_f(odd ? q01 : q00));
                a[3] = __float_as_uint(f2tf_f(odd ? q11 : q10));
                const float* vj = vp + j * 8 * 136;
#pragma unroll
                for (int nt = 0; nt < 16; nt++) {
                    unsigned bf[2];
                    bf[0] = __float_as_uint(vj[nt * 8]);
                    bf[1] = __float_as_uint(vj[4 * 136 + nt * 8]);
                    mma8(accO[nt], a, bf);
                }
            }
        }
        __syncthreads();
        if (kt + 2 < FA_NKT) { loadK(st, kt + 2); loadV(st, kt + 2); }
        cpa_commit();
    }

    float inv0 = 1.f / (l0 * 16.f), inv1 = 1.f / (l1 * 16.f);
    int gr0 = qbase + r0, gr1 = gr0 + 8;
#pragma unroll
    for (int nt = 0; nt < 16; nt++) {
        int col = nt * 8 + tg * 2;
        if (gr0 < 394)
            *(float2*)&Ob[(size_t)gr0 * EMB_ + col] =
                make_float2(f2tf_f(accO[nt][0] * inv0), f2tf_f(accO[nt][1] * inv0));
        if (gr1 < 394)
            *(float2*)&Ob[(size_t)gr1 * EMB_ + col] =
                make_float2(f2tf_f(accO[nt][2] * inv1), f2tf_f(accO[nt][3] * inv1));
    }
}

// ---------------- layer norm (ln1) --------------------------------------------
__global__ __launch_bounds__(256)
void ln_kernel(const float* __restrict__ in, const float* __restrict__ g,
               const float* __restrict__ b, float* __restrict__ out,
               const float* __restrict__ addsrc, int docvt) {
    int r = blockIdx.x, e = threadIdx.x;
    size_t idx = (size_t)r * EMB_ + e;
    float v = in[idx];
    float s = v, s2 = v * v;
#pragma unroll
    for (int off = 16; off > 0; off >>= 1) {
        s  += __shfl_xor_sync(0xffffffff, s,  off);
        s2 += __shfl_xor_sync(0xffffffff, s2, off);
    }
    __shared__ float ss[8], ss2[8];
    if ((e & 31) == 0) { ss[e >> 5] = s; ss2[e >> 5] = s2; }
    __syncthreads();
    float tot = 0.f, tot2 = 0.f;
#pragma unroll
    for (int i = 0; i < 8; i++) { tot += ss[i]; tot2 += ss2[i]; }
    float mean = tot * (1.f / EMB_);
    float var = tot2 * (1.f / EMB_) - mean * mean;
    float nv = (v - mean) * rsqrtf(var + 1e-5f) * g[e] + b[e];
    if (docvt) nv = f2tf_f(nv);
    out[idx] = addsrc ? (addsrc[idx] + nv) : nv;
}

// ---------------- fused ln2 + residual + pool partial -------------------------
__global__ __launch_bounds__(256)
void ln2_pool(const float* __restrict__ h, const float* __restrict__ g,
              const float* __restrict__ bb, float* __restrict__ z,
              float* __restrict__ pool) {
    int b = blockIdx.x, seg = blockIdx.y, e = threadIdx.x;
    int t0 = seg * 50, t1 = t0 + 50; if (t1 > NTOK) t1 = NTOK;
    __shared__ float ss[8], ss2[8];
    float ge = g[e], be = bb[e];
    float accp = 0.f;
    for (int t = t0; t < t1; t++) {
        size_t idx = ((size_t)b * NTOK + t) * EMB_ + e;
        float v = h[idx];
        float s = v, s2 = v * v;
#pragma unroll
        for (int off = 16; off > 0; off >>= 1) {
            s  += __shfl_xor_sync(0xffffffff, s,  off);
            s2 += __shfl_xor_sync(0xffffffff, s2, off);
        }
        if ((e & 31) == 0) { ss[e >> 5] = s; ss2[e >> 5] = s2; }
        __syncthreads();
        float tot = 0.f, tot2 = 0.f;
#pragma unroll
        for (int i = 0; i < 8; i++) { tot += ss[i]; tot2 += ss2[i]; }
        float mean = tot * (1.f / EMB_);
        float var = tot2 * (1.f / EMB_) - mean * mean;
        float nv = (v - mean) * rsqrtf(var + 1e-5f) * ge + be;
        float zv = z[idx] + nv;
        z[idx] = zv;
        accp += zv;
        __syncthreads();
    }
    pool[((size_t)b * 8 + seg) * EMB_ + e] = accp;
}

// ---------------- head ---------------------------------------------------------
__global__ __launch_bounds__(256)
void head_kernel(const float* __restrict__ pool, const float* __restrict__ g,
                 const float* __restrict__ bb, const float* __restrict__ Wc,
                 const float* __restrict__ bc, float* __restrict__ out) {
    int b = blockIdx.x, e = threadIdx.x;
    float s = 0.f;
#pragma unroll
    for (int i = 0; i < 8; i++) s += pool[((size_t)b * 8 + i) * EMB_ + e];
    float pooled = s * (1.f / NTOK);
    __shared__ float red[256];
    red[e] = pooled; __syncthreads();
    for (int st = 128; st > 0; st >>= 1) { if (e < st) red[e] += red[e + st]; __syncthreads(); }
    float mean = red[0] * (1.f / EMB_);
    __syncthreads();
    float d = pooled - mean;
    red[e] = d * d; __syncthreads();
    for (int st = 128; st > 0; st >>= 1) { if (e < st) red[e] += red[e + st]; __syncthreads(); }
    float var = red[0] * (1.f / EMB_);
    __syncthreads();
    float nv = d * rsqrtf(var + 1e-5f) * g[e] + bb[e];
    red[e] = nv * Wc[e * 2 + 0]; __syncthreads();
    for (int st = 128; st > 0; st >>= 1) { if (e < st) red[e] += red[e + st]; __syncthreads(); }
    float l0 = red[0] + bc[0];
    __syncthreads();
    red[e] = nv * Wc[e * 2 + 1]; __syncthreads();
    for (int st = 128; st > 0; st >>= 1) { if (e < st) red[e] += red[e + st]; __syncthreads(); }
    float l1 = red[0] + bc[1];
    if (e == 0) {
        float mx = fmaxf(l0, l1);
        float lse = mx + logf(expf(l0 - mx) + expf(l1 - mx));
        out[b * 2 + 0] = l0 - lse;
        out[b * 2 + 1] = l1 - lse;
    }
}

// ---------------- launch --------------------------------------------------------
extern "C" void kernel_launch(void* const* d_in, const int* in_sizes, int n_in,
                              void* d_out, int out_size) {
    const float* x     = (const float*)d_in[0];
    const float* W1    = (const float*)d_in[1];
    const float* b1    = (const float*)d_in[2];
    const float* cls1  = (const float*)d_in[3];
    const float* W2    = (const float*)d_in[4];
    const float* b2    = (const float*)d_in[5];
    const float* cls2  = (const float*)d_in[6];
    const float* ln1_g = (const float*)d_in[7];
    const float* ln1_b = (const float*)d_in[8];
    const float* Wq    = (const float*)d_in[9];
    const float* bq    = (const float*)d_in[10];
    const float* Wk    = (const float*)d_in[11];
    const float* bk    = (const float*)d_in[12];
    const float* Wv    = (const float*)d_in[13];
    const float* bv    = (const float*)d_in[14];
    const float* Wp    = (const float*)d_in[15];
    const float* bp    = (const float*)d_in[16];
    const float* ln2_g = (const float*)d_in[17];
    const float* ln2_b = (const float*)d_in[18];
    const float* lnc_g = (const float*)d_in[19];
    const float* lnc_b = (const float*)d_in[20];
    const float* Wc    = (const float*)d_in[21];
    const float* bc    = (const float*)d_in[22];
    float* out = (float*)d_out;

    static int inited = 0;
    if (!inited) {
        cudaFuncSetAttribute(gemm_nn,  cudaFuncAttributeMaxDynamicSharedMemorySize, SMEM_NN);
        cudaFuncSetAttribute(gemm_pe1, cudaFuncAttributeMaxDynamicSharedMemorySize, SMEM_NN);
        cudaFuncSetAttribute(flash_attn, cudaFuncAttributeMaxDynamicSharedMemorySize, FA_SMEM);
        inited = 1;
    }

    float *T2, *Wt, *bqkv, *z, *h, *qkv, *o, *pool;
    cudaGetSymbolAddress((void**)&T2, g_T2);
    cudaGetSymbolAddress((void**)&Wt, g_Wt);
    cudaGetSymbolAddress((void**)&bqkv, g_bqkv);
    cudaGetSymbolAddress((void**)&z,  g_z);
    cudaGetSymbolAddress((void**)&h,  g_h);
    cudaGetSymbolAddress((void**)&qkv, g_qkv);
    cudaGetSymbolAddress((void**)&o,  g_o);
    cudaGetSymbolAddress((void**)&pool, g_pool);

    prep_w<<<(PREP_N + 255) / 256, 256>>>(W1, W2, Wq, Wk, Wv, Wp, bq, bk, bv, Wt, bqkv);
    im2col2<<<dim3(196, B_), 192>>>(x, T2);
    cls_fill<<<B_, 256>>>(cls1, cls2, z);

    gemm_pe1<<<dim3(2, 196), 256, SMEM_NN>>>(x, Wt + OFF_W1P, b1, z);
    gemm_nn<<<dim3(2, 196), 256, SMEM_NN>>>(T2, Wt + OFF_W2, b2, z, MPE, 256, 192, 2);

    ln_kernel<<<MTOK, 256>>>(z, ln1_g, ln1_b, h, nullptr, 1);

    gemm_nn<<<dim3(6, 394), 256, SMEM_NN>>>(h, Wt + OFF_WQKV, bqkv, qkv, MTOK, 768, 256, 5);

    flash_attn<<<dim3(4, 256), 256, FA_SMEM>>>(qkv, qkv + (size_t)MTOK * EMB_,
                                               qkv + 2 * (size_t)MTOK * EMB_, o);

    gemm_nn<<<dim3(2, 394), 256, SMEM_NN>>>(o, Wt + OFF_WP, bp, h, MTOK, 256, 256, 0);

    ln2_pool<<<dim3(B_, 8), 256>>>(h, ln2_g, ln2_b, z, pool);
    head_kernel<<<B_, 256>>>(pool, lnc_g, lnc_b, Wc, bc, out);
}

// round 13
// speedup vs baseline: 1.6665x; 1.4865x over previous
#include <cuda_runtime.h>
#include <cuda_fp16.h>
#include <math.h>

#define B_      128
#define EMB_    256
#define NTOK    394
#define MTOK    (B_ * NTOK)          // 50432
#define MPE     (B_ * 196)           // 25088
#define XN      (B_ * 3 * 224 * 224) // 19267584

#define KC      32
#define ASTRH   40                   // A smem row stride (halfs)
#define BSTRH2  136                  // B smem row stride (half2)
#define A_STG   (128 * ASTRH)        // 5120 halfs / stage
#define B_STG   (BSTRH2 * 16 * 2)    // 4352 halfs / stage
#define SMEM_NN ((3 * (A_STG + B_STG)) * 2)   // 56832 B
#define FA_SMEM (128*136*2 + 2*64*136*2 + 2*32*136*4)  // 104448
#define FA_NKT  7
#define QKV_SZ  ((size_t)B_ * 2 * 394 * 128)  // halfs per q/k/v region

// ---------------- scratch ---------------------------------------------------
__device__ __half g_x16[XN];
__device__ __half g_T2[MPE * 192];
__device__ __half g_Wt[507904];      // W2 | Wp | W1perm | Wqkv, k-pair interleaved
__device__ float  g_bqkv[768];
__device__ float  g_z [MTOK * EMB_];
__device__ __half g_h16[MTOK * EMB_];
__device__ float  g_hf[MTOK * EMB_];
__device__ __half g_qkv[3 * QKV_SZ];
__device__ __half g_o16[MTOK * EMB_];
__device__ float  g_pool[B_ * 8 * EMB_];

#define OFF_W2   0
#define OFF_WP   49152
#define OFF_W1P  114688
#define OFF_WQKV 311296
#define PREP_N   508672

// ---------------- helpers ----------------------------------------------------
__device__ __forceinline__ void mma16(float* acc, const unsigned* a, const unsigned* b) {
    asm volatile(
        "mma.sync.aligned.m16n8k16.row.col.f32.f16.f16.f32 "
        "{%0,%1,%2,%3}, {%4,%5,%6,%7}, {%8,%9}, {%0,%1,%2,%3};\n"
        : "+f"(acc[0]), "+f"(acc[1]), "+f"(acc[2]), "+f"(acc[3])
        : "r"(a[0]), "r"(a[1]), "r"(a[2]), "r"(a[3]), "r"(b[0]), "r"(b[1]));
}
__device__ __forceinline__ unsigned pack2(float a, float b) {
    __half2 h = __floats2half2_rn(a, b);
    return *reinterpret_cast<unsigned*>(&h);
}
__device__ __forceinline__ void cpa16(void* dst, const void* src, bool pred) {
    unsigned d = (unsigned)__cvta_generic_to_shared(dst);
    int sz = pred ? 16 : 0;
    asm volatile("cp.async.cg.shared.global [%0], [%1], 16, %2;\n"
                 :: "r"(d), "l"(src), "r"(sz));
}
__device__ __forceinline__ void cpa_commit() { asm volatile("cp.async.commit_group;\n"); }
template <int N>
__device__ __forceinline__ void cpa_wait() { asm volatile("cp.async.wait_group %0;\n" :: "n"(N)); }

// ---------------- weight prep: half + k-pair interleave ----------------------
__global__ void prep_w(const float* __restrict__ W1, const float* __restrict__ W2,
                       const float* __restrict__ Wq, const float* __restrict__ Wk,
                       const float* __restrict__ Wv, const float* __restrict__ Wp,
                       const float* __restrict__ bq, const float* __restrict__ bk,
                       const float* __restrict__ bv,
                       __half* __restrict__ out, float* __restrict__ bqkv) {
    int i = blockIdx.x * 256 + threadIdx.x;
    if (i >= PREP_N) return;
    if (i >= 507904) {                      // qkv bias
        int j = i - 507904;
        int which = j >> 8, col = j & 255;
        const float* src = which == 0 ? bq : which == 1 ? bk : bv;
        bqkv[j] = src[col];
        return;
    }
    float v;
    if (i < OFF_WP) {                       // W2 [192][256] -> [96][256][2]
        int kp = i >> 9, r = i & 511, n = r >> 1, p = r & 1;
        v = W2[(2 * kp + p) * 256 + n];
    } else if (i < OFF_W1P) {               // Wp [256][256] -> [128][256][2]
        int idx = i - OFF_WP;
        int kp = idx >> 9, r = idx & 511, n = r >> 1, p = r & 1;
        v = Wp[(2 * kp + p) * 256 + n];
    } else if (i < OFF_WQKV) {              // W1 permuted k'=c*256+pi*16+pj, interleaved
        int idx = i - OFF_W1P;
        int kp = idx >> 9, r = idx & 511, n = r >> 1, p = r & 1;
        int kpr = 2 * kp + p;
        int c = kpr >> 8, rem = kpr & 255;
        int pi = rem >> 4, pj = rem & 15;
        v = W1[((pi * 16 + pj) * 3 + c) * 256 + n];
    } else {                                // Wqkv [256][768] -> [128][768][2]
        int idx = i - OFF_WQKV;
        int kp = idx / 1536, r = idx % 1536, n = r >> 1, p = r & 1;
        int k = 2 * kp + p;
        int which = n >> 8, col = n & 255;
        const float* src = which == 0 ? Wq : which == 1 ? Wk : Wv;
        v = src[k * 256 + col];
    }
    out[i] = __float2half_rn(v);
}

// ---------------- x -> half ---------------------------------------------------
__global__ void x2h(const float* __restrict__ x, __half* __restrict__ xh) {
    int i = (blockIdx.x * 256 + threadIdx.x) * 4;
    float4 v = *(const float4*)(x + i);
    __half2 h0 = __floats2half2_rn(v.x, v.y);
    __half2 h1 = __floats2half2_rn(v.z, v.w);
    *(__half2*)(xh + i) = h0;
    *(__half2*)(xh + i + 2) = h1;
}

// ---------------- im2col (p=8 sampled patches) -------------------------------
__global__ void im2col2(const float* __restrict__ x, __half* __restrict__ T) {
    __shared__ float buf[192];
    int i = blockIdx.x, b = blockIdx.y;
    int jdx = 4 * i + 3;
    int ph = jdx / 28, pw = jdx % 28;
    const float* xb = x + (size_t)b * 3 * 224 * 224 + (size_t)(ph * 8) * 224 + pw * 8;
    int t = threadIdx.x;
    int c = t >> 6, pos = t & 63;
    int pi = pos >> 3, pj = pos & 7;
    buf[pos * 3 + c] = xb[((size_t)c * 224 + pi) * 224 + pj];
    __syncthreads();
    T[((size_t)b * 196 + i) * 192 + t] = __float2half_rn(buf[t]);
}
__global__ void cls_fill(const float* __restrict__ cls1,
                         const float* __restrict__ cls2,
                         float* __restrict__ z) {
    int b = blockIdx.x, e = threadIdx.x;
    z[((size_t)b * NTOK + 0)   * EMB_ + e] = cls2[e];
    z[((size_t)b * NTOK + 197) * EMB_ + e] = cls1[e];
}

// ---------------- patch1 GEMM: implicit im2col from x16, fp16 mma ------------
__global__ __launch_bounds__(256, 2)
void gemm_pe1(const __half* __restrict__ x, const __half* __restrict__ Bm,
              const float* __restrict__ bias, float* __restrict__ C) {
    extern __shared__ __half smem[];
    __half* As = smem;                         // [3][A_STG]
    __half* Bs = smem + 3 * A_STG;             // [3][B_STG]
    int tid = threadIdx.x;
    int bm = blockIdx.y * 128, bn = blockIdx.x * 128;
    int wid = tid >> 5, lane = tid & 31;
    int wm = wid & 3, wn = wid >> 2;
    int gid = lane >> 2, tg = lane & 3;

    size_t rowb[2];
#pragma unroll
    for (int i = 0; i < 2; i++) {
        int m = bm + (tid >> 2) + i * 64;
        int b = m / 196, j = m % 196;
        int ph = j / 14, pw = j % 14;
        rowb[i] = (size_t)b * 150528 + (size_t)(ph * 16) * 224 + pw * 16;
    }
    int ch = tid & 3;
    int pj0 = (ch & 1) * 8, gsel = ch >> 1;

    auto loadA = [&](int s, int k0) {
        __half* dst = As + s * A_STG;
        int gidx = (k0 >> 4) + gsel;
        int c = gidx >> 4, pi = gidx & 15;
        size_t off = (size_t)c * 50176 + pi * 224 + pj0;
#pragma unroll
        for (int i = 0; i < 2; i++) {
            int row = (tid >> 2) + i * 64;
            cpa16(dst + row * ASTRH + ch * 8, x + rowb[i] + off, true);
        }
    };
    auto loadB = [&](int s, int k0) {
        const __half2* B2 = (const __half2*)Bm;
        __half2* dst = (__half2*)(Bs + s * B_STG);
        int kp0 = k0 >> 1;
#pragma unroll
        for (int i = 0; i < 2; i++) {
            int idx = tid + i * 256;
            int row = idx >> 5, cc = (idx & 31) << 2;
            cpa16(dst + row * BSTRH2 + cc, B2 + (size_t)(kp0 + row) * 256 + bn + cc, true);
        }
    };

    float acc[2][8][4] = {};
    const int nk = 768 / KC;                   // 24
    loadA(0, 0); loadB(0, 0); cpa_commit();
    loadA(1, KC); loadB(1, KC); cpa_commit();

    int arow = wm * 32 + gid;
    for (int it = 0; it < nk; it++) {
        cpa_wait<1>(); __syncthreads();
        if (it + 2 < nk) { loadA((it + 2) % 3, (it + 2) * KC); loadB((it + 2) % 3, (it + 2) * KC); }
        cpa_commit();
        const unsigned* Au = (const unsigned*)(As + (it % 3) * A_STG);
        const unsigned* Bu = (const unsigned*)(Bs + (it % 3) * B_STG);
#pragma unroll
        for (int kk2 = 0; kk2 < 2; kk2++) {
            unsigned af[2][4], bf[8][2];
#pragma unroll
            for (int mt = 0; mt < 2; mt++) {
                int r = arow + mt * 16;
                af[mt][0] = Au[r * 20 + kk2 * 8 + tg];
                af[mt][1] = Au[(r + 8) * 20 + kk2 * 8 + tg];
                af[mt][2] = Au[r * 20 + kk2 * 8 + tg + 4];
                af[mt][3] = Au[(r + 8) * 20 + kk2 * 8 + tg + 4];
            }
#pragma unroll
            for (int nt = 0; nt < 8; nt++) {
                int n = wn * 64 + nt * 8 + gid;
                bf[nt][0] = Bu[(kk2 * 8 + tg) * BSTRH2 + n];
                bf[nt][1] = Bu[(kk2 * 8 + tg + 4) * BSTRH2 + n];
            }
#pragma unroll
            for (int mt = 0; mt < 2; mt++)
#pragma unroll
                for (int nt = 0; nt < 8; nt++)
                    mma16(acc[mt][nt], af[mt], bf[nt]);
        }
        __syncthreads();
    }

#pragma unroll
    for (int mt = 0; mt < 2; mt++)
#pragma unroll
        for (int nt = 0; nt < 8; nt++) {
            int n = bn + wn * 64 + nt * 8 + tg * 2;
            float bv0 = bias[n], bv1 = bias[n + 1];
#pragma unroll
            for (int half_ = 0; half_ < 2; half_++) {
                int m = bm + wm * 32 + mt * 16 + gid + half_ * 8;
                int b = m / 196, jj = m % 196;
                *(float2*)&C[((size_t)b * NTOK + 198 + jj) * EMB_ + n] =
                    make_float2(acc[mt][nt][half_ * 2] + bv0,
                                acc[mt][nt][half_ * 2 + 1] + bv1);
            }
        }
}

// ---------------- NN GEMM fp16: modes 0 (proj->f32), 2 (pe2->z), 5 (qkv) -----
__global__ __launch_bounds__(256, 2)
void gemm_nn(const __half* __restrict__ A, const __half* __restrict__ Bm,
             const float* __restrict__ bias, void* __restrict__ Cout,
             int N, int K, int mode) {
    extern __shared__ __half smem[];
    __half* As = smem;
    __half* Bs = smem + 3 * A_STG;
    int tid = threadIdx.x;
    int bm = blockIdx.y * 128, bn = blockIdx.x * 128;
    int wid = tid >> 5, lane = tid & 31;
    int wm = wid & 3, wn = wid >> 2;
    int gid = lane >> 2, tg = lane & 3;

    auto loadA = [&](int s, int k0) {
        __half* dst = As + s * A_STG;
#pragma unroll
        for (int i = 0; i < 2; i++) {
            int idx = tid + i * 256;
            int row = idx >> 2, cc = (idx & 3) << 3;
            cpa16(dst + row * ASTRH + cc, A + (size_t)(bm + row) * K + k0 + cc, true);
        }
    };
    auto loadB = [&](int s, int k0) {
        const __half2* B2 = (const __half2*)Bm;
        __half2* dst = (__half2*)(Bs + s * B_STG);
        int kp0 = k0 >> 1;
#pragma unroll
        for (int i = 0; i < 2; i++) {
            int idx = tid + i * 256;
            int row = idx >> 5, cc = (idx & 31) << 2;
            cpa16(dst + row * BSTRH2 + cc, B2 + (size_t)(kp0 + row) * N + bn + cc, true);
        }
    };

    float acc[2][8][4] = {};
    int nk = K / KC;
    loadA(0, 0); loadB(0, 0); cpa_commit();
    loadA(1, KC); loadB(1, KC); cpa_commit();

    int arow = wm * 32 + gid;
    for (int it = 0; it < nk; it++) {
        cpa_wait<1>(); __syncthreads();
        if (it + 2 < nk) { loadA((it + 2) % 3, (it + 2) * KC); loadB((it + 2) % 3, (it + 2) * KC); }
        cpa_commit();
        const unsigned* Au = (const unsigned*)(As + (it % 3) * A_STG);
        const unsigned* Bu = (const unsigned*)(Bs + (it % 3) * B_STG);
#pragma unroll
        for (int kk2 = 0; kk2 < 2; kk2++) {
            unsigned af[2][4], bf[8][2];
#pragma unroll
            for (int mt = 0; mt < 2; mt++) {
                int r = arow + mt * 16;
                af[mt][0] = Au[r * 20 + kk2 * 8 + tg];
                af[mt][1] = Au[(r + 8) * 20 + kk2 * 8 + tg];
                af[mt][2] = Au[r * 20 + kk2 * 8 + tg + 4];
                af[mt][3] = Au[(r + 8) * 20 + kk2 * 8 + tg + 4];
            }
#pragma unroll
            for (int nt = 0; nt < 8; nt++) {
                int n = wn * 64 + nt * 8 + gid;
                bf[nt][0] = Bu[(kk2 * 8 + tg) * BSTRH2 + n];
                bf[nt][1] = Bu[(kk2 * 8 + tg + 4) * BSTRH2 + n];
            }
#pragma unroll
            for (int mt = 0; mt < 2; mt++)
#pragma unroll
                for (int nt = 0; nt < 8; nt++)
                    mma16(acc[mt][nt], af[mt], bf[nt]);
        }
        __syncthreads();
    }

#pragma unroll
    for (int mt = 0; mt < 2; mt++) {
#pragma unroll
        for (int nt = 0; nt < 8; nt++) {
            int n = bn + wn * 64 + nt * 8 + tg * 2;
            float bv0 = bias ? bias[n] : 0.f;
            float bv1 = bias ? bias[n + 1] : 0.f;
#pragma unroll
            for (int half_ = 0; half_ < 2; half_++) {
                int m = bm + wm * 32 + mt * 16 + gid + half_ * 8;
                float v0 = acc[mt][nt][half_ * 2 + 0] + bv0;
                float v1 = acc[mt][nt][half_ * 2 + 1] + bv1;
                if (mode == 0) {
                    *(float2*)&((float*)Cout)[(size_t)m * 256 + n] = make_float2(v0, v1);
                } else if (mode == 2) {
                    int b = m / 196, jj = m % 196;
                    *(float2*)&((float*)Cout)[((size_t)b * NTOK + 1 + jj) * EMB_ + n] =
                        make_float2(v0, v1);
                } else {
                    int b = m / NTOK, t = m % NTOK;
                    int which = n >> 8, d2 = n & 255;
                    int hh = d2 >> 7, dd = d2 & 127;
                    int bh = b * 2 + hh;
                    __half* base = (__half*)Cout;
                    if (which < 2) {
                        __half2 hv = __floats2half2_rn(v0, v1);
                        *(__half2*)&base[(size_t)which * QKV_SZ +
                                         ((size_t)bh * 394 + t) * 128 + dd] = hv;
                    } else {
                        __half* vdst = base + 2 * QKV_SZ +
                                       ((size_t)bh * 197 + (t >> 1)) * 256 + dd * 2 + (t & 1);
                        vdst[0] = __float2half_rn(v0);
                        vdst[2] = __float2half_rn(v1);
                    }
                }
            }
        }
    }
}

// ---------------- flash attention fp16: identity P-refragmentation -----------
__global__ __launch_bounds__(256)
void flash_attn(const __half* __restrict__ qkv, __half* __restrict__ Og) {
    extern __shared__ __half smem[];
    __half* Qs = smem;                         // [128][136]
    __half* Ks = Qs + 128 * 136;               // [2][64][136]
    __half* Vs = Ks + 2 * 64 * 136;            // [2][32][272]  (half2 rows of 136)
    int tid = threadIdx.x, lane = tid & 31, wid = tid >> 5;
    int gid = lane >> 2, tg = lane & 3;
    int qt = blockIdx.x, bh = blockIdx.y;
    const __half* Qb = qkv + (size_t)bh * 394 * 128;
    const __half* Kb = qkv + QKV_SZ + (size_t)bh * 394 * 128;
    const __half* Vb = qkv + 2 * QKV_SZ + (size_t)bh * 197 * 256;
    __half* Ob = Og + (size_t)(bh >> 1) * NTOK * EMB_ + (bh & 1) * 128;
    int qbase = qt * 128;
    int r0 = wid * 16 + gid;

    auto loadQ = [&]() {
#pragma unroll
        for (int i = 0; i < 8; i++) {
            int idx = tid + i * 256; int row = idx >> 4; int cc = (idx & 15) << 3;
            int gr = qbase + row; if (gr >= 394) gr = 0;
            cpa16(Qs + row * 136 + cc, Qb + (size_t)gr * 128 + cc, true);
        }
    };
    auto loadK = [&](int st, int kt) {
        __half* dst = Ks + st * 64 * 136;
#pragma unroll
        for (int i = 0; i < 4; i++) {
            int idx = tid + i * 256; int row = idx >> 4; int cc = (idx & 15) << 3;
            int gr = kt * 64 + row; if (gr >= 394) gr = 0;
            cpa16(dst + row * 136 + cc, Kb + (size_t)gr * 128 + cc, true);
        }
    };
    auto loadV = [&](int st, int kt) {
        __half* dst = Vs + st * 32 * 272;
#pragma unroll
        for (int i = 0; i < 4; i++) {
            int idx = tid + i * 256; int row = idx >> 5; int cc = (idx & 31) << 3;
            int gp = kt * 32 + row; if (gp >= 197) gp = 0;
            cpa16(dst + row * 272 + cc, Vb + (size_t)gp * 256 + cc, true);
        }
    };

    loadQ(); loadK(0, 0); loadV(0, 0); cpa_commit();
    loadK(1, 1); loadV(1, 1); cpa_commit();

    float accO[16][4] = {};
    float m0 = -1e30f, m1 = -1e30f, l0 = 0.f, l1 = 0.f;

    for (int kt = 0; kt < FA_NKT; kt++) {
        int st = kt & 1;
        cpa_wait<1>();
        __syncthreads();

        // ---- S = Q K^T : warp rows [wid*16,+16), all 64 kv cols ----
        float accS[8][4] = {};
        {
            const unsigned* Qu = (const unsigned*)Qs;
            const unsigned* Ku = (const unsigned*)(Ks + st * 64 * 136);
#pragma unroll
            for (int j = 0; j < 8; j++) {          // k16 over d=128
                unsigned af[4];
                af[0] = Qu[r0 * 68 + j * 8 + tg];
                af[1] = Qu[(r0 + 8) * 68 + j * 8 + tg];
                af[2] = Qu[r0 * 68 + j * 8 + tg + 4];
                af[3] = Qu[(r0 + 8) * 68 + j * 8 + tg + 4];
#pragma unroll
                for (int nt = 0; nt < 8; nt++) {
                    int kv = nt * 8 + gid;
                    unsigned bf[2];
                    bf[0] = Ku[kv * 68 + j * 8 + tg];
                    bf[1] = Ku[kv * 68 + j * 8 + tg + 4];
                    mma16(accS[nt], af, bf);
                }
            }
        }
        // ---- mask kv >= 394 ----
        int cb = kt * 64 + tg * 2;
#pragma unroll
        for (int nt = 0; nt < 8; nt++) {
            int c0 = cb + nt * 8;
            if (c0 >= 394)     { accS[nt][0] = -1e30f; accS[nt][2] = -1e30f; }
            if (c0 + 1 >= 394) { accS[nt][1] = -1e30f; accS[nt][3] = -1e30f; }
        }
        // ---- online softmax (quad shuffles) ----
        float rm0 = -1e30f, rm1 = -1e30f;
#pragma unroll
        for (int nt = 0; nt < 8; nt++) {
            rm0 = fmaxf(rm0, fmaxf(accS[nt][0], accS[nt][1]));
            rm1 = fmaxf(rm1, fmaxf(accS[nt][2], accS[nt][3]));
        }
        rm0 = fmaxf(rm0, __shfl_xor_sync(0xffffffffu, rm0, 1));
        rm0 = fmaxf(rm0, __shfl_xor_sync(0xffffffffu, rm0, 2));
        rm1 = fmaxf(rm1, __shfl_xor_sync(0xffffffffu, rm1, 1));
        rm1 = fmaxf(rm1, __shfl_xor_sync(0xffffffffu, rm1, 2));
        float mn0 = fmaxf(m0, rm0), mn1 = fmaxf(m1, rm1);
        float sc0 = __expf(m0 - mn0), sc1 = __expf(m1 - mn1);
        float rs0 = 0.f, rs1 = 0.f;
#pragma unroll
        for (int nt = 0; nt < 8; nt++) {
            accS[nt][0] = __expf(accS[nt][0] - mn0);
            accS[nt][1] = __expf(accS[nt][1] - mn0);
            accS[nt][2] = __expf(accS[nt][2] - mn1);
            accS[nt][3] = __expf(accS[nt][3] - mn1);
            rs0 += accS[nt][0] + accS[nt][1];
            rs1 += accS[nt][2] + accS[nt][3];
        }
        rs0 += __shfl_xor_sync(0xffffffffu, rs0, 1);
        rs0 += __shfl_xor_sync(0xffffffffu, rs0, 2);
        rs1 += __shfl_xor_sync(0xffffffffu, rs1, 1);
        rs1 += __shfl_xor_sync(0xffffffffu, rs1, 2);
        l0 = l0 * sc0 + rs0;  l1 = l1 * sc1 + rs1;
        m0 = mn0;  m1 = mn1;
#pragma unroll
        for (int nt = 0; nt < 16; nt++) {
            accO[nt][0] *= sc0; accO[nt][1] *= sc0;
            accO[nt][2] *= sc1; accO[nt][3] *= sc1;
        }
        // ---- O += P V : fp16 C-frag -> A-frag is the identity mapping ----
        {
            const unsigned* Vu = (const unsigned*)(Vs + st * 32 * 272);
#pragma unroll
            for (int j2 = 0; j2 < 4; j2++) {       // k16 over kv=64
                unsigned a[4];
                a[0] = pack2(accS[2 * j2][0],     accS[2 * j2][1]);
                a[1] = pack2(accS[2 * j2][2],     accS[2 * j2][3]);
                a[2] = pack2(accS[2 * j2 + 1][0], accS[2 * j2 + 1][1]);
                a[3] = pack2(accS[2 * j2 + 1][2], accS[2 * j2 + 1][3]);
#pragma unroll
                for (int nt = 0; nt < 16; nt++) {
                    int n = nt * 8 + gid;
                    unsigned bf[2];
                    bf[0] = Vu[(8 * j2 + tg) * 136 + n];
                    bf[1] = Vu[(8 * j2 + tg + 4) * 136 + n];
                    mma16(accO[nt], a, bf);
                }
            }
        }
        __syncthreads();
        if (kt + 2 < FA_NKT) { loadK(st, kt + 2); loadV(st, kt + 2); }
        cpa_commit();
    }

    float inv0 = 1.f / (l0 * 16.f), inv1 = 1.f / (l1 * 16.f);
    int gr0 = qbase + r0, gr1 = gr0 + 8;
#pragma unroll
    for (int nt = 0; nt < 16; nt++) {
        int col = nt * 8 + tg * 2;
        if (gr0 < 394)
            *(__half2*)&Ob[(size_t)gr0 * EMB_ + col] =
                __floats2half2_rn(accO[nt][0] * inv0, accO[nt][1] * inv0);
        if (gr1 < 394)
            *(__half2*)&Ob[(size_t)gr1 * EMB_ + col] =
                __floats2half2_rn(accO[nt][2] * inv1, accO[nt][3] * inv1);
    }
}

// ---------------- ln1: z fp32 -> half -----------------------------------------
__global__ __launch_bounds__(256)
void ln1_kernel(const float* __restrict__ in, const float* __restrict__ g,
                const float* __restrict__ b, __half* __restrict__ out) {
    int r = blockIdx.x, e = threadIdx.x;
    size_t idx = (size_t)r * EMB_ + e;
    float v = in[idx];
    float s = v, s2 = v * v;
#pragma unroll
    for (int off = 16; off > 0; off >>= 1) {
        s  += __shfl_xor_sync(0xffffffff, s,  off);
        s2 += __shfl_xor_sync(0xffffffff, s2, off);
    }
    __shared__ float ss[8], ss2[8];
    if ((e & 31) == 0) { ss[e >> 5] = s; ss2[e >> 5] = s2; }
    __syncthreads();
    float tot = 0.f, tot2 = 0.f;
#pragma unroll
    for (int i = 0; i < 8; i++) { tot += ss[i]; tot2 += ss2[i]; }
    float mean = tot * (1.f / EMB_);
    float var = tot2 * (1.f / EMB_) - mean * mean;
    float nv = (v - mean) * rsqrtf(var + 1e-5f) * g[e] + b[e];
    out[idx] = __float2half_rn(nv);
}

// ---------------- fused ln2 + residual + pool partial -------------------------
__global__ __launch_bounds__(256)
void ln2_pool(const float* __restrict__ h, const float* __restrict__ g,
              const float* __restrict__ bb, float* __restrict__ z,
              float* __restrict__ pool) {
    int b = blockIdx.x, seg = blockIdx.y, e = threadIdx.x;
    int t0 = seg * 50, t1 = t0 + 50; if (t1 > NTOK) t1 = NTOK;
    __shared__ float ss[8], ss2[8];
    float ge = g[e], be = bb[e];
    float accp = 0.f;
    for (int t = t0; t < t1; t++) {
        size_t idx = ((size_t)b * NTOK + t) * EMB_ + e;
        float v = h[idx];
        float s = v, s2 = v * v;
#pragma unroll
        for (int off = 16; off > 0; off >>= 1) {
            s  += __shfl_xor_sync(0xffffffff, s,  off);
            s2 += __shfl_xor_sync(0xffffffff, s2, off);
        }
        if ((e & 31) == 0) { ss[e >> 5] = s; ss2[e >> 5] = s2; }
        __syncthreads();
        float tot = 0.f, tot2 = 0.f;
#pragma unroll
        for (int i = 0; i < 8; i++) { tot += ss[i]; tot2 += ss2[i]; }
        float mean = tot * (1.f / EMB_);
        float var = tot2 * (1.f / EMB_) - mean * mean;
        float nv = (v - mean) * rsqrtf(var + 1e-5f) * ge + be;
        float zv = z[idx] + nv;
        z[idx] = zv;
        accp += zv;
        __syncthreads();
    }
    pool[((size_t)b * 8 + seg) * EMB_ + e] = accp;
}

// ---------------- head ---------------------------------------------------------
__global__ __launch_bounds__(256)
void head_kernel(const float* __restrict__ pool, const float* __restrict__ g,
                 const float* __restrict__ bb, const float* __restrict__ Wc,
                 const float* __restrict__ bc, float* __restrict__ out) {
    int b = blockIdx.x, e = threadIdx.x;
    float s = 0.f;
#pragma unroll
    for (int i = 0; i < 8; i++) s += pool[((size_t)b * 8 + i) * EMB_ + e];
    float pooled = s * (1.f / NTOK);
    __shared__ float red[256];
    red[e] = pooled; __syncthreads();
    for (int st = 128; st > 0; st >>= 1) { if (e < st) red[e] += red[e + st]; __syncthreads(); }
    float mean = red[0] * (1.f / EMB_);
    __syncthreads();
    float d = pooled - mean;
    red[e] = d * d; __syncthreads();
    for (int st = 128; st > 0; st >>= 1) { if (e < st) red[e] += red[e + st]; __syncthreads(); }
    float var = red[0] * (1.f / EMB_);
    __syncthreads();
    float nv = d * rsqrtf(var + 1e-5f) * g[e] + bb[e];
    red[e] = nv * Wc[e * 2 + 0]; __syncthreads();
    for (int st = 128; st > 0; st >>= 1) { if (e < st) red[e] += red[e + st]; __syncthreads(); }
    float l0 = red[0] + bc[0];
    __syncthreads();
    red[e] = nv * Wc[e * 2 + 1]; __syncthreads();
    for (int st = 128; st > 0; st >>= 1) { if (e < st) red[e] += red[e + st]; __syncthreads(); }
    float l1 = red[0] + bc[1];
    if (e == 0) {
        float mx = fmaxf(l0, l1);
        float lse = mx + logf(expf(l0 - mx) + expf(l1 - mx));
        out[b * 2 + 0] = l0 - lse;
        out[b * 2 + 1] = l1 - lse;
    }
}

// ---------------- launch --------------------------------------------------------
extern "C" void kernel_launch(void* const* d_in, const int* in_sizes, int n_in,
                              void* d_out, int out_size) {
    const float* x     = (const float*)d_in[0];
    const float* W1    = (const float*)d_in[1];
    const float* b1    = (const float*)d_in[2];
    const float* cls1  = (const float*)d_in[3];
    const float* W2    = (const float*)d_in[4];
    const float* b2    = (const float*)d_in[5];
    const float* cls2  = (const float*)d_in[6];
    const float* ln1_g = (const float*)d_in[7];
    const float* ln1_b = (const float*)d_in[8];
    const float* Wq    = (const float*)d_in[9];
    const float* bq    = (const float*)d_in[10];
    const float* Wk    = (const float*)d_in[11];
    const float* bk    = (const float*)d_in[12];
    const float* Wv    = (const float*)d_in[13];
    const float* bv    = (const float*)d_in[14];
    const float* Wp    = (const float*)d_in[15];
    const float* bp    = (const float*)d_in[16];
    const float* ln2_g = (const float*)d_in[17];
    const float* ln2_b = (const float*)d_in[18];
    const float* lnc_g = (const float*)d_in[19];
    const float* lnc_b = (const float*)d_in[20];
    const float* Wc    = (const float*)d_in[21];
    const float* bc    = (const float*)d_in[22];
    float* out = (float*)d_out;

    static int inited = 0;
    if (!inited) {
        cudaFuncSetAttribute(gemm_nn,  cudaFuncAttributeMaxDynamicSharedMemorySize, SMEM_NN);
        cudaFuncSetAttribute(gemm_pe1, cudaFuncAttributeMaxDynamicSharedMemorySize, SMEM_NN);
        cudaFuncSetAttribute(flash_attn, cudaFuncAttributeMaxDynamicSharedMemorySize, FA_SMEM);
        inited = 1;
    }

    __half *x16, *T2, *Wt, *h16, *qkv, *o16;
    float *bqkv, *z, *hf, *pool;
    cudaGetSymbolAddress((void**)&x16, g_x16);
    cudaGetSymbolAddress((void**)&T2,  g_T2);
    cudaGetSymbolAddress((void**)&Wt,  g_Wt);
    cudaGetSymbolAddress((void**)&bqkv, g_bqkv);
    cudaGetSymbolAddress((void**)&z,   g_z);
    cudaGetSymbolAddress((void**)&h16, g_h16);
    cudaGetSymbolAddress((void**)&hf,  g_hf);
    cudaGetSymbolAddress((void**)&qkv, g_qkv);
    cudaGetSymbolAddress((void**)&o16, g_o16);
    cudaGetSymbolAddress((void**)&pool, g_pool);

    prep_w<<<(PREP_N + 255) / 256, 256>>>(W1, W2, Wq, Wk, Wv, Wp, bq, bk, bv, Wt, bqkv);
    x2h<<<XN / 1024, 256>>>(x, x16);
    im2col2<<<dim3(196, B_), 192>>>(x, T2);
    cls_fill<<<B_, 256>>>(cls1, cls2, z);

    gemm_pe1<<<dim3(2, 196), 256, SMEM_NN>>>(x16, Wt + OFF_W1P, b1, z);
    gemm_nn<<<dim3(2, 196), 256, SMEM_NN>>>(T2, Wt + OFF_W2, b2, z, 256, 192, 2);

    ln1_kernel<<<MTOK, 256>>>(z, ln1_g, ln1_b, h16);

    gemm_nn<<<dim3(6, 394), 256, SMEM_NN>>>(h16, Wt + OFF_WQKV, bqkv, qkv, 768, 256, 5);

    flash_attn<<<dim3(4, 256), 256, FA_SMEM>>>(qkv, o16);

    gemm_nn<<<dim3(2, 394), 256, SMEM_NN>>>(o16, Wt + OFF_WP, bp, hf, 256, 256, 0);

    ln2_pool<<<dim3(B_, 8), 256>>>(hf, ln2_g, ln2_b, z, pool);
    head_kernel<<<B_, 256>>>(pool, lnc_g, lnc_b, Wc, bc, out);
}

// round 14
// speedup vs baseline: 1.9740x; 1.1845x over previous
#include <cuda_runtime.h>
#include <cuda_fp16.h>
#include <math.h>

#define B_      128
#define EMB_    256
#define NTOK    394
#define MTOK    (B_ * 394)           // 50432
#define MPE     (B_ * 196)           // 25088
#define XN      (B_ * 3 * 224 * 224) // 19267584

#define KC      32
#define ASTRH   40                   // A smem row stride (halfs)
#define BSTRH2  136                  // B smem row stride (half2)
#define A_STG   (128 * ASTRH)        // 5120 halfs / stage
#define B_STG   (BSTRH2 * 16 * 2)    // 4352 halfs / stage
#define SMEM_NN ((3 * (A_STG + B_STG)) * 2)   // 56832 B
#define FA_SMEM (128*136*2 + 2*64*136*2 + 2*32*136*4)  // 104448
#define FA_NKT  7
#define QKV_SZ  ((size_t)B_ * 2 * 394 * 128)  // halfs per q/k/v region

// ---------------- scratch ---------------------------------------------------
__device__ __half g_x16[XN];
__device__ __half g_T2[MPE * 192];
__device__ __half g_Wt[507904];      // W2 | Wp | W1perm | Wqkv, k-pair interleaved
__device__ float  g_bqkv[768];
__device__ float  g_z [MTOK * EMB_];
__device__ __half g_h16[MTOK * EMB_];
__device__ float  g_hf[MTOK * EMB_];
__device__ __half g_qkv[3 * QKV_SZ];
__device__ __half g_o16[MTOK * EMB_];
__device__ float  g_pool[B_ * 8 * EMB_];

#define OFF_W2   0
#define OFF_WP   49152
#define OFF_W1P  114688
#define OFF_WQKV 311296
#define PREP_N   508672

// ---------------- helpers ----------------------------------------------------
__device__ __forceinline__ void mma16(float* acc, const unsigned* a, const unsigned* b) {
    asm volatile(
        "mma.sync.aligned.m16n8k16.row.col.f32.f16.f16.f32 "
        "{%0,%1,%2,%3}, {%4,%5,%6,%7}, {%8,%9}, {%0,%1,%2,%3};\n"
        : "+f"(acc[0]), "+f"(acc[1]), "+f"(acc[2]), "+f"(acc[3])
        : "r"(a[0]), "r"(a[1]), "r"(a[2]), "r"(a[3]), "r"(b[0]), "r"(b[1]));
}
__device__ __forceinline__ unsigned pack2(float a, float b) {
    __half2 h = __floats2half2_rn(a, b);
    return *reinterpret_cast<unsigned*>(&h);
}
__device__ __forceinline__ void cpa16(void* dst, const void* src, bool pred) {
    unsigned d = (unsigned)__cvta_generic_to_shared(dst);
    int sz = pred ? 16 : 0;
    asm volatile("cp.async.cg.shared.global [%0], [%1], 16, %2;\n"
                 :: "r"(d), "l"(src), "r"(sz));
}
__device__ __forceinline__ void cpa_commit() { asm volatile("cp.async.commit_group;\n"); }
template <int N>
__device__ __forceinline__ void cpa_wait() { asm volatile("cp.async.wait_group %0;\n" :: "n"(N)); }

// ---------------- weight prep: half + k-pair interleave ----------------------
__global__ void prep_w(const float* __restrict__ W1, const float* __restrict__ W2,
                       const float* __restrict__ Wq, const float* __restrict__ Wk,
                       const float* __restrict__ Wv, const float* __restrict__ Wp,
                       const float* __restrict__ bq, const float* __restrict__ bk,
                       const float* __restrict__ bv,
                       __half* __restrict__ out, float* __restrict__ bqkv) {
    int i = blockIdx.x * 256 + threadIdx.x;
    if (i >= PREP_N) return;
    if (i >= 507904) {                      // qkv bias
        int j = i - 507904;
        int which = j >> 8, col = j & 255;
        const float* src = which == 0 ? bq : which == 1 ? bk : bv;
        bqkv[j] = src[col];
        return;
    }
    float v;
    if (i < OFF_WP) {                       // W2 [192][256] -> [96][256][2]
        int kp = i >> 9, r = i & 511, n = r >> 1, p = r & 1;
        v = W2[(2 * kp + p) * 256 + n];
    } else if (i < OFF_W1P) {               // Wp [256][256] -> [128][256][2]
        int idx = i - OFF_WP;
        int kp = idx >> 9, r = idx & 511, n = r >> 1, p = r & 1;
        v = Wp[(2 * kp + p) * 256 + n];
    } else if (i < OFF_WQKV) {              // W1 permuted k'=c*256+pi*16+pj, interleaved
        int idx = i - OFF_W1P;
        int kp = idx >> 9, r = idx & 511, n = r >> 1, p = r & 1;
        int kpr = 2 * kp + p;
        int c = kpr >> 8, rem = kpr & 255;
        int pi = rem >> 4, pj = rem & 15;
        v = W1[((pi * 16 + pj) * 3 + c) * 256 + n];
    } else {                                // Wqkv [256][768] -> [128][768][2]
        int idx = i - OFF_WQKV;
        int kp = idx / 1536, r = idx % 1536, n = r >> 1, p = r & 1;
        int k = 2 * kp + p;
        int which = n >> 8, col = n & 255;
        const float* src = which == 0 ? Wq : which == 1 ? Wk : Wv;
        v = src[k * 256 + col];
    }
    out[i] = __float2half_rn(v);
}

// ---------------- x -> half ---------------------------------------------------
__global__ void x2h(const float* __restrict__ x, __half* __restrict__ xh) {
    int i = (blockIdx.x * 256 + threadIdx.x) * 4;
    float4 v = *(const float4*)(x + i);
    __half2 h0 = __floats2half2_rn(v.x, v.y);
    __half2 h1 = __floats2half2_rn(v.z, v.w);
    *(__half2*)(xh + i) = h0;
    *(__half2*)(xh + i + 2) = h1;
}

// ---------------- im2col (p=8 sampled patches) -------------------------------
__global__ void im2col2(const float* __restrict__ x, __half* __restrict__ T) {
    __shared__ float buf[192];
    int i = blockIdx.x, b = blockIdx.y;
    int jdx = 4 * i + 3;
    int ph = jdx / 28, pw = jdx % 28;
    const float* xb = x + (size_t)b * 3 * 224 * 224 + (size_t)(ph * 8) * 224 + pw * 8;
    int t = threadIdx.x;
    int c = t >> 6, pos = t & 63;
    int pi = pos >> 3, pj = pos & 7;
    buf[pos * 3 + c] = xb[((size_t)c * 224 + pi) * 224 + pj];
    __syncthreads();
    T[((size_t)b * 196 + i) * 192 + t] = __float2half_rn(buf[t]);
}
__global__ void cls_fill(const float* __restrict__ cls1,
                         const float* __restrict__ cls2,
                         float* __restrict__ z) {
    int b = blockIdx.x, e = threadIdx.x;
    z[((size_t)b * NTOK + 0)   * EMB_ + e] = cls2[e];
    z[((size_t)b * NTOK + 197) * EMB_ + e] = cls1[e];
}

// ---------------- patch1 GEMM: implicit im2col from x16, fp16 mma ------------
__global__ __launch_bounds__(256, 2)
void gemm_pe1(const __half* __restrict__ x, const __half* __restrict__ Bm,
              const float* __restrict__ bias, float* __restrict__ C) {
    extern __shared__ __half smem[];
    __half* As = smem;                         // [3][A_STG]
    __half* Bs = smem + 3 * A_STG;             // [3][B_STG]
    int tid = threadIdx.x;
    int bm = blockIdx.y * 128, bn = blockIdx.x * 128;
    int wid = tid >> 5, lane = tid & 31;
    int wm = wid & 3, wn = wid >> 2;
    int gid = lane >> 2, tg = lane & 3;

    size_t rowb[2];
#pragma unroll
    for (int i = 0; i < 2; i++) {
        int m = bm + (tid >> 2) + i * 64;
        int b = m / 196, j = m % 196;
        int ph = j / 14, pw = j % 14;
        rowb[i] = (size_t)b * 150528 + (size_t)(ph * 16) * 224 + pw * 16;
    }
    int ch = tid & 3;
    int pj0 = (ch & 1) * 8, gsel = ch >> 1;

    auto loadA = [&](int s, int k0) {
        __half* dst = As + s * A_STG;
        int gidx = (k0 >> 4) + gsel;
        int c = gidx >> 4, pi = gidx & 15;
        size_t off = (size_t)c * 50176 + pi * 224 + pj0;
#pragma unroll
        for (int i = 0; i < 2; i++) {
            int row = (tid >> 2) + i * 64;
            cpa16(dst + row * ASTRH + ch * 8, x + rowb[i] + off, true);
        }
    };
    auto loadB = [&](int s, int k0) {
        const __half2* B2 = (const __half2*)Bm;
        __half2* dst = (__half2*)(Bs + s * B_STG);
        int kp0 = k0 >> 1;
#pragma unroll
        for (int i = 0; i < 2; i++) {
            int idx = tid + i * 256;
            int row = idx >> 5, cc = (idx & 31) << 2;
            cpa16(dst + row * BSTRH2 + cc, B2 + (size_t)(kp0 + row) * 256 + bn + cc, true);
        }
    };

    float acc[2][8][4] = {};
    const int nk = 768 / KC;                   // 24
    loadA(0, 0); loadB(0, 0); cpa_commit();
    loadA(1, KC); loadB(1, KC); cpa_commit();

    int arow = wm * 32 + gid;
    for (int it = 0; it < nk; it++) {
        cpa_wait<1>(); __syncthreads();
        if (it + 2 < nk) { loadA((it + 2) % 3, (it + 2) * KC); loadB((it + 2) % 3, (it + 2) * KC); }
        cpa_commit();
        const unsigned* Au = (const unsigned*)(As + (it % 3) * A_STG);
        const unsigned* Bu = (const unsigned*)(Bs + (it % 3) * B_STG);
#pragma unroll
        for (int kk2 = 0; kk2 < 2; kk2++) {
            unsigned af[2][4], bf[8][2];
#pragma unroll
            for (int mt = 0; mt < 2; mt++) {
                int r = arow + mt * 16;
                af[mt][0] = Au[r * 20 + kk2 * 8 + tg];
                af[mt][1] = Au[(r + 8) * 20 + kk2 * 8 + tg];
                af[mt][2] = Au[r * 20 + kk2 * 8 + tg + 4];
                af[mt][3] = Au[(r + 8) * 20 + kk2 * 8 + tg + 4];
            }
#pragma unroll
            for (int nt = 0; nt < 8; nt++) {
                int n = wn * 64 + nt * 8 + gid;
                bf[nt][0] = Bu[(kk2 * 8 + tg) * BSTRH2 + n];
                bf[nt][1] = Bu[(kk2 * 8 + tg + 4) * BSTRH2 + n];
            }
#pragma unroll
            for (int mt = 0; mt < 2; mt++)
#pragma unroll
                for (int nt = 0; nt < 8; nt++)
                    mma16(acc[mt][nt], af[mt], bf[nt]);
        }
        __syncthreads();
    }

#pragma unroll
    for (int mt = 0; mt < 2; mt++)
#pragma unroll
        for (int nt = 0; nt < 8; nt++) {
            int n = bn + wn * 64 + nt * 8 + tg * 2;
            float bv0 = bias[n], bv1 = bias[n + 1];
#pragma unroll
            for (int half_ = 0; half_ < 2; half_++) {
                int m = bm + wm * 32 + mt * 16 + gid + half_ * 8;
                int b = m / 196, jj = m % 196;
                *(float2*)&C[((size_t)b * NTOK + 198 + jj) * EMB_ + n] =
                    make_float2(acc[mt][nt][half_ * 2] + bv0,
                                acc[mt][nt][half_ * 2 + 1] + bv1);
            }
        }
}

// ---------------- NN GEMM fp16: modes 0 (proj->f32), 2 (pe2->z), 5 (qkv) -----
__global__ __launch_bounds__(256, 2)
void gemm_nn(const __half* __restrict__ A, const __half* __restrict__ Bm,
             const float* __restrict__ bias, void* __restrict__ Cout,
             int N, int K, int mode) {
    extern __shared__ __half smem[];
    __half* As = smem;
    __half* Bs = smem + 3 * A_STG;
    int tid = threadIdx.x;
    int bm = blockIdx.y * 128, bn = blockIdx.x * 128;
    int wid = tid >> 5, lane = tid & 31;
    int wm = wid & 3, wn = wid >> 2;
    int gid = lane >> 2, tg = lane & 3;

    auto loadA = [&](int s, int k0) {
        __half* dst = As + s * A_STG;
#pragma unroll
        for (int i = 0; i < 2; i++) {
            int idx = tid + i * 256;
            int row = idx >> 2, cc = (idx & 3) << 3;
            cpa16(dst + row * ASTRH + cc, A + (size_t)(bm + row) * K + k0 + cc, true);
        }
    };
    auto loadB = [&](int s, int k0) {
        const __half2* B2 = (const __half2*)Bm;
        __half2* dst = (__half2*)(Bs + s * B_STG);
        int kp0 = k0 >> 1;
#pragma unroll
        for (int i = 0; i < 2; i++) {
            int idx = tid + i * 256;
            int row = idx >> 5, cc = (idx & 31) << 2;
            cpa16(dst + row * BSTRH2 + cc, B2 + (size_t)(kp0 + row) * N + bn + cc, true);
        }
    };

    float acc[2][8][4] = {};
    int nk = K / KC;
    loadA(0, 0); loadB(0, 0); cpa_commit();
    loadA(1, KC); loadB(1, KC); cpa_commit();

    int arow = wm * 32 + gid;
    for (int it = 0; it < nk; it++) {
        cpa_wait<1>(); __syncthreads();
        if (it + 2 < nk) { loadA((it + 2) % 3, (it + 2) * KC); loadB((it + 2) % 3, (it + 2) * KC); }
        cpa_commit();
        const unsigned* Au = (const unsigned*)(As + (it % 3) * A_STG);
        const unsigned* Bu = (const unsigned*)(Bs + (it % 3) * B_STG);
#pragma unroll
        for (int kk2 = 0; kk2 < 2; kk2++) {
            unsigned af[2][4], bf[8][2];
#pragma unroll
            for (int mt = 0; mt < 2; mt++) {
                int r = arow + mt * 16;
                af[mt][0] = Au[r * 20 + kk2 * 8 + tg];
                af[mt][1] = Au[(r + 8) * 20 + kk2 * 8 + tg];
                af[mt][2] = Au[r * 20 + kk2 * 8 + tg + 4];
                af[mt][3] = Au[(r + 8) * 20 + kk2 * 8 + tg + 4];
            }
#pragma unroll
            for (int nt = 0; nt < 8; nt++) {
                int n = wn * 64 + nt * 8 + gid;
                bf[nt][0] = Bu[(kk2 * 8 + tg) * BSTRH2 + n];
                bf[nt][1] = Bu[(kk2 * 8 + tg + 4) * BSTRH2 + n];
            }
#pragma unroll
            for (int mt = 0; mt < 2; mt++)
#pragma unroll
                for (int nt = 0; nt < 8; nt++)
                    mma16(acc[mt][nt], af[mt], bf[nt]);
        }
        __syncthreads();
    }

#pragma unroll
    for (int mt = 0; mt < 2; mt++) {
#pragma unroll
        for (int nt = 0; nt < 8; nt++) {
            int n = bn + wn * 64 + nt * 8 + tg * 2;
            float bv0 = bias ? bias[n] : 0.f;
            float bv1 = bias ? bias[n + 1] : 0.f;
#pragma unroll
            for (int half_ = 0; half_ < 2; half_++) {
                int m = bm + wm * 32 + mt * 16 + gid + half_ * 8;
                float v0 = acc[mt][nt][half_ * 2 + 0] + bv0;
                float v1 = acc[mt][nt][half_ * 2 + 1] + bv1;
                if (mode == 0) {
                    *(float2*)&((float*)Cout)[(size_t)m * 256 + n] = make_float2(v0, v1);
                } else if (mode == 2) {
                    int b = m / 196, jj = m % 196;
                    *(float2*)&((float*)Cout)[((size_t)b * NTOK + 1 + jj) * EMB_ + n] =
                        make_float2(v0, v1);
                } else {
                    int b = m / NTOK, t = m % NTOK;
                    int which = n >> 8, d2 = n & 255;
                    int hh = d2 >> 7, dd = d2 & 127;
                    int bh = b * 2 + hh;
                    __half* base = (__half*)Cout;
                    if (which < 2) {
                        __half2 hv = __floats2half2_rn(v0, v1);
                        *(__half2*)&base[(size_t)which * QKV_SZ +
                                         ((size_t)bh * 394 + t) * 128 + dd] = hv;
                    } else {
                        __half* vdst = base + 2 * QKV_SZ +
                                       ((size_t)bh * 197 + (t >> 1)) * 256 + dd * 2 + (t & 1);
                        vdst[0] = __float2half_rn(v0);
                        vdst[2] = __float2half_rn(v1);
                    }
                }
            }
        }
    }
}

// ---------------- flash attention fp16: identity P-refragmentation -----------
__global__ __launch_bounds__(256)
void flash_attn(const __half* __restrict__ qkv, __half* __restrict__ Og) {
    extern __shared__ __half smem[];
    __half* Qs = smem;                         // [128][136]
    __half* Ks = Qs + 128 * 136;               // [2][64][136]
    __half* Vs = Ks + 2 * 64 * 136;            // [2][32][272]
    int tid = threadIdx.x, lane = tid & 31, wid = tid >> 5;
    int gid = lane >> 2, tg = lane & 3;
    int qt = blockIdx.x, bh = blockIdx.y;
    const __half* Qb = qkv + (size_t)bh * 394 * 128;
    const __half* Kb = qkv + QKV_SZ + (size_t)bh * 394 * 128;
    const __half* Vb = qkv + 2 * QKV_SZ + (size_t)bh * 197 * 256;
    __half* Ob = Og + (size_t)(bh >> 1) * NTOK * EMB_ + (bh & 1) * 128;
    int qbase = qt * 128;
    int r0 = wid * 16 + gid;

    auto loadQ = [&]() {
#pragma unroll
        for (int i = 0; i < 8; i++) {
            int idx = tid + i * 256; int row = idx >> 4; int cc = (idx & 15) << 3;
            int gr = qbase + row; if (gr >= 394) gr = 0;
            cpa16(Qs + row * 136 + cc, Qb + (size_t)gr * 128 + cc, true);
        }
    };
    auto loadK = [&](int st, int kt) {
        __half* dst = Ks + st * 64 * 136;
#pragma unroll
        for (int i = 0; i < 4; i++) {
            int idx = tid + i * 256; int row = idx >> 4; int cc = (idx & 15) << 3;
            int gr = kt * 64 + row; if (gr >= 394) gr = 0;
            cpa16(dst + row * 136 + cc, Kb + (size_t)gr * 128 + cc, true);
        }
    };
    auto loadV = [&](int st, int kt) {
        __half* dst = Vs + st * 32 * 272;
#pragma unroll
        for (int i = 0; i < 4; i++) {
            int idx = tid + i * 256; int row = idx >> 5; int cc = (idx & 31) << 3;
            int gp = kt * 32 + row; if (gp >= 197) gp = 0;
            cpa16(dst + row * 272 + cc, Vb + (size_t)gp * 256 + cc, true);
        }
    };

    loadQ(); loadK(0, 0); loadV(0, 0); cpa_commit();
    loadK(1, 1); loadV(1, 1); cpa_commit();

    float accO[16][4] = {};
    float m0 = -1e30f, m1 = -1e30f, l0 = 0.f, l1 = 0.f;

    for (int kt = 0; kt < FA_NKT; kt++) {
        int st = kt & 1;
        cpa_wait<1>();
        __syncthreads();

        float accS[8][4] = {};
        {
            const unsigned* Qu = (const unsigned*)Qs;
            const unsigned* Ku = (const unsigned*)(Ks + st * 64 * 136);
#pragma unroll
            for (int j = 0; j < 8; j++) {
                unsigned af[4];
                af[0] = Qu[r0 * 68 + j * 8 + tg];
                af[1] = Qu[(r0 + 8) * 68 + j * 8 + tg];
                af[2] = Qu[r0 * 68 + j * 8 + tg + 4];
                af[3] = Qu[(r0 + 8) * 68 + j * 8 + tg + 4];
#pragma unroll
                for (int nt = 0; nt < 8; nt++) {
                    int kv = nt * 8 + gid;
                    unsigned bf[2];
                    bf[0] = Ku[kv * 68 + j * 8 + tg];
                    bf[1] = Ku[kv * 68 + j * 8 + tg + 4];
                    mma16(accS[nt], af, bf);
                }
            }
        }
        int cb = kt * 64 + tg * 2;
#pragma unroll
        for (int nt = 0; nt < 8; nt++) {
            int c0 = cb + nt * 8;
            if (c0 >= 394)     { accS[nt][0] = -1e30f; accS[nt][2] = -1e30f; }
            if (c0 + 1 >= 394) { accS[nt][1] = -1e30f; accS[nt][3] = -1e30f; }
        }
        float rm0 = -1e30f, rm1 = -1e30f;
#pragma unroll
        for (int nt = 0; nt < 8; nt++) {
            rm0 = fmaxf(rm0, fmaxf(accS[nt][0], accS[nt][1]));
            rm1 = fmaxf(rm1, fmaxf(accS[nt][2], accS[nt][3]));
        }
        rm0 = fmaxf(rm0, __shfl_xor_sync(0xffffffffu, rm0, 1));
        rm0 = fmaxf(rm0, __shfl_xor_sync(0xffffffffu, rm0, 2));
        rm1 = fmaxf(rm1, __shfl_xor_sync(0xffffffffu, rm1, 1));
        rm1 = fmaxf(rm1, __shfl_xor_sync(0xffffffffu, rm1, 2));
        float mn0 = fmaxf(m0, rm0), mn1 = fmaxf(m1, rm1);
        float sc0 = __expf(m0 - mn0), sc1 = __expf(m1 - mn1);
        float rs0 = 0.f, rs1 = 0.f;
#pragma unroll
        for (int nt = 0; nt < 8; nt++) {
            accS[nt][0] = __expf(accS[nt][0] - mn0);
            accS[nt][1] = __expf(accS[nt][1] - mn0);
            accS[nt][2] = __expf(accS[nt][2] - mn1);
            accS[nt][3] = __expf(accS[nt][3] - mn1);
            rs0 += accS[nt][0] + accS[nt][1];
            rs1 += accS[nt][2] + accS[nt][3];
        }
        rs0 += __shfl_xor_sync(0xffffffffu, rs0, 1);
        rs0 += __shfl_xor_sync(0xffffffffu, rs0, 2);
        rs1 += __shfl_xor_sync(0xffffffffu, rs1, 1);
        rs1 += __shfl_xor_sync(0xffffffffu, rs1, 2);
        l0 = l0 * sc0 + rs0;  l1 = l1 * sc1 + rs1;
        m0 = mn0;  m1 = mn1;
#pragma unroll
        for (int nt = 0; nt < 16; nt++) {
            accO[nt][0] *= sc0; accO[nt][1] *= sc0;
            accO[nt][2] *= sc1; accO[nt][3] *= sc1;
        }
        {
            const unsigned* Vu = (const unsigned*)(Vs + st * 32 * 272);
#pragma unroll
            for (int j2 = 0; j2 < 4; j2++) {
                unsigned a[4];
                a[0] = pack2(accS[2 * j2][0],     accS[2 * j2][1]);
                a[1] = pack2(accS[2 * j2][2],     accS[2 * j2][3]);
                a[2] = pack2(accS[2 * j2 + 1][0], accS[2 * j2 + 1][1]);
                a[3] = pack2(accS[2 * j2 + 1][2], accS[2 * j2 + 1][3]);
#pragma unroll
                for (int nt = 0; nt < 16; nt++) {
                    int n = nt * 8 + gid;
                    unsigned bf[2];
                    bf[0] = Vu[(8 * j2 + tg) * 136 + n];
                    bf[1] = Vu[(8 * j2 + tg + 4) * 136 + n];
                    mma16(accO[nt], a, bf);
                }
            }
        }
        __syncthreads();
        if (kt + 2 < FA_NKT) { loadK(st, kt + 2); loadV(st, kt + 2); }
        cpa_commit();
    }

    float inv0 = 1.f / (l0 * 16.f), inv1 = 1.f / (l1 * 16.f);
    int gr0 = qbase + r0, gr1 = gr0 + 8;
#pragma unroll
    for (int nt = 0; nt < 16; nt++) {
        int col = nt * 8 + tg * 2;
        if (gr0 < 394)
            *(__half2*)&Ob[(size_t)gr0 * EMB_ + col] =
                __floats2half2_rn(accO[nt][0] * inv0, accO[nt][1] * inv0);
        if (gr1 < 394)
            *(__half2*)&Ob[(size_t)gr1 * EMB_ + col] =
                __floats2half2_rn(accO[nt][2] * inv1, accO[nt][3] * inv1);
    }
}

// ---------------- ln1: warp-per-token, z fp32 -> half, no block sync ---------
__global__ __launch_bounds__(256)
void ln1_kernel(const float* __restrict__ in, const float* __restrict__ g,
                const float* __restrict__ b, __half* __restrict__ out) {
    int warp = threadIdx.x >> 5, lane = threadIdx.x & 31;
    int r = blockIdx.x * 8 + warp;           // MTOK = 6304 * 8
    const float* row = in + (size_t)r * EMB_ + lane * 8;
    float4 v0 = *(const float4*)row;
    float4 v1 = *(const float4*)(row + 4);
    float v[8] = {v0.x, v0.y, v0.z, v0.w, v1.x, v1.y, v1.z, v1.w};
    float s = 0.f, s2 = 0.f;
#pragma unroll
    for (int i = 0; i < 8; i++) { s += v[i]; s2 += v[i] * v[i]; }
#pragma unroll
    for (int off = 16; off > 0; off >>= 1) {
        s  += __shfl_xor_sync(0xffffffffu, s,  off);
        s2 += __shfl_xor_sync(0xffffffffu, s2, off);
    }
    float mean = s * (1.f / EMB_);
    float rstd = rsqrtf(s2 * (1.f / EMB_) - mean * mean + 1e-5f);
    float4 g0 = *(const float4*)(g + lane * 8);
    float4 g1 = *(const float4*)(g + lane * 8 + 4);
    float4 b0 = *(const float4*)(b + lane * 8);
    float4 b1 = *(const float4*)(b + lane * 8 + 4);
    float gg[8] = {g0.x, g0.y, g0.z, g0.w, g1.x, g1.y, g1.z, g1.w};
    float bb[8] = {b0.x, b0.y, b0.z, b0.w, b1.x, b1.y, b1.z, b1.w};
    __half2 h[4];
#pragma unroll
    for (int i = 0; i < 4; i++) {
        float n0 = (v[2 * i]     - mean) * rstd * gg[2 * i]     + bb[2 * i];
        float n1 = (v[2 * i + 1] - mean) * rstd * gg[2 * i + 1] + bb[2 * i + 1];
        h[i] = __floats2half2_rn(n0, n1);
    }
    *(uint4*)(out + (size_t)r * EMB_ + lane * 8) = *(uint4*)h;
}

// ---- ln2 + residual + pool partial: warp-per-token, z NOT written back ------
__global__ __launch_bounds__(256)
void ln2_pool(const float* __restrict__ h, const float* __restrict__ g,
              const float* __restrict__ bb, const float* __restrict__ z,
              float* __restrict__ pool) {
    int b = blockIdx.x, seg = blockIdx.y;
    int warp = threadIdx.x >> 5, lane = threadIdx.x & 31;
    int t0 = seg * 50, t1 = t0 + 50; if (t1 > NTOK) t1 = NTOK;
    float4 g0 = *(const float4*)(g + lane * 8);
    float4 g1 = *(const float4*)(g + lane * 8 + 4);
    float4 bv0 = *(const float4*)(bb + lane * 8);
    float4 bv1 = *(const float4*)(bb + lane * 8 + 4);
    float gg[8] = {g0.x, g0.y, g0.z, g0.w, g1.x, g1.y, g1.z, g1.w};
    float be[8] = {bv0.x, bv0.y, bv0.z, bv0.w, bv1.x, bv1.y, bv1.z, bv1.w};
    float accp[8] = {};
    for (int t = t0 + warp; t < t1; t += 8) {
        size_t base = ((size_t)b * NTOK + t) * EMB_ + lane * 8;
        float4 v0 = *(const float4*)(h + base);
        float4 v1 = *(const float4*)(h + base + 4);
        float v[8] = {v0.x, v0.y, v0.z, v0.w, v1.x, v1.y, v1.z, v1.w};
        float s = 0.f, s2 = 0.f;
#pragma unroll
        for (int i = 0; i < 8; i++) { s += v[i]; s2 += v[i] * v[i]; }
#pragma unroll
        for (int off = 16; off > 0; off >>= 1) {
            s  += __shfl_xor_sync(0xffffffffu, s,  off);
            s2 += __shfl_xor_sync(0xffffffffu, s2, off);
        }
        float mean = s * (1.f / EMB_);
        float rstd = rsqrtf(s2 * (1.f / EMB_) - mean * mean + 1e-5f);
        float4 z0 = *(const float4*)(z + base);
        float4 z1 = *(const float4*)(z + base + 4);
        float zv[8] = {z0.x, z0.y, z0.z, z0.w, z1.x, z1.y, z1.z, z1.w};
#pragma unroll
        for (int i = 0; i < 8; i++)
            accp[i] += zv[i] + (v[i] - mean) * rstd * gg[i] + be[i];
    }
    __shared__ float sm[8][256];
#pragma unroll
    for (int i = 0; i < 8; i++) sm[warp][lane * 8 + i] = accp[i];
    __syncthreads();
    int e = threadIdx.x;
    float tot = 0.f;
#pragma unroll
    for (int w = 0; w < 8; w++) tot += sm[w][e];
    pool[((size_t)b * 8 + seg) * EMB_ + e] = tot;
}

// ---------------- head ---------------------------------------------------------
__global__ __launch_bounds__(256)
void head_kernel(const float* __restrict__ pool, const float* __restrict__ g,
                 const float* __restrict__ bb, const float* __restrict__ Wc,
                 const float* __restrict__ bc, float* __restrict__ out) {
    int b = blockIdx.x, e = threadIdx.x;
    float s = 0.f;
#pragma unroll
    for (int i = 0; i < 8; i++) s += pool[((size_t)b * 8 + i) * EMB_ + e];
    float pooled = s * (1.f / NTOK);
    __shared__ float red[256];
    red[e] = pooled; __syncthreads();
    for (int st = 128; st > 0; st >>= 1) { if (e < st) red[e] += red[e + st]; __syncthreads(); }
    float mean = red[0] * (1.f / EMB_);
    __syncthreads();
    float d = pooled - mean;
    red[e] = d * d; __syncthreads();
    for (int st = 128; st > 0; st >>= 1) { if (e < st) red[e] += red[e + st]; __syncthreads(); }
    float var = red[0] * (1.f / EMB_);
    __syncthreads();
    float nv = d * rsqrtf(var + 1e-5f) * g[e] + bb[e];
    red[e] = nv * Wc[e * 2 + 0]; __syncthreads();
    for (int st = 128; st > 0; st >>= 1) { if (e < st) red[e] += red[e + st]; __syncthreads(); }
    float l0 = red[0] + bc[0];
    __syncthreads();
    red[e] = nv * Wc[e * 2 + 1]; __syncthreads();
    for (int st = 128; st > 0; st >>= 1) { if (e < st) red[e] += red[e + st]; __syncthreads(); }
    float l1 = red[0] + bc[1];
    if (e == 0) {
        float mx = fmaxf(l0, l1);
        float lse = mx + logf(expf(l0 - mx) + expf(l1 - mx));
        out[b * 2 + 0] = l0 - lse;
        out[b * 2 + 1] = l1 - lse;
    }
}

// ---------------- launch --------------------------------------------------------
extern "C" void kernel_launch(void* const* d_in, const int* in_sizes, int n_in,
                              void* d_out, int out_size) {
    const float* x     = (const float*)d_in[0];
    const float* W1    = (const float*)d_in[1];
    const float* b1    = (const float*)d_in[2];
    const float* cls1  = (const float*)d_in[3];
    const float* W2    = (const float*)d_in[4];
    const float* b2    = (const float*)d_in[5];
    const float* cls2  = (const float*)d_in[6];
    const float* ln1_g = (const float*)d_in[7];
    const float* ln1_b = (const float*)d_in[8];
    const float* Wq    = (const float*)d_in[9];
    const float* bq    = (const float*)d_in[10];
    const float* Wk    = (const float*)d_in[11];
    const float* bk    = (const float*)d_in[12];
    const float* Wv    = (const float*)d_in[13];
    const float* bv    = (const float*)d_in[14];
    const float* Wp    = (const float*)d_in[15];
    const float* bp    = (const float*)d_in[16];
    const float* ln2_g = (const float*)d_in[17];
    const float* ln2_b = (const float*)d_in[18];
    const float* lnc_g = (const float*)d_in[19];
    const float* lnc_b = (const float*)d_in[20];
    const float* Wc    = (const float*)d_in[21];
    const float* bc    = (const float*)d_in[22];
    float* out = (float*)d_out;

    static int inited = 0;
    if (!inited) {
        cudaFuncSetAttribute(gemm_nn,  cudaFuncAttributeMaxDynamicSharedMemorySize, SMEM_NN);
        cudaFuncSetAttribute(gemm_pe1, cudaFuncAttributeMaxDynamicSharedMemorySize, SMEM_NN);
        cudaFuncSetAttribute(flash_attn, cudaFuncAttributeMaxDynamicSharedMemorySize, FA_SMEM);
        inited = 1;
    }

    __half *x16, *T2, *Wt, *h16, *qkv, *o16;
    float *bqkv, *z, *hf, *pool;
    cudaGetSymbolAddress((void**)&x16, g_x16);
    cudaGetSymbolAddress((void**)&T2,  g_T2);
    cudaGetSymbolAddress((void**)&Wt,  g_Wt);
    cudaGetSymbolAddress((void**)&bqkv, g_bqkv);
    cudaGetSymbolAddress((void**)&z,   g_z);
    cudaGetSymbolAddress((void**)&h16, g_h16);
    cudaGetSymbolAddress((void**)&hf,  g_hf);
    cudaGetSymbolAddress((void**)&qkv, g_qkv);
    cudaGetSymbolAddress((void**)&o16, g_o16);
    cudaGetSymbolAddress((void**)&pool, g_pool);

    prep_w<<<(PREP_N + 255) / 256, 256>>>(W1, W2, Wq, Wk, Wv, Wp, bq, bk, bv, Wt, bqkv);
    x2h<<<XN / 1024, 256>>>(x, x16);
    im2col2<<<dim3(196, B_), 192>>>(x, T2);
    cls_fill<<<B_, 256>>>(cls1, cls2, z);

    gemm_pe1<<<dim3(2, 196), 256, SMEM_NN>>>(x16, Wt + OFF_W1P, b1, z);
    gemm_nn<<<dim3(2, 196), 256, SMEM_NN>>>(T2, Wt + OFF_W2, b2, z, 256, 192, 2);

    ln1_kernel<<<MTOK / 8, 256>>>(z, ln1_g, ln1_b, h16);

    gemm_nn<<<dim3(6, 394), 256, SMEM_NN>>>(h16, Wt + OFF_WQKV, bqkv, qkv, 768, 256, 5);

    flash_attn<<<dim3(4, 256), 256, FA_SMEM>>>(qkv, o16);

    gemm_nn<<<dim3(2, 394), 256, SMEM_NN>>>(o16, Wt + OFF_WP, bp, hf, 256, 256, 0);

    ln2_pool<<<dim3(B_, 8), 256>>>(hf, ln2_g, ln2_b, z, pool);
    head_kernel<<<B_, 256>>>(pool, lnc_g, lnc_b, Wc, bc, out);
}

// round 15
// speedup vs baseline: 2.0526x; 1.0398x over previous
#include <cuda_runtime.h>
#include <cuda_fp16.h>
#include <math.h>

#define B_      128
#define EMB_    256
#define NTOK    394
#define MTOK    (B_ * 394)           // 50432
#define MPE     (B_ * 196)           // 25088
#define XN      (B_ * 3 * 224 * 224) // 19267584

#define KC      32
#define ASTRH   40                   // A smem row stride (halfs)
#define BSTRH2  136                  // B smem row stride (half2)
#define A_STG   (128 * ASTRH)        // 5120 halfs / stage
#define B_STG   (BSTRH2 * 16 * 2)    // 4352 halfs / stage
#define SMEM_NN ((3 * (A_STG + B_STG)) * 2)   // 56832 B
#define FA_SMEM (128*136*2 + 2*64*136*2 + 2*32*136*4)  // 104448
#define FA_NKT  7
#define QKV_SZ  ((size_t)B_ * 2 * 394 * 128)  // halfs per q/k/v region

// ---------------- scratch ---------------------------------------------------
__device__ __half g_x16[XN];
__device__ __half g_T2[MPE * 192];
__device__ __half g_Wt[507904];      // W2 | Wp | W1perm | Wqkv, k-pair interleaved
__device__ float  g_bqkv[768];
__device__ float  g_z [MTOK * EMB_];
__device__ __half g_h16[MTOK * EMB_];
__device__ float  g_hf[MTOK * EMB_];
__device__ __half g_qkv[3 * QKV_SZ];
__device__ __half g_o16[MTOK * EMB_];
__device__ float  g_pool[B_ * 8 * EMB_];

#define OFF_W2   0
#define OFF_WP   49152
#define OFF_W1P  114688
#define OFF_WQKV 311296
#define PREP_N   508672

// prep_all block ranges
#define PREP_BLK 1987
#define X2H_BLK  18816
#define IM2_BLK  18816
#define IM2_N    (MPE * 192)         // 4816896
#define ALL_BLK  (PREP_BLK + X2H_BLK + IM2_BLK + B_)

// ---------------- helpers ----------------------------------------------------
__device__ __forceinline__ void mma16(float* acc, const unsigned* a, const unsigned* b) {
    asm volatile(
        "mma.sync.aligned.m16n8k16.row.col.f32.f16.f16.f32 "
        "{%0,%1,%2,%3}, {%4,%5,%6,%7}, {%8,%9}, {%0,%1,%2,%3};\n"
        : "+f"(acc[0]), "+f"(acc[1]), "+f"(acc[2]), "+f"(acc[3])
        : "r"(a[0]), "r"(a[1]), "r"(a[2]), "r"(a[3]), "r"(b[0]), "r"(b[1]));
}
__device__ __forceinline__ unsigned pack2(float a, float b) {
    __half2 h = __floats2half2_rn(a, b);
    return *reinterpret_cast<unsigned*>(&h);
}
__device__ __forceinline__ void cpa16(void* dst, const void* src, bool pred) {
    unsigned d = (unsigned)__cvta_generic_to_shared(dst);
    int sz = pred ? 16 : 0;
    asm volatile("cp.async.cg.shared.global [%0], [%1], 16, %2;\n"
                 :: "r"(d), "l"(src), "r"(sz));
}
__device__ __forceinline__ void cpa_commit() { asm volatile("cp.async.commit_group;\n"); }
template <int N>
__device__ __forceinline__ void cpa_wait() { asm volatile("cp.async.wait_group %0;\n" :: "n"(N)); }

// ---------------- fused preamble: weights + x->half + im2col2 + cls ----------
__global__ void prep_all(const float* __restrict__ x,
                         const float* __restrict__ W1, const float* __restrict__ W2,
                         const float* __restrict__ Wq, const float* __restrict__ Wk,
                         const float* __restrict__ Wv, const float* __restrict__ Wp,
                         const float* __restrict__ bq, const float* __restrict__ bk,
                         const float* __restrict__ bv,
                         const float* __restrict__ cls1, const float* __restrict__ cls2,
                         __half* __restrict__ x16, __half* __restrict__ T2,
                         __half* __restrict__ Wt, float* __restrict__ bqkv,
                         float* __restrict__ z) {
    int blk = blockIdx.x, tid = threadIdx.x;
    if (blk < PREP_BLK) {
        int i = blk * 256 + tid;
        if (i >= PREP_N) return;
        if (i >= 507904) {
            int j = i - 507904;
            int which = j >> 8, col = j & 255;
            const float* src = which == 0 ? bq : which == 1 ? bk : bv;
            bqkv[j] = src[col];
            return;
        }
        float v;
        if (i < OFF_WP) {                       // W2 [192][256] -> [96][256][2]
            int kp = i >> 9, r = i & 511, n = r >> 1, p = r & 1;
            v = W2[(2 * kp + p) * 256 + n];
        } else if (i < OFF_W1P) {               // Wp
            int idx = i - OFF_WP;
            int kp = idx >> 9, r = idx & 511, n = r >> 1, p = r & 1;
            v = Wp[(2 * kp + p) * 256 + n];
        } else if (i < OFF_WQKV) {              // W1 permuted + interleaved
            int idx = i - OFF_W1P;
            int kp = idx >> 9, r = idx & 511, n = r >> 1, p = r & 1;
            int kpr = 2 * kp + p;
            int c = kpr >> 8, rem = kpr & 255;
            int pi = rem >> 4, pj = rem & 15;
            v = W1[((pi * 16 + pj) * 3 + c) * 256 + n];
        } else {                                // Wqkv
            int idx = i - OFF_WQKV;
            int kp = idx / 1536, r = idx % 1536, n = r >> 1, p = r & 1;
            int k = 2 * kp + p;
            int which = n >> 8, col = n & 255;
            const float* src = which == 0 ? Wq : which == 1 ? Wk : Wv;
            v = src[k * 256 + col];
        }
        Wt[i] = __float2half_rn(v);
    } else if (blk < PREP_BLK + X2H_BLK) {
        int i = ((blk - PREP_BLK) * 256 + tid) * 4;
        float4 v = *(const float4*)(x + i);
        *(__half2*)(x16 + i)     = __floats2half2_rn(v.x, v.y);
        *(__half2*)(x16 + i + 2) = __floats2half2_rn(v.z, v.w);
    } else if (blk < PREP_BLK + X2H_BLK + IM2_BLK) {
        int o = (blk - PREP_BLK - X2H_BLK) * 256 + tid;
        if (o >= IM2_N) return;
        int row = o / 192, t = o - row * 192;
        int b = row / 196, i2 = row - b * 196;
        int jdx = 4 * i2 + 3;
        int ph = jdx / 28, pw = jdx - ph * 28;
        int pos = t / 3, c = t - pos * 3;
        int pi = pos >> 3, pj = pos & 7;
        T2[o] = __float2half_rn(
            x[(size_t)b * 150528 + (size_t)c * 50176 +
              (size_t)(ph * 8 + pi) * 224 + pw * 8 + pj]);
    } else {
        int b = blk - (PREP_BLK + X2H_BLK + IM2_BLK);
        int e = tid;
        z[((size_t)b * NTOK + 0)   * EMB_ + e] = cls2[e];
        z[((size_t)b * NTOK + 197) * EMB_ + e] = cls1[e];
    }
}

// ---------------- fused patch-embed GEMM (pe1 implicit im2col + pe2) ---------
__global__ __launch_bounds__(256, 2)
void gemm_pe(const __half* __restrict__ x, const __half* __restrict__ T2,
             const __half* __restrict__ W1p, const __half* __restrict__ W2p,
             const float* __restrict__ b1, const float* __restrict__ b2,
             float* __restrict__ z) {
    extern __shared__ __half smem[];
    __half* As = smem;
    __half* Bs = smem + 3 * A_STG;
    int tid = threadIdx.x;
    int bn = blockIdx.x * 128;
    int wid = tid >> 5, lane = tid & 31;
    int wm = wid & 3, wn = wid >> 2;
    int gid = lane >> 2, tg = lane & 3;
    int arow = wm * 32 + gid;

    if (blockIdx.y < 196) {
        // ================= pe1: K=768, implicit im2col from x16 ==============
        int bm = blockIdx.y * 128;
        size_t rowb[2];
#pragma unroll
        for (int i = 0; i < 2; i++) {
            int m = bm + (tid >> 2) + i * 64;
            int b = m / 196, j = m % 196;
            int ph = j / 14, pw = j % 14;
            rowb[i] = (size_t)b * 150528 + (size_t)(ph * 16) * 224 + pw * 16;
        }
        int ch = tid & 3;
        int pj0 = (ch & 1) * 8, gsel = ch >> 1;

        auto loadA = [&](int s, int k0) {
            __half* dst = As + s * A_STG;
            int gidx = (k0 >> 4) + gsel;
            int c = gidx >> 4, pi = gidx & 15;
            size_t off = (size_t)c * 50176 + pi * 224 + pj0;
#pragma unroll
            for (int i = 0; i < 2; i++) {
                int row = (tid >> 2) + i * 64;
                cpa16(dst + row * ASTRH + ch * 8, x + rowb[i] + off, true);
            }
        };
        auto loadB = [&](int s, int k0) {
            const __half2* B2 = (const __half2*)W1p;
            __half2* dst = (__half2*)(Bs + s * B_STG);
            int kp0 = k0 >> 1;
#pragma unroll
            for (int i = 0; i < 2; i++) {
                int idx = tid + i * 256;
                int row = idx >> 5, cc = (idx & 31) << 2;
                cpa16(dst + row * BSTRH2 + cc, B2 + (size_t)(kp0 + row) * 256 + bn + cc, true);
            }
        };

        float acc[2][8][4] = {};
        const int nk = 768 / KC;
        loadA(0, 0); loadB(0, 0); cpa_commit();
        loadA(1, KC); loadB(1, KC); cpa_commit();
        for (int it = 0; it < nk; it++) {
            cpa_wait<1>(); __syncthreads();
            if (it + 2 < nk) { loadA((it + 2) % 3, (it + 2) * KC); loadB((it + 2) % 3, (it + 2) * KC); }
            cpa_commit();
            const unsigned* Au = (const unsigned*)(As + (it % 3) * A_STG);
            const unsigned* Bu = (const unsigned*)(Bs + (it % 3) * B_STG);
#pragma unroll
            for (int kk2 = 0; kk2 < 2; kk2++) {
                unsigned af[2][4], bf[8][2];
#pragma unroll
                for (int mt = 0; mt < 2; mt++) {
                    int r = arow + mt * 16;
                    af[mt][0] = Au[r * 20 + kk2 * 8 + tg];
                    af[mt][1] = Au[(r + 8) * 20 + kk2 * 8 + tg];
                    af[mt][2] = Au[r * 20 + kk2 * 8 + tg + 4];
                    af[mt][3] = Au[(r + 8) * 20 + kk2 * 8 + tg + 4];
                }
#pragma unroll
                for (int nt = 0; nt < 8; nt++) {
                    int n = wn * 64 + nt * 8 + gid;
                    bf[nt][0] = Bu[(kk2 * 8 + tg) * BSTRH2 + n];
                    bf[nt][1] = Bu[(kk2 * 8 + tg + 4) * BSTRH2 + n];
                }
#pragma unroll
                for (int mt = 0; mt < 2; mt++)
#pragma unroll
                    for (int nt = 0; nt < 8; nt++)
                        mma16(acc[mt][nt], af[mt], bf[nt]);
            }
            __syncthreads();
        }
#pragma unroll
        for (int mt = 0; mt < 2; mt++)
#pragma unroll
            for (int nt = 0; nt < 8; nt++) {
                int n = bn + wn * 64 + nt * 8 + tg * 2;
                float bv0 = b1[n], bv1 = b1[n + 1];
#pragma unroll
                for (int half_ = 0; half_ < 2; half_++) {
                    int m = bm + wm * 32 + mt * 16 + gid + half_ * 8;
                    int b = m / 196, jj = m % 196;
                    *(float2*)&z[((size_t)b * NTOK + 198 + jj) * EMB_ + n] =
                        make_float2(acc[mt][nt][half_ * 2] + bv0,
                                    acc[mt][nt][half_ * 2 + 1] + bv1);
                }
            }
    } else {
        // ================= pe2: K=192, A = T2 ================================
        int bm = (blockIdx.y - 196) * 128;
        auto loadA = [&](int s, int k0) {
            __half* dst = As + s * A_STG;
#pragma unroll
            for (int i = 0; i < 2; i++) {
                int idx = tid + i * 256;
                int row = idx >> 2, cc = (idx & 3) << 3;
                cpa16(dst + row * ASTRH + cc, T2 + (size_t)(bm + row) * 192 + k0 + cc, true);
            }
        };
        auto loadB = [&](int s, int k0) {
            const __half2* B2 = (const __half2*)W2p;
            __half2* dst = (__half2*)(Bs + s * B_STG);
            int kp0 = k0 >> 1;
#pragma unroll
            for (int i = 0; i < 2; i++) {
                int idx = tid + i * 256;
                int row = idx >> 5, cc = (idx & 31) << 2;
                cpa16(dst + row * BSTRH2 + cc, B2 + (size_t)(kp0 + row) * 256 + bn + cc, true);
            }
        };

        float acc[2][8][4] = {};
        const int nk = 192 / KC;        // 6
        loadA(0, 0); loadB(0, 0); cpa_commit();
        loadA(1, KC); loadB(1, KC); cpa_commit();
        for (int it = 0; it < nk; it++) {
            cpa_wait<1>(); __syncthreads();
            if (it + 2 < nk) { loadA((it + 2) % 3, (it + 2) * KC); loadB((it + 2) % 3, (it + 2) * KC); }
            cpa_commit();
            const unsigned* Au = (const unsigned*)(As + (it % 3) * A_STG);
            const unsigned* Bu = (const unsigned*)(Bs + (it % 3) * B_STG);
#pragma unroll
            for (int kk2 = 0; kk2 < 2; kk2++) {
                unsigned af[2][4], bf[8][2];
#pragma unroll
                for (int mt = 0; mt < 2; mt++) {
                    int r = arow + mt * 16;
                    af[mt][0] = Au[r * 20 + kk2 * 8 + tg];
                    af[mt][1] = Au[(r + 8) * 20 + kk2 * 8 + tg];
                    af[mt][2] = Au[r * 20 + kk2 * 8 + tg + 4];
                    af[mt][3] = Au[(r + 8) * 20 + kk2 * 8 + tg + 4];
                }
#pragma unroll
                for (int nt = 0; nt < 8; nt++) {
                    int n = wn * 64 + nt * 8 + gid;
                    bf[nt][0] = Bu[(kk2 * 8 + tg) * BSTRH2 + n];
                    bf[nt][1] = Bu[(kk2 * 8 + tg + 4) * BSTRH2 + n];
                }
#pragma unroll
                for (int mt = 0; mt < 2; mt++)
#pragma unroll
                    for (int nt = 0; nt < 8; nt++)
                        mma16(acc[mt][nt], af[mt], bf[nt]);
            }
            __syncthreads();
        }
#pragma unroll
        for (int mt = 0; mt < 2; mt++)
#pragma unroll
            for (int nt = 0; nt < 8; nt++) {
                int n = bn + wn * 64 + nt * 8 + tg * 2;
                float bv0 = b2[n], bv1 = b2[n + 1];
#pragma unroll
                for (int half_ = 0; half_ < 2; half_++) {
                    int m = bm + wm * 32 + mt * 16 + gid + half_ * 8;
                    int b = m / 196, jj = m % 196;
                    *(float2*)&z[((size_t)b * NTOK + 1 + jj) * EMB_ + n] =
                        make_float2(acc[mt][nt][half_ * 2] + bv0,
                                    acc[mt][nt][half_ * 2 + 1] + bv1);
                }
            }
    }
}

// ---------------- NN GEMM fp16: modes 0 (proj->f32), 5 (qkv) -----------------
__global__ __launch_bounds__(256, 2)
void gemm_nn(const __half* __restrict__ A, const __half* __restrict__ Bm,
             const float* __restrict__ bias, void* __restrict__ Cout,
             int N, int K, int mode) {
    extern __shared__ __half smem[];
    __half* As = smem;
    __half* Bs = smem + 3 * A_STG;
    int tid = threadIdx.x;
    int bm = blockIdx.y * 128, bn = blockIdx.x * 128;
    int wid = tid >> 5, lane = tid & 31;
    int wm = wid & 3, wn = wid >> 2;
    int gid = lane >> 2, tg = lane & 3;

    auto loadA = [&](int s, int k0) {
        __half* dst = As + s * A_STG;
#pragma unroll
        for (int i = 0; i < 2; i++) {
            int idx = tid + i * 256;
            int row = idx >> 2, cc = (idx & 3) << 3;
            cpa16(dst + row * ASTRH + cc, A + (size_t)(bm + row) * K + k0 + cc, true);
        }
    };
    auto loadB = [&](int s, int k0) {
        const __half2* B2 = (const __half2*)Bm;
        __half2* dst = (__half2*)(Bs + s * B_STG);
        int kp0 = k0 >> 1;
#pragma unroll
        for (int i = 0; i < 2; i++) {
            int idx = tid + i * 256;
            int row = idx >> 5, cc = (idx & 31) << 2;
            cpa16(dst + row * BSTRH2 + cc, B2 + (size_t)(kp0 + row) * N + bn + cc, true);
        }
    };

    float acc[2][8][4] = {};
    int nk = K / KC;
    loadA(0, 0); loadB(0, 0); cpa_commit();
    loadA(1, KC); loadB(1, KC); cpa_commit();

    int arow = wm * 32 + gid;
    for (int it = 0; it < nk; it++) {
        cpa_wait<1>(); __syncthreads();
        if (it + 2 < nk) { loadA((it + 2) % 3, (it + 2) * KC); loadB((it + 2) % 3, (it + 2) * KC); }
        cpa_commit();
        const unsigned* Au = (const unsigned*)(As + (it % 3) * A_STG);
        const unsigned* Bu = (const unsigned*)(Bs + (it % 3) * B_STG);
#pragma unroll
        for (int kk2 = 0; kk2 < 2; kk2++) {
            unsigned af[2][4], bf[8][2];
#pragma unroll
            for (int mt = 0; mt < 2; mt++) {
                int r = arow + mt * 16;
                af[mt][0] = Au[r * 20 + kk2 * 8 + tg];
                af[mt][1] = Au[(r + 8) * 20 + kk2 * 8 + tg];
                af[mt][2] = Au[r * 20 + kk2 * 8 + tg + 4];
                af[mt][3] = Au[(r + 8) * 20 + kk2 * 8 + tg + 4];
            }
#pragma unroll
            for (int nt = 0; nt < 8; nt++) {
                int n = wn * 64 + nt * 8 + gid;
                bf[nt][0] = Bu[(kk2 * 8 + tg) * BSTRH2 + n];
                bf[nt][1] = Bu[(kk2 * 8 + tg + 4) * BSTRH2 + n];
            }
#pragma unroll
            for (int mt = 0; mt < 2; mt++)
#pragma unroll
                for (int nt = 0; nt < 8; nt++)
                    mma16(acc[mt][nt], af[mt], bf[nt]);
        }
        __syncthreads();
    }

#pragma unroll
    for (int mt = 0; mt < 2; mt++) {
#pragma unroll
        for (int nt = 0; nt < 8; nt++) {
            int n = bn + wn * 64 + nt * 8 + tg * 2;
            float bv0 = bias ? bias[n] : 0.f;
            float bv1 = bias ? bias[n + 1] : 0.f;
#pragma unroll
            for (int half_ = 0; half_ < 2; half_++) {
                int m = bm + wm * 32 + mt * 16 + gid + half_ * 8;
                float v0 = acc[mt][nt][half_ * 2 + 0] + bv0;
                float v1 = acc[mt][nt][half_ * 2 + 1] + bv1;
                if (mode == 0) {
                    *(float2*)&((float*)Cout)[(size_t)m * 256 + n] = make_float2(v0, v1);
                } else {
                    int b = m / NTOK, t = m % NTOK;
                    int which = n >> 8, d2 = n & 255;
                    int hh = d2 >> 7, dd = d2 & 127;
                    int bh = b * 2 + hh;
                    __half* base = (__half*)Cout;
                    if (which < 2) {
                        __half2 hv = __floats2half2_rn(v0, v1);
                        *(__half2*)&base[(size_t)which * QKV_SZ +
                                         ((size_t)bh * 394 + t) * 128 + dd] = hv;
                    } else {
                        __half* vdst = base + 2 * QKV_SZ +
                                       ((size_t)bh * 197 + (t >> 1)) * 256 + dd * 2 + (t & 1);
                        vdst[0] = __float2half_rn(v0);
                        vdst[2] = __float2half_rn(v1);
                    }
                }
            }
        }
    }
}

// ---------------- flash attention fp16: identity P-refragmentation -----------
__global__ __launch_bounds__(256)
void flash_attn(const __half* __restrict__ qkv, __half* __restrict__ Og) {
    extern __shared__ __half smem[];
    __half* Qs = smem;                         // [128][136]
    __half* Ks = Qs + 128 * 136;               // [2][64][136]
    __half* Vs = Ks + 2 * 64 * 136;            // [2][32][272]
    int tid = threadIdx.x, lane = tid & 31, wid = tid >> 5;
    int gid = lane >> 2, tg = lane & 3;
    int qt = blockIdx.x, bh = blockIdx.y;
    const __half* Qb = qkv + (size_t)bh * 394 * 128;
    const __half* Kb = qkv + QKV_SZ + (size_t)bh * 394 * 128;
    const __half* Vb = qkv + 2 * QKV_SZ + (size_t)bh * 197 * 256;
    __half* Ob = Og + (size_t)(bh >> 1) * NTOK * EMB_ + (bh & 1) * 128;
    int qbase = qt * 128;
    int r0 = wid * 16 + gid;

    auto loadQ = [&]() {
#pragma unroll
        for (int i = 0; i < 8; i++) {
            int idx = tid + i * 256; int row = idx >> 4; int cc = (idx & 15) << 3;
            int gr = qbase + row; if (gr >= 394) gr = 0;
            cpa16(Qs + row * 136 + cc, Qb + (size_t)gr * 128 + cc, true);
        }
    };
    auto loadK = [&](int st, int kt) {
        __half* dst = Ks + st * 64 * 136;
#pragma unroll
        for (int i = 0; i < 4; i++) {
            int idx = tid + i * 256; int row = idx >> 4; int cc = (idx & 15) << 3;
            int gr = kt * 64 + row; if (gr >= 394) gr = 0;
            cpa16(dst + row * 136 + cc, Kb + (size_t)gr * 128 + cc, true);
        }
    };
    auto loadV = [&](int st, int kt) {
        __half* dst = Vs + st * 32 * 272;
#pragma unroll
        for (int i = 0; i < 4; i++) {
            int idx = tid + i * 256; int row = idx >> 5; int cc = (idx & 31) << 3;
            int gp = kt * 32 + row; if (gp >= 197) gp = 0;
            cpa16(dst + row * 272 + cc, Vb + (size_t)gp * 256 + cc, true);
        }
    };

    loadQ(); loadK(0, 0); loadV(0, 0); cpa_commit();
    loadK(1, 1); loadV(1, 1); cpa_commit();

    float accO[16][4] = {};
    float m0 = -1e30f, m1 = -1e30f, l0 = 0.f, l1 = 0.f;

    for (int kt = 0; kt < FA_NKT; kt++) {
        int st = kt & 1;
        cpa_wait<1>();
        __syncthreads();

        float accS[8][4] = {};
        {
            const unsigned* Qu = (const unsigned*)Qs;
            const unsigned* Ku = (const unsigned*)(Ks + st * 64 * 136);
#pragma unroll
            for (int j = 0; j < 8; j++) {
                unsigned af[4];
                af[0] = Qu[r0 * 68 + j * 8 + tg];
                af[1] = Qu[(r0 + 8) * 68 + j * 8 + tg];
                af[2] = Qu[r0 * 68 + j * 8 + tg + 4];
                af[3] = Qu[(r0 + 8) * 68 + j * 8 + tg + 4];
#pragma unroll
                for (int nt = 0; nt < 8; nt++) {
                    int kv = nt * 8 + gid;
                    unsigned bf[2];
                    bf[0] = Ku[kv * 68 + j * 8 + tg];
                    bf[1] = Ku[kv * 68 + j * 8 + tg + 4];
                    mma16(accS[nt], af, bf);
                }
            }
        }
        int cb = kt * 64 + tg * 2;
#pragma unroll
        for (int nt = 0; nt < 8; nt++) {
            int c0 = cb + nt * 8;
            if (c0 >= 394)     { accS[nt][0] = -1e30f; accS[nt][2] = -1e30f; }
            if (c0 + 1 >= 394) { accS[nt][1] = -1e30f; accS[nt][3] = -1e30f; }
        }
        float rm0 = -1e30f, rm1 = -1e30f;
#pragma unroll
        for (int nt = 0; nt < 8; nt++) {
            rm0 = fmaxf(rm0, fmaxf(accS[nt][0], accS[nt][1]));
            rm1 = fmaxf(rm1, fmaxf(accS[nt][2], accS[nt][3]));
        }
        rm0 = fmaxf(rm0, __shfl_xor_sync(0xffffffffu, rm0, 1));
        rm0 = fmaxf(rm0, __shfl_xor_sync(0xffffffffu, rm0, 2));
        rm1 = fmaxf(rm1, __shfl_xor_sync(0xffffffffu, rm1, 1));
        rm1 = fmaxf(rm1, __shfl_xor_sync(0xffffffffu, rm1, 2));
        float mn0 = fmaxf(m0, rm0), mn1 = fmaxf(m1, rm1);
        float sc0 = __expf(m0 - mn0), sc1 = __expf(m1 - mn1);
        float rs0 = 0.f, rs1 = 0.f;
#pragma unroll
        for (int nt = 0; nt < 8; nt++) {
            accS[nt][0] = __expf(accS[nt][0] - mn0);
            accS[nt][1] = __expf(accS[nt][1] - mn0);
            accS[nt][2] = __expf(accS[nt][2] - mn1);
            accS[nt][3] = __expf(accS[nt][3] - mn1);
            rs0 += accS[nt][0] + accS[nt][1];
            rs1 += accS[nt][2] + accS[nt][3];
        }
        rs0 += __shfl_xor_sync(0xffffffffu, rs0, 1);
        rs0 += __shfl_xor_sync(0xffffffffu, rs0, 2);
        rs1 += __shfl_xor_sync(0xffffffffu, rs1, 1);
        rs1 += __shfl_xor_sync(0xffffffffu, rs1, 2);
        l0 = l0 * sc0 + rs0;  l1 = l1 * sc1 + rs1;
        m0 = mn0;  m1 = mn1;
#pragma unroll
        for (int nt = 0; nt < 16; nt++) {
            accO[nt][0] *= sc0; accO[nt][1] *= sc0;
            accO[nt][2] *= sc1; accO[nt][3] *= sc1;
        }
        {
            const unsigned* Vu = (const unsigned*)(Vs + st * 32 * 272);
#pragma unroll
            for (int j2 = 0; j2 < 4; j2++) {
                unsigned a[4];
                a[0] = pack2(accS[2 * j2][0],     accS[2 * j2][1]);
                a[1] = pack2(accS[2 * j2][2],     accS[2 * j2][3]);
                a[2] = pack2(accS[2 * j2 + 1][0], accS[2 * j2 + 1][1]);
                a[3] = pack2(accS[2 * j2 + 1][2], accS[2 * j2 + 1][3]);
#pragma unroll
                for (int nt = 0; nt < 16; nt++) {
                    int n = nt * 8 + gid;
                    unsigned bf[2];
                    bf[0] = Vu[(8 * j2 + tg) * 136 + n];
                    bf[1] = Vu[(8 * j2 + tg + 4) * 136 + n];
                    mma16(accO[nt], a, bf);
                }
            }
        }
        __syncthreads();
        if (kt + 2 < FA_NKT) { loadK(st, kt + 2); loadV(st, kt + 2); }
        cpa_commit();
    }

    float inv0 = 1.f / (l0 * 16.f), inv1 = 1.f / (l1 * 16.f);
    int gr0 = qbase + r0, gr1 = gr0 + 8;
#pragma unroll
    for (int nt = 0; nt < 16; nt++) {
        int col = nt * 8 + tg * 2;
        if (gr0 < 394)
            *(__half2*)&Ob[(size_t)gr0 * EMB_ + col] =
                __floats2half2_rn(accO[nt][0] * inv0, accO[nt][1] * inv0);
        if (gr1 < 394)
            *(__half2*)&Ob[(size_t)gr1 * EMB_ + col] =
                __floats2half2_rn(accO[nt][2] * inv1, accO[nt][3] * inv1);
    }
}

// ---------------- ln1: warp-per-token, z fp32 -> half, no block sync ---------
__global__ __launch_bounds__(256)
void ln1_kernel(const float* __restrict__ in, const float* __restrict__ g,
                const float* __restrict__ b, __half* __restrict__ out) {
    int warp = threadIdx.x >> 5, lane = threadIdx.x & 31;
    int r = blockIdx.x * 8 + warp;
    const float* row = in + (size_t)r * EMB_ + lane * 8;
    float4 v0 = *(const float4*)row;
    float4 v1 = *(const float4*)(row + 4);
    float v[8] = {v0.x, v0.y, v0.z, v0.w, v1.x, v1.y, v1.z, v1.w};
    float s = 0.f, s2 = 0.f;
#pragma unroll
    for (int i = 0; i < 8; i++) { s += v[i]; s2 += v[i] * v[i]; }
#pragma unroll
    for (int off = 16; off > 0; off >>= 1) {
        s  += __shfl_xor_sync(0xffffffffu, s,  off);
        s2 += __shfl_xor_sync(0xffffffffu, s2, off);
    }
    float mean = s * (1.f / EMB_);
    float rstd = rsqrtf(s2 * (1.f / EMB_) - mean * mean + 1e-5f);
    float4 g0 = *(const float4*)(g + lane * 8);
    float4 g1 = *(const float4*)(g + lane * 8 + 4);
    float4 b0 = *(const float4*)(b + lane * 8);
    float4 b1 = *(const float4*)(b + lane * 8 + 4);
    float gg[8] = {g0.x, g0.y, g0.z, g0.w, g1.x, g1.y, g1.z, g1.w};
    float bb[8] = {b0.x, b0.y, b0.z, b0.w, b1.x, b1.y, b1.z, b1.w};
    __half2 h[4];
#pragma unroll
    for (int i = 0; i < 4; i++) {
        float n0 = (v[2 * i]     - mean) * rstd * gg[2 * i]     + bb[2 * i];
        float n1 = (v[2 * i + 1] - mean) * rstd * gg[2 * i + 1] + bb[2 * i + 1];
        h[i] = __floats2half2_rn(n0, n1);
    }
    *(uint4*)(out + (size_t)r * EMB_ + lane * 8) = *(uint4*)h;
}

// ---- ln2 + residual + pool partial: warp-per-token, z NOT written back ------
__global__ __launch_bounds__(256)
void ln2_pool(const float* __restrict__ h, const float* __restrict__ g,
              const float* __restrict__ bb, const float* __restrict__ z,
              float* __restrict__ pool) {
    int b = blockIdx.x, seg = blockIdx.y;
    int warp = threadIdx.x >> 5, lane = threadIdx.x & 31;
    int t0 = seg * 50, t1 = t0 + 50; if (t1 > NTOK) t1 = NTOK;
    float4 g0 = *(const float4*)(g + lane * 8);
    float4 g1 = *(const float4*)(g + lane * 8 + 4);
    float4 bv0 = *(const float4*)(bb + lane * 8);
    float4 bv1 = *(const float4*)(bb + lane * 8 + 4);
    float gg[8] = {g0.x, g0.y, g0.z, g0.w, g1.x, g1.y, g1.z, g1.w};
    float be[8] = {bv0.x, bv0.y, bv0.z, bv0.w, bv1.x, bv1.y, bv1.z, bv1.w};
    float accp[8] = {};
    for (int t = t0 + warp; t < t1; t += 8) {
        size_t base = ((size_t)b * NTOK + t) * EMB_ + lane * 8;
        float4 v0 = *(const float4*)(h + base);
        float4 v1 = *(const float4*)(h + base + 4);
        float v[8] = {v0.x, v0.y, v0.z, v0.w, v1.x, v1.y, v1.z, v1.w};
        float s = 0.f, s2 = 0.f;
#pragma unroll
        for (int i = 0; i < 8; i++) { s += v[i]; s2 += v[i] * v[i]; }
#pragma unroll
        for (int off = 16; off > 0; off >>= 1) {
            s  += __shfl_xor_sync(0xffffffffu, s,  off);
            s2 += __shfl_xor_sync(0xffffffffu, s2, off);
        }
        float mean = s * (1.f / EMB_);
        float rstd = rsqrtf(s2 * (1.f / EMB_) - mean * mean + 1e-5f);
        float4 z0 = *(const float4*)(z + base);
        float4 z1 = *(const float4*)(z + base + 4);
        float zv[8] = {z0.x, z0.y, z0.z, z0.w, z1.x, z1.y, z1.z, z1.w};
#pragma unroll
        for (int i = 0; i < 8; i++)
            accp[i] += zv[i] + (v[i] - mean) * rstd * gg[i] + be[i];
    }
    __shared__ float sm[8][256];
#pragma unroll
    for (int i = 0; i < 8; i++) sm[warp][lane * 8 + i] = accp[i];
    __syncthreads();
    int e = threadIdx.x;
    float tot = 0.f;
#pragma unroll
    for (int w = 0; w < 8; w++) tot += sm[w][e];
    pool[((size_t)b * 8 + seg) * EMB_ + e] = tot;
}

// ---------------- head ---------------------------------------------------------
__global__ __launch_bounds__(256)
void head_kernel(const float* __restrict__ pool, const float* __restrict__ g,
                 const float* __restrict__ bb, const float* __restrict__ Wc,
                 const float* __restrict__ bc, float* __restrict__ out) {
    int b = blockIdx.x, e = threadIdx.x;
    float s = 0.f;
#pragma unroll
    for (int i = 0; i < 8; i++) s += pool[((size_t)b * 8 + i) * EMB_ + e];
    float pooled = s * (1.f / NTOK);
    __shared__ float red[256];
    red[e] = pooled; __syncthreads();
    for (int st = 128; st > 0; st >>= 1) { if (e < st) red[e] += red[e + st]; __syncthreads(); }
    float mean = red[0] * (1.f / EMB_);
    __syncthreads();
    float d = pooled - mean;
    red[e] = d * d; __syncthreads();
    for (int st = 128; st > 0; st >>= 1) { if (e < st) red[e] += red[e + st]; __syncthreads(); }
    float var = red[0] * (1.f / EMB_);
    __syncthreads();
    float nv = d * rsqrtf(var + 1e-5f) * g[e] + bb[e];
    red[e] = nv * Wc[e * 2 + 0]; __syncthreads();
    for (int st = 128; st > 0; st >>= 1) { if (e < st) red[e] += red[e + st]; __syncthreads(); }
    float l0 = red[0] + bc[0];
    __syncthreads();
    red[e] = nv * Wc[e * 2 + 1]; __syncthreads();
    for (int st = 128; st > 0; st >>= 1) { if (e < st) red[e] += red[e + st]; __syncthreads(); }
    float l1 = red[0] + bc[1];
    if (e == 0) {
        float mx = fmaxf(l0, l1);
        float lse = mx + logf(expf(l0 - mx) + expf(l1 - mx));
        out[b * 2 + 0] = l0 - lse;
        out[b * 2 + 1] = l1 - lse;
    }
}

// ---------------- launch --------------------------------------------------------
extern "C" void kernel_launch(void* const* d_in, const int* in_sizes, int n_in,
                              void* d_out, int out_size) {
    const float* x     = (const float*)d_in[0];
    const float* W1    = (const float*)d_in[1];
    const float* b1    = (const float*)d_in[2];
    const float* cls1  = (const float*)d_in[3];
    const float* W2    = (const float*)d_in[4];
    const float* b2    = (const float*)d_in[5];
    const float* cls2  = (const float*)d_in[6];
    const float* ln1_g = (const float*)d_in[7];
    const float* ln1_b = (const float*)d_in[8];
    const float* Wq    = (const float*)d_in[9];
    const float* bq    = (const float*)d_in[10];
    const float* Wk    = (const float*)d_in[11];
    const float* bk    = (const float*)d_in[12];
    const float* Wv    = (const float*)d_in[13];
    const float* bv    = (const float*)d_in[14];
    const float* Wp    = (const float*)d_in[15];
    const float* bp    = (const float*)d_in[16];
    const float* ln2_g = (const float*)d_in[17];
    const float* ln2_b = (const float*)d_in[18];
    const float* lnc_g = (const float*)d_in[19];
    const float* lnc_b = (const float*)d_in[20];
    const float* Wc    = (const float*)d_in[21];
    const float* bc    = (const float*)d_in[22];
    float* out = (float*)d_out;

    static int inited = 0;
    if (!inited) {
        cudaFuncSetAttribute(gemm_nn, cudaFuncAttributeMaxDynamicSharedMemorySize, SMEM_NN);
        cudaFuncSetAttribute(gemm_pe, cudaFuncAttributeMaxDynamicSharedMemorySize, SMEM_NN);
        cudaFuncSetAttribute(flash_attn, cudaFuncAttributeMaxDynamicSharedMemorySize, FA_SMEM);
        inited = 1;
    }

    __half *x16, *T2, *Wt, *h16, *qkv, *o16;
    float *bqkv, *z, *hf, *pool;
    cudaGetSymbolAddress((void**)&x16, g_x16);
    cudaGetSymbolAddress((void**)&T2,  g_T2);
    cudaGetSymbolAddress((void**)&Wt,  g_Wt);
    cudaGetSymbolAddress((void**)&bqkv, g_bqkv);
    cudaGetSymbolAddress((void**)&z,   g_z);
    cudaGetSymbolAddress((void**)&h16, g_h16);
    cudaGetSymbolAddress((void**)&hf,  g_hf);
    cudaGetSymbolAddress((void**)&qkv, g_qkv);
    cudaGetSymbolAddress((void**)&o16, g_o16);
    cudaGetSymbolAddress((void**)&pool, g_pool);

    prep_all<<<ALL_BLK, 256>>>(x, W1, W2, Wq, Wk, Wv, Wp, bq, bk, bv,
                               cls1, cls2, x16, T2, Wt, bqkv, z);

    gemm_pe<<<dim3(2, 392), 256, SMEM_NN>>>(x16, T2, Wt + OFF_W1P, Wt + OFF_W2, b1, b2, z);

    ln1_kernel<<<MTOK / 8, 256>>>(z, ln1_g, ln1_b, h16);

    gemm_nn<<<dim3(6, 394), 256, SMEM_NN>>>(h16, Wt + OFF_WQKV, bqkv, qkv, 768, 256, 5);

    flash_attn<<<dim3(4, 256), 256, FA_SMEM>>>(qkv, o16);

    gemm_nn<<<dim3(2, 394), 256, SMEM_NN>>>(o16, Wt + OFF_WP, bp, hf, 256, 256, 0);

    ln2_pool<<<dim3(B_, 8), 256>>>(hf, ln2_g, ln2_b, z, pool);
    head_kernel<<<B_, 256>>>(pool, lnc_g, lnc_b, Wc, bc, out);
}

// round 16
// speedup vs baseline: 2.0582x; 1.0027x over previous
#include <cuda_runtime.h>
#include <cuda_fp16.h>
#include <math.h>

#define B_      128
#define EMB_    256
#define NTOK    394
#define MTOK    (B_ * 394)           // 50432
#define MPE     (B_ * 196)           // 25088
#define XN      (B_ * 3 * 224 * 224) // 19267584

#define KC      32
#define ASTRH   40                   // A smem row stride (halfs)
#define BSTR    40                   // B smem row stride (halfs)
#define A_STG   (128 * ASTRH)        // 5120 halfs / stage
#define B_STG   (128 * BSTR)         // 5120 halfs / stage
#define SMEM_NN ((3 * (A_STG + B_STG)) * 2)   // 61440 B
#define FA_SMEM (128*136*2 + 2*64*136*2 + 2*32*136*4)  // 104448
#define FA_NKT  7
#define QKV_SZ  ((size_t)B_ * 2 * 394 * 128)  // halfs per q/k/v region

// ---------------- scratch ---------------------------------------------------
__device__ __half g_x16[XN];
__device__ __half g_T2[MPE * 192];
__device__ __half g_Wt[507904];      // W2 | Wp | W1perm | Wqkv, all n-major [N][K]
__device__ float  g_bqkv[768];
__device__ float  g_z [MTOK * EMB_];
__device__ __half g_h16[MTOK * EMB_];
__device__ float  g_hf[MTOK * EMB_];
__device__ __half g_qkv[3 * QKV_SZ];
__device__ __half g_o16[MTOK * EMB_];
__device__ float  g_pool[B_ * 8 * EMB_];

#define OFF_W2   0
#define OFF_WP   49152
#define OFF_W1P  114688
#define OFF_WQKV 311296
#define PREP_N   508672

// prep_all block ranges
#define PREP_BLK 1987
#define X2H_BLK  18816
#define IM2_BLK  18816
#define IM2_N    (MPE * 192)
#define ALL_BLK  (PREP_BLK + X2H_BLK + IM2_BLK + B_)

// ---------------- helpers ----------------------------------------------------
__device__ __forceinline__ void mma16(float* acc, const unsigned* a, const unsigned* b) {
    asm volatile(
        "mma.sync.aligned.m16n8k16.row.col.f32.f16.f16.f32 "
        "{%0,%1,%2,%3}, {%4,%5,%6,%7}, {%8,%9}, {%0,%1,%2,%3};\n"
        : "+f"(acc[0]), "+f"(acc[1]), "+f"(acc[2]), "+f"(acc[3])
        : "r"(a[0]), "r"(a[1]), "r"(a[2]), "r"(a[3]), "r"(b[0]), "r"(b[1]));
}
__device__ __forceinline__ void ldm_x4(unsigned* r, unsigned addr) {
    asm volatile("ldmatrix.sync.aligned.m8n8.x4.shared.b16 {%0,%1,%2,%3}, [%4];"
                 : "=r"(r[0]), "=r"(r[1]), "=r"(r[2]), "=r"(r[3]) : "r"(addr));
}
__device__ __forceinline__ void ldm_x2(unsigned* r, unsigned addr) {
    asm volatile("ldmatrix.sync.aligned.m8n8.x2.shared.b16 {%0,%1}, [%2];"
                 : "=r"(r[0]), "=r"(r[1]) : "r"(addr));
}
__device__ __forceinline__ unsigned pack2(float a, float b) {
    __half2 h = __floats2half2_rn(a, b);
    return *reinterpret_cast<unsigned*>(&h);
}
__device__ __forceinline__ void cpa16(void* dst, const void* src, bool pred) {
    unsigned d = (unsigned)__cvta_generic_to_shared(dst);
    int sz = pred ? 16 : 0;
    asm volatile("cp.async.cg.shared.global [%0], [%1], 16, %2;\n"
                 :: "r"(d), "l"(src), "r"(sz));
}
__device__ __forceinline__ void cpa_commit() { asm volatile("cp.async.commit_group;\n"); }
template <int N>
__device__ __forceinline__ void cpa_wait() { asm volatile("cp.async.wait_group %0;\n" :: "n"(N)); }

// ---------------- fused preamble ----------------------------------------------
__global__ void prep_all(const float* __restrict__ x,
                         const float* __restrict__ W1, const float* __restrict__ W2,
                         const float* __restrict__ Wq, const float* __restrict__ Wk,
                         const float* __restrict__ Wv, const float* __restrict__ Wp,
                         const float* __restrict__ bq, const float* __restrict__ bk,
                         const float* __restrict__ bv,
                         const float* __restrict__ cls1, const float* __restrict__ cls2,
                         __half* __restrict__ x16, __half* __restrict__ T2,
                         __half* __restrict__ Wt, float* __restrict__ bqkv,
                         float* __restrict__ z) {
    int blk = blockIdx.x, tid = threadIdx.x;
    if (blk < PREP_BLK) {
        int i = blk * 256 + tid;
        if (i >= PREP_N) return;
        if (i >= 507904) {
            int j = i - 507904;
            int which = j >> 8, col = j & 255;
            const float* src = which == 0 ? bq : which == 1 ? bk : bv;
            bqkv[j] = src[col];
            return;
        }
        float v;
        if (i < OFF_WP) {                       // W2 n-major [256][192]
            int n = i / 192, k = i % 192;
            v = W2[k * 256 + n];
        } else if (i < OFF_W1P) {               // Wp n-major [256][256]
            int idx = i - OFF_WP;
            int n = idx >> 8, k = idx & 255;
            v = Wp[k * 256 + n];
        } else if (i < OFF_WQKV) {              // W1 permuted, n-major [256][768]
            int idx = i - OFF_W1P;
            int n = idx / 768, kp = idx % 768;
            int c = kp >> 8, rem = kp & 255;
            int pi = rem >> 4, pj = rem & 15;
            v = W1[((pi * 16 + pj) * 3 + c) * 256 + n];
        } else {                                // Wqkv n-major [768][256]
            int idx = i - OFF_WQKV;
            int n = idx >> 8, k = idx & 255;
            int which = n >> 8, col = n & 255;
            const float* src = which == 0 ? Wq : which == 1 ? Wk : Wv;
            v = src[k * 256 + col];
        }
        Wt[i] = __float2half_rn(v);
    } else if (blk < PREP_BLK + X2H_BLK) {
        int i = ((blk - PREP_BLK) * 256 + tid) * 4;
        float4 v = *(const float4*)(x + i);
        *(__half2*)(x16 + i)     = __floats2half2_rn(v.x, v.y);
        *(__half2*)(x16 + i + 2) = __floats2half2_rn(v.z, v.w);
    } else if (blk < PREP_BLK + X2H_BLK + IM2_BLK) {
        int o = (blk - PREP_BLK - X2H_BLK) * 256 + tid;
        if (o >= IM2_N) return;
        int row = o / 192, t = o - row * 192;
        int b = row / 196, i2 = row - b * 196;
        int jdx = 4 * i2 + 3;
        int ph = jdx / 28, pw = jdx - ph * 28;
        int pos = t / 3, c = t - pos * 3;
        int pi = pos >> 3, pj = pos & 7;
        T2[o] = __float2half_rn(
            x[(size_t)b * 150528 + (size_t)c * 50176 +
              (size_t)(ph * 8 + pi) * 224 + pw * 8 + pj]);
    } else {
        int b = blk - (PREP_BLK + X2H_BLK + IM2_BLK);
        int e = tid;
        z[((size_t)b * NTOK + 0)   * EMB_ + e] = cls2[e];
        z[((size_t)b * NTOK + 197) * EMB_ + e] = cls1[e];
    }
}

// ---------------- fused patch-embed GEMM --------------------------------------
__global__ __launch_bounds__(256, 2)
void gemm_pe(const __half* __restrict__ x, const __half* __restrict__ T2,
             const __half* __restrict__ W1p, const __half* __restrict__ W2p,
             const float* __restrict__ b1, const float* __restrict__ b2,
             float* __restrict__ z) {
    extern __shared__ __half smem[];
    __half* As = smem;
    __half* Bs = smem + 3 * A_STG;
    int tid = threadIdx.x;
    int bn = blockIdx.x * 128;
    int wid = tid >> 5, lane = tid & 31;
    int wm = wid & 3, wn = wid >> 2;
    int gid = lane >> 2, tg = lane & 3;
    unsigned AsU0 = (unsigned)__cvta_generic_to_shared(As);
    unsigned BsU0 = (unsigned)__cvta_generic_to_shared(Bs);
    int la7 = lane & 7;
    unsigned aoff = ((unsigned)((wm * 32) + la7 + ((lane >> 3) & 1) * 8) * ASTRH
                     + (lane >> 4) * 8) * 2;
    unsigned boff = ((unsigned)((wn * 64) + la7) * BSTR + ((lane >> 3) & 1) * 8) * 2;

    if (blockIdx.y < 196) {
        // ===== pe1: K=768, implicit im2col from x16 =====
        int bm = blockIdx.y * 128;
        size_t rowb[2];
#pragma unroll
        for (int i = 0; i < 2; i++) {
            int m = bm + (tid >> 2) + i * 64;
            int b = m / 196, j = m % 196;
            int ph = j / 14, pw = j % 14;
            rowb[i] = (size_t)b * 150528 + (size_t)(ph * 16) * 224 + pw * 16;
        }
        int ch = tid & 3;
        int pj0 = (ch & 1) * 8, gsel = ch >> 1;

        auto loadA = [&](int s, int k0) {
            __half* dst = As + s * A_STG;
            int gidx = (k0 >> 4) + gsel;
            int c = gidx >> 4, pi = gidx & 15;
            size_t off = (size_t)c * 50176 + pi * 224 + pj0;
#pragma unroll
            for (int i = 0; i < 2; i++) {
                int row = (tid >> 2) + i * 64;
                cpa16(dst + row * ASTRH + ch * 8, x + rowb[i] + off, true);
            }
        };
        auto loadB = [&](int s, int k0) {
            __half* dst = Bs + s * B_STG;
#pragma unroll
            for (int i = 0; i < 2; i++) {
                int idx = tid + i * 256;
                int row = idx >> 2, cc = (idx & 3) << 3;
                cpa16(dst + row * BSTR + cc, W1p + (size_t)(bn + row) * 768 + k0 + cc, true);
            }
        };

        float acc[2][8][4] = {};
        const int nk = 768 / KC;
        loadA(0, 0); loadB(0, 0); cpa_commit();
        loadA(1, KC); loadB(1, KC); cpa_commit();
        for (int it = 0; it < nk; it++) {
            cpa_wait<1>(); __syncthreads();
            if (it + 2 < nk) { loadA((it + 2) % 3, (it + 2) * KC); loadB((it + 2) % 3, (it + 2) * KC); }
            cpa_commit();
            unsigned AsU = AsU0 + (it % 3) * (A_STG * 2) + aoff;
            unsigned BsU = BsU0 + (it % 3) * (B_STG * 2) + boff;
#pragma unroll
            for (int kk2 = 0; kk2 < 2; kk2++) {
                unsigned af[2][4];
                ldm_x4(af[0], AsU + kk2 * 32);
                ldm_x4(af[1], AsU + 16 * ASTRH * 2 + kk2 * 32);
                unsigned bfk[8][2];
#pragma unroll
                for (int nt = 0; nt < 8; nt++)
                    ldm_x2(bfk[nt], BsU + nt * 8 * BSTR * 2 + kk2 * 32);
#pragma unroll
                for (int mt = 0; mt < 2; mt++)
#pragma unroll
                    for (int nt = 0; nt < 8; nt++)
                        mma16(acc[mt][nt], af[mt], bfk[nt]);
            }
        }
#pragma unroll
        for (int mt = 0; mt < 2; mt++)
#pragma unroll
            for (int nt = 0; nt < 8; nt++) {
                int n = bn + wn * 64 + nt * 8 + tg * 2;
                float bv0 = b1[n], bv1 = b1[n + 1];
#pragma unroll
                for (int half_ = 0; half_ < 2; half_++) {
                    int m = bm + wm * 32 + mt * 16 + gid + half_ * 8;
                    int b = m / 196, jj = m % 196;
                    *(float2*)&z[((size_t)b * NTOK + 198 + jj) * EMB_ + n] =
                        make_float2(acc[mt][nt][half_ * 2] + bv0,
                                    acc[mt][nt][half_ * 2 + 1] + bv1);
                }
            }
    } else {
        // ===== pe2: K=192, A = T2 =====
        int bm = (blockIdx.y - 196) * 128;
        auto loadA = [&](int s, int k0) {
            __half* dst = As + s * A_STG;
#pragma unroll
            for (int i = 0; i < 2; i++) {
                int idx = tid + i * 256;
                int row = idx >> 2, cc = (idx & 3) << 3;
                cpa16(dst + row * ASTRH + cc, T2 + (size_t)(bm + row) * 192 + k0 + cc, true);
            }
        };
        auto loadB = [&](int s, int k0) {
            __half* dst = Bs + s * B_STG;
#pragma unroll
            for (int i = 0; i < 2; i++) {
                int idx = tid + i * 256;
                int row = idx >> 2, cc = (idx & 3) << 3;
                cpa16(dst + row * BSTR + cc, W2p + (size_t)(bn + row) * 192 + k0 + cc, true);
            }
        };

        float acc[2][8][4] = {};
        const int nk = 192 / KC;
        loadA(0, 0); loadB(0, 0); cpa_commit();
        loadA(1, KC); loadB(1, KC); cpa_commit();
        for (int it = 0; it < nk; it++) {
            cpa_wait<1>(); __syncthreads();
            if (it + 2 < nk) { loadA((it + 2) % 3, (it + 2) * KC); loadB((it + 2) % 3, (it + 2) * KC); }
            cpa_commit();
            unsigned AsU = AsU0 + (it % 3) * (A_STG * 2) + aoff;
            unsigned BsU = BsU0 + (it % 3) * (B_STG * 2) + boff;
#pragma unroll
            for (int kk2 = 0; kk2 < 2; kk2++) {
                unsigned af[2][4];
                ldm_x4(af[0], AsU + kk2 * 32);
                ldm_x4(af[1], AsU + 16 * ASTRH * 2 + kk2 * 32);
                unsigned bfk[8][2];
#pragma unroll
                for (int nt = 0; nt < 8; nt++)
                    ldm_x2(bfk[nt], BsU + nt * 8 * BSTR * 2 + kk2 * 32);
#pragma unroll
                for (int mt = 0; mt < 2; mt++)
#pragma unroll
                    for (int nt = 0; nt < 8; nt++)
                        mma16(acc[mt][nt], af[mt], bfk[nt]);
            }
        }
#pragma unroll
        for (int mt = 0; mt < 2; mt++)
#pragma unroll
            for (int nt = 0; nt < 8; nt++) {
                int n = bn + wn * 64 + nt * 8 + tg * 2;
                float bv0 = b2[n], bv1 = b2[n + 1];
#pragma unroll
                for (int half_ = 0; half_ < 2; half_++) {
                    int m = bm + wm * 32 + mt * 16 + gid + half_ * 8;
                    int b = m / 196, jj = m % 196;
                    *(float2*)&z[((size_t)b * NTOK + 1 + jj) * EMB_ + n] =
                        make_float2(acc[mt][nt][half_ * 2] + bv0,
                                    acc[mt][nt][half_ * 2 + 1] + bv1);
                }
            }
    }
}

// ---------------- NN GEMM fp16 (ldmatrix): modes 0 (proj), 5 (qkv) -----------
__global__ __launch_bounds__(256, 2)
void gemm_nn(const __half* __restrict__ A, const __half* __restrict__ Bm,
             const float* __restrict__ bias, void* __restrict__ Cout,
             int N, int K, int mode) {
    extern __shared__ __half smem[];
    __half* As = smem;
    __half* Bs = smem + 3 * A_STG;
    int tid = threadIdx.x;
    int bm = blockIdx.y * 128, bn = blockIdx.x * 128;
    int wid = tid >> 5, lane = tid & 31;
    int wm = wid & 3, wn = wid >> 2;
    int gid = lane >> 2, tg = lane & 3;
    unsigned AsU0 = (unsigned)__cvta_generic_to_shared(As);
    unsigned BsU0 = (unsigned)__cvta_generic_to_shared(Bs);
    int la7 = lane & 7;
    unsigned aoff = ((unsigned)((wm * 32) + la7 + ((lane >> 3) & 1) * 8) * ASTRH
                     + (lane >> 4) * 8) * 2;
    unsigned boff = ((unsigned)((wn * 64) + la7) * BSTR + ((lane >> 3) & 1) * 8) * 2;

    auto loadA = [&](int s, int k0) {
        __half* dst = As + s * A_STG;
#pragma unroll
        for (int i = 0; i < 2; i++) {
            int idx = tid + i * 256;
            int row = idx >> 2, cc = (idx & 3) << 3;
            cpa16(dst + row * ASTRH + cc, A + (size_t)(bm + row) * K + k0 + cc, true);
        }
    };
    auto loadB = [&](int s, int k0) {
        __half* dst = Bs + s * B_STG;
#pragma unroll
        for (int i = 0; i < 2; i++) {
            int idx = tid + i * 256;
            int row = idx >> 2, cc = (idx & 3) << 3;
            cpa16(dst + row * BSTR + cc, Bm + (size_t)(bn + row) * K + k0 + cc, true);
        }
    };

    float acc[2][8][4] = {};
    int nk = K / KC;
    loadA(0, 0); loadB(0, 0); cpa_commit();
    loadA(1, KC); loadB(1, KC); cpa_commit();

    for (int it = 0; it < nk; it++) {
        cpa_wait<1>(); __syncthreads();
        if (it + 2 < nk) { loadA((it + 2) % 3, (it + 2) * KC); loadB((it + 2) % 3, (it + 2) * KC); }
        cpa_commit();
        unsigned AsU = AsU0 + (it % 3) * (A_STG * 2) + aoff;
        unsigned BsU = BsU0 + (it % 3) * (B_STG * 2) + boff;
#pragma unroll
        for (int kk2 = 0; kk2 < 2; kk2++) {
            unsigned af[2][4];
            ldm_x4(af[0], AsU + kk2 * 32);
            ldm_x4(af[1], AsU + 16 * ASTRH * 2 + kk2 * 32);
            unsigned bfk[8][2];
#pragma unroll
            for (int nt = 0; nt < 8; nt++)
                ldm_x2(bfk[nt], BsU + nt * 8 * BSTR * 2 + kk2 * 32);
#pragma unroll
            for (int mt = 0; mt < 2; mt++)
#pragma unroll
                for (int nt = 0; nt < 8; nt++)
                    mma16(acc[mt][nt], af[mt], bfk[nt]);
        }
    }

#pragma unroll
    for (int mt = 0; mt < 2; mt++) {
#pragma unroll
        for (int nt = 0; nt < 8; nt++) {
            int n = bn + wn * 64 + nt * 8 + tg * 2;
            float bv0 = bias ? bias[n] : 0.f;
            float bv1 = bias ? bias[n + 1] : 0.f;
#pragma unroll
            for (int half_ = 0; half_ < 2; half_++) {
                int m = bm + wm * 32 + mt * 16 + gid + half_ * 8;
                float v0 = acc[mt][nt][half_ * 2 + 0] + bv0;
                float v1 = acc[mt][nt][half_ * 2 + 1] + bv1;
                if (mode == 0) {
                    *(float2*)&((float*)Cout)[(size_t)m * 256 + n] = make_float2(v0, v1);
                } else {
                    int b = m / NTOK, t = m % NTOK;
                    int which = n >> 8, d2 = n & 255;
                    int hh = d2 >> 7, dd = d2 & 127;
                    int bh = b * 2 + hh;
                    __half* base = (__half*)Cout;
                    if (which < 2) {
                        __half2 hv = __floats2half2_rn(v0, v1);
                        *(__half2*)&base[(size_t)which * QKV_SZ +
                                         ((size_t)bh * 394 + t) * 128 + dd] = hv;
                    } else {
                        __half* vdst = base + 2 * QKV_SZ +
                                       ((size_t)bh * 197 + (t >> 1)) * 256 + dd * 2 + (t & 1);
                        vdst[0] = __float2half_rn(v0);
                        vdst[2] = __float2half_rn(v1);
                    }
                }
            }
        }
    }
}

// ---------------- flash attention fp16 (unchanged) ---------------------------
__global__ __launch_bounds__(256)
void flash_attn(const __half* __restrict__ qkv, __half* __restrict__ Og) {
    extern __shared__ __half smem[];
    __half* Qs = smem;
    __half* Ks = Qs + 128 * 136;
    __half* Vs = Ks + 2 * 64 * 136;
    int tid = threadIdx.x, lane = tid & 31, wid = tid >> 5;
    int gid = lane >> 2, tg = lane & 3;
    int qt = blockIdx.x, bh = blockIdx.y;
    const __half* Qb = qkv + (size_t)bh * 394 * 128;
    const __half* Kb = qkv + QKV_SZ + (size_t)bh * 394 * 128;
    const __half* Vb = qkv + 2 * QKV_SZ + (size_t)bh * 197 * 256;
    __half* Ob = Og + (size_t)(bh >> 1) * NTOK * EMB_ + (bh & 1) * 128;
    int qbase = qt * 128;
    int r0 = wid * 16 + gid;

    auto loadQ = [&]() {
#pragma unroll
        for (int i = 0; i < 8; i++) {
            int idx = tid + i * 256; int row = idx >> 4; int cc = (idx & 15) << 3;
            int gr = qbase + row; if (gr >= 394) gr = 0;
            cpa16(Qs + row * 136 + cc, Qb + (size_t)gr * 128 + cc, true);
        }
    };
    auto loadK = [&](int st, int kt) {
        __half* dst = Ks + st * 64 * 136;
#pragma unroll
        for (int i = 0; i < 4; i++) {
            int idx = tid + i * 256; int row = idx >> 4; int cc = (idx & 15) << 3;
            int gr = kt * 64 + row; if (gr >= 394) gr = 0;
            cpa16(dst + row * 136 + cc, Kb + (size_t)gr * 128 + cc, true);
        }
    };
    auto loadV = [&](int st, int kt) {
        __half* dst = Vs + st * 32 * 272;
#pragma unroll
        for (int i = 0; i < 4; i++) {
            int idx = tid + i * 256; int row = idx >> 5; int cc = (idx & 31) << 3;
            int gp = kt * 32 + row; if (gp >= 197) gp = 0;
            cpa16(dst + row * 272 + cc, Vb + (size_t)gp * 256 + cc, true);
        }
    };

    loadQ(); loadK(0, 0); loadV(0, 0); cpa_commit();
    loadK(1, 1); loadV(1, 1); cpa_commit();

    float accO[16][4] = {};
    float m0 = -1e30f, m1 = -1e30f, l0 = 0.f, l1 = 0.f;

    for (int kt = 0; kt < FA_NKT; kt++) {
        int st = kt & 1;
        cpa_wait<1>();
        __syncthreads();

        float accS[8][4] = {};
        {
            const unsigned* Qu = (const unsigned*)Qs;
            const unsigned* Ku = (const unsigned*)(Ks + st * 64 * 136);
#pragma unroll
            for (int j = 0; j < 8; j++) {
                unsigned af[4];
                af[0] = Qu[r0 * 68 + j * 8 + tg];
                af[1] = Qu[(r0 + 8) * 68 + j * 8 + tg];
                af[2] = Qu[r0 * 68 + j * 8 + tg + 4];
                af[3] = Qu[(r0 + 8) * 68 + j * 8 + tg + 4];
#pragma unroll
                for (int nt = 0; nt < 8; nt++) {
                    int kv = nt * 8 + gid;
                    unsigned bf[2];
                    bf[0] = Ku[kv * 68 + j * 8 + tg];
                    bf[1] = Ku[kv * 68 + j * 8 + tg + 4];
                    mma16(accS[nt], af, bf);
                }
            }
        }
        int cb = kt * 64 + tg * 2;
#pragma unroll
        for (int nt = 0; nt < 8; nt++) {
            int c0 = cb + nt * 8;
            if (c0 >= 394)     { accS[nt][0] = -1e30f; accS[nt][2] = -1e30f; }
            if (c0 + 1 >= 394) { accS[nt][1] = -1e30f; accS[nt][3] = -1e30f; }
        }
        float rm0 = -1e30f, rm1 = -1e30f;
#pragma unroll
        for (int nt = 0; nt < 8; nt++) {
            rm0 = fmaxf(rm0, fmaxf(accS[nt][0], accS[nt][1]));
            rm1 = fmaxf(rm1, fmaxf(accS[nt][2], accS[nt][3]));
        }
        rm0 = fmaxf(rm0, __shfl_xor_sync(0xffffffffu, rm0, 1));
        rm0 = fmaxf(rm0, __shfl_xor_sync(0xffffffffu, rm0, 2));
        rm1 = fmaxf(rm1, __shfl_xor_sync(0xffffffffu, rm1, 1));
        rm1 = fmaxf(rm1, __shfl_xor_sync(0xffffffffu, rm1, 2));
        float mn0 = fmaxf(m0, rm0), mn1 = fmaxf(m1, rm1);
        float sc0 = __expf(m0 - mn0), sc1 = __expf(m1 - mn1);
        float rs0 = 0.f, rs1 = 0.f;
#pragma unroll
        for (int nt = 0; nt < 8; nt++) {
            accS[nt][0] = __expf(accS[nt][0] - mn0);
            accS[nt][1] = __expf(accS[nt][1] - mn0);
            accS[nt][2] = __expf(accS[nt][2] - mn1);
            accS[nt][3] = __expf(accS[nt][3] - mn1);
            rs0 += accS[nt][0] + accS[nt][1];
            rs1 += accS[nt][2] + accS[nt][3];
        }
        rs0 += __shfl_xor_sync(0xffffffffu, rs0, 1);
        rs0 += __shfl_xor_sync(0xffffffffu, rs0, 2);
        rs1 += __shfl_xor_sync(0xffffffffu, rs1, 1);
        rs1 += __shfl_xor_sync(0xffffffffu, rs1, 2);
        l0 = l0 * sc0 + rs0;  l1 = l1 * sc1 + rs1;
        m0 = mn0;  m1 = mn1;
#pragma unroll
        for (int nt = 0; nt < 16; nt++) {
            accO[nt][0] *= sc0; accO[nt][1] *= sc0;
            accO[nt][2] *= sc1; accO[nt][3] *= sc1;
        }
        {
            const unsigned* Vu = (const unsigned*)(Vs + st * 32 * 272);
#pragma unroll
            for (int j2 = 0; j2 < 4; j2++) {
                unsigned a[4];
                a[0] = pack2(accS[2 * j2][0],     accS[2 * j2][1]);
                a[1] = pack2(accS[2 * j2][2],     accS[2 * j2][3]);
                a[2] = pack2(accS[2 * j2 + 1][0], accS[2 * j2 + 1][1]);
                a[3] = pack2(accS[2 * j2 + 1][2], accS[2 * j2 + 1][3]);
#pragma unroll
                for (int nt = 0; nt < 16; nt++) {
                    int n = nt * 8 + gid;
                    unsigned bf[2];
                    bf[0] = Vu[(8 * j2 + tg) * 136 + n];
                    bf[1] = Vu[(8 * j2 + tg + 4) * 136 + n];
                    mma16(accO[nt], a, bf);
                }
            }
        }
        __syncthreads();
        if (kt + 2 < FA_NKT) { loadK(st, kt + 2); loadV(st, kt + 2); }
        cpa_commit();
    }

    float inv0 = 1.f / (l0 * 16.f), inv1 = 1.f / (l1 * 16.f);
    int gr0 = qbase + r0, gr1 = gr0 + 8;
#pragma unroll
    for (int nt = 0; nt < 16; nt++) {
        int col = nt * 8 + tg * 2;
        if (gr0 < 394)
            *(__half2*)&Ob[(size_t)gr0 * EMB_ + col] =
                __floats2half2_rn(accO[nt][0] * inv0, accO[nt][1] * inv0);
        if (gr1 < 394)
            *(__half2*)&Ob[(size_t)gr1 * EMB_ + col] =
                __floats2half2_rn(accO[nt][2] * inv1, accO[nt][3] * inv1);
    }
}

// ---------------- ln1: warp-per-token -----------------------------------------
__global__ __launch_bounds__(256)
void ln1_kernel(const float* __restrict__ in, const float* __restrict__ g,
                const float* __restrict__ b, __half* __restrict__ out) {
    int warp = threadIdx.x >> 5, lane = threadIdx.x & 31;
    int r = blockIdx.x * 8 + warp;
    const float* row = in + (size_t)r * EMB_ + lane * 8;
    float4 v0 = *(const float4*)row;
    float4 v1 = *(const float4*)(row + 4);
    float v[8] = {v0.x, v0.y, v0.z, v0.w, v1.x, v1.y, v1.z, v1.w};
    float s = 0.f, s2 = 0.f;
#pragma unroll
    for (int i = 0; i < 8; i++) { s += v[i]; s2 += v[i] * v[i]; }
#pragma unroll
    for (int off = 16; off > 0; off >>= 1) {
        s  += __shfl_xor_sync(0xffffffffu, s,  off);
        s2 += __shfl_xor_sync(0xffffffffu, s2, off);
    }
    float mean = s * (1.f / EMB_);
    float rstd = rsqrtf(s2 * (1.f / EMB_) - mean * mean + 1e-5f);
    float4 g0 = *(const float4*)(g + lane * 8);
    float4 g1 = *(const float4*)(g + lane * 8 + 4);
    float4 b0 = *(const float4*)(b + lane * 8);
    float4 b1 = *(const float4*)(b + lane * 8 + 4);
    float gg[8] = {g0.x, g0.y, g0.z, g0.w, g1.x, g1.y, g1.z, g1.w};
    float bb[8] = {b0.x, b0.y, b0.z, b0.w, b1.x, b1.y, b1.z, b1.w};
    __half2 h[4];
#pragma unroll
    for (int i = 0; i < 4; i++) {
        float n0 = (v[2 * i]     - mean) * rstd * gg[2 * i]     + bb[2 * i];
        float n1 = (v[2 * i + 1] - mean) * rstd * gg[2 * i + 1] + bb[2 * i + 1];
        h[i] = __floats2half2_rn(n0, n1);
    }
    *(uint4*)(out + (size_t)r * EMB_ + lane * 8) = *(uint4*)h;
}

// ---- ln2 + residual + pool partial -------------------------------------------
__global__ __launch_bounds__(256)
void ln2_pool(const float* __restrict__ h, const float* __restrict__ g,
              const float* __restrict__ bb, const float* __restrict__ z,
              float* __restrict__ pool) {
    int b = blockIdx.x, seg = blockIdx.y;
    int warp = threadIdx.x >> 5, lane = threadIdx.x & 31;
    int t0 = seg * 50, t1 = t0 + 50; if (t1 > NTOK) t1 = NTOK;
    float4 g0 = *(const float4*)(g + lane * 8);
    float4 g1 = *(const float4*)(g + lane * 8 + 4);
    float4 bv0 = *(const float4*)(bb + lane * 8);
    float4 bv1 = *(const float4*)(bb + lane * 8 + 4);
    float gg[8] = {g0.x, g0.y, g0.z, g0.w, g1.x, g1.y, g1.z, g1.w};
    float be[8] = {bv0.x, bv0.y, bv0.z, bv0.w, bv1.x, bv1.y, bv1.z, bv1.w};
    float accp[8] = {};
    for (int t = t0 + warp; t < t1; t += 8) {
        size_t base = ((size_t)b * NTOK + t) * EMB_ + lane * 8;
        float4 v0 = *(const float4*)(h + base);
        float4 v1 = *(const float4*)(h + base + 4);
        float v[8] = {v0.x, v0.y, v0.z, v0.w, v1.x, v1.y, v1.z, v1.w};
        float s = 0.f, s2 = 0.f;
#pragma unroll
        for (int i = 0; i < 8; i++) { s += v[i]; s2 += v[i] * v[i]; }
#pragma unroll
        for (int off = 16; off > 0; off >>= 1) {
            s  += __shfl_xor_sync(0xffffffffu, s,  off);
            s2 += __shfl_xor_sync(0xffffffffu, s2, off);
        }
        float mean = s * (1.f / EMB_);
        float rstd = rsqrtf(s2 * (1.f / EMB_) - mean * mean + 1e-5f);
        float4 z0 = *(const float4*)(z + base);
        float4 z1 = *(const float4*)(z + base + 4);
        float zv[8] = {z0.x, z0.y, z0.z, z0.w, z1.x, z1.y, z1.z, z1.w};
#pragma unroll
        for (int i = 0; i < 8; i++)
            accp[i] += zv[i] + (v[i] - mean) * rstd * gg[i] + be[i];
    }
    __shared__ float sm[8][256];
#pragma unroll
    for (int i = 0; i < 8; i++) sm[warp][lane * 8 + i] = accp[i];
    __syncthreads();
    int e = threadIdx.x;
    float tot = 0.f;
#pragma unroll
    for (int w = 0; w < 8; w++) tot += sm[w][e];
    pool[((size_t)b * 8 + seg) * EMB_ + e] = tot;
}

// ---------------- head ----------------------------------------------------------
__global__ __launch_bounds__(256)
void head_kernel(const float* __restrict__ pool, const float* __restrict__ g,
                 const float* __restrict__ bb, const float* __restrict__ Wc,
                 const float* __restrict__ bc, float* __restrict__ out) {
    int b = blockIdx.x, e = threadIdx.x;
    float s = 0.f;
#pragma unroll
    for (int i = 0; i < 8; i++) s += pool[((size_t)b * 8 + i) * EMB_ + e];
    float pooled = s * (1.f / NTOK);
    __shared__ float red[256];
    red[e] = pooled; __syncthreads();
    for (int st = 128; st > 0; st >>= 1) { if (e < st) red[e] += red[e + st]; __syncthreads(); }
    float mean = red[0] * (1.f / EMB_);
    __syncthreads();
    float d = pooled - mean;
    red[e] = d * d; __syncthreads();
    for (int st = 128; st > 0; st >>= 1) { if (e < st) red[e] += red[e + st]; __syncthreads(); }
    float var = red[0] * (1.f / EMB_);
    __syncthreads();
    float nv = d * rsqrtf(var + 1e-5f) * g[e] + bb[e];
    red[e] = nv * Wc[e * 2 + 0]; __syncthreads();
    for (int st = 128; st > 0; st >>= 1) { if (e < st) red[e] += red[e + st]; __syncthreads(); }
    float l0 = red[0] + bc[0];
    __syncthreads();
    red[e] = nv * Wc[e * 2 + 1]; __syncthreads();
    for (int st = 128; st > 0; st >>= 1) { if (e < st) red[e] += red[e + st]; __syncthreads(); }
    float l1 = red[0] + bc[1];
    if (e == 0) {
        float mx = fmaxf(l0, l1);
        float lse = mx + logf(expf(l0 - mx) + expf(l1 - mx));
        out[b * 2 + 0] = l0 - lse;
        out[b * 2 + 1] = l1 - lse;
    }
}

// ---------------- launch ----------------------------------------------------------
extern "C" void kernel_launch(void* const* d_in, const int* in_sizes, int n_in,
                              void* d_out, int out_size) {
    const float* x     = (const float*)d_in[0];
    const float* W1    = (const float*)d_in[1];
    const float* b1    = (const float*)d_in[2];
    const float* cls1  = (const float*)d_in[3];
    const float* W2    = (const float*)d_in[4];
    const float* b2    = (const float*)d_in[5];
    const float* cls2  = (const float*)d_in[6];
    const float* ln1_g = (const float*)d_in[7];
    const float* ln1_b = (const float*)d_in[8];
    const float* Wq    = (const float*)d_in[9];
    const float* bq    = (const float*)d_in[10];
    const float* Wk    = (const float*)d_in[11];
    const float* bk    = (const float*)d_in[12];
    const float* Wv    = (const float*)d_in[13];
    const float* bv    = (const float*)d_in[14];
    const float* Wp    = (const float*)d_in[15];
    const float* bp    = (const float*)d_in[16];
    const float* ln2_g = (const float*)d_in[17];
    const float* ln2_b = (const float*)d_in[18];
    const float* lnc_g = (const float*)d_in[19];
    const float* lnc_b = (const float*)d_in[20];
    const float* Wc    = (const float*)d_in[21];
    const float* bc    = (const float*)d_in[22];
    float* out = (float*)d_out;

    static int inited = 0;
    if (!inited) {
        cudaFuncSetAttribute(gemm_nn, cudaFuncAttributeMaxDynamicSharedMemorySize, SMEM_NN);
        cudaFuncSetAttribute(gemm_pe, cudaFuncAttributeMaxDynamicSharedMemorySize, SMEM_NN);
        cudaFuncSetAttribute(flash_attn, cudaFuncAttributeMaxDynamicSharedMemorySize, FA_SMEM);
        inited = 1;
    }

    __half *x16, *T2, *Wt, *h16, *qkv, *o16;
    float *bqkv, *z, *hf, *pool;
    cudaGetSymbolAddress((void**)&x16, g_x16);
    cudaGetSymbolAddress((void**)&T2,  g_T2);
    cudaGetSymbolAddress((void**)&Wt,  g_Wt);
    cudaGetSymbolAddress((void**)&bqkv, g_bqkv);
    cudaGetSymbolAddress((void**)&z,   g_z);
    cudaGetSymbolAddress((void**)&h16, g_h16);
    cudaGetSymbolAddress((void**)&hf,  g_hf);
    cudaGetSymbolAddress((void**)&qkv, g_qkv);
    cudaGetSymbolAddress((void**)&o16, g_o16);
    cudaGetSymbolAddress((void**)&pool, g_pool);

    prep_all<<<ALL_BLK, 256>>>(x, W1, W2, Wq, Wk, Wv, Wp, bq, bk, bv,
                               cls1, cls2, x16, T2, Wt, bqkv, z);

    gemm_pe<<<dim3(2, 392), 256, SMEM_NN>>>(x16, T2, Wt + OFF_W1P, Wt + OFF_W2, b1, b2, z);

    ln1_kernel<<<MTOK / 8, 256>>>(z, ln1_g, ln1_b, h16);

    gemm_nn<<<dim3(6, 394), 256, SMEM_NN>>>(h16, Wt + OFF_WQKV, bqkv, qkv, 768, 256, 5);

    flash_attn<<<dim3(4, 256), 256, FA_SMEM>>>(qkv, o16);

    gemm_nn<<<dim3(2, 394), 256, SMEM_NN>>>(o16, Wt + OFF_WP, bp, hf, 256, 256, 0);

    ln2_pool<<<dim3(B_, 8), 256>>>(hf, ln2_g, ln2_b, z, pool);
    head_kernel<<<B_, 256>>>(pool, lnc_g, lnc_b, Wc, bc, out);
}

// round 17
// speedup vs baseline: 2.0654x; 1.0035x over previous
#include <cuda_runtime.h>
#include <cuda_fp16.h>
#include <math.h>

#define B_      128
#define EMB_    256
#define NTOK    394
#define MTOK    (B_ * 394)           // 50432
#define MPE     (B_ * 196)           // 25088
#define XN      (B_ * 3 * 224 * 224) // 19267584

// ---- gemm_pe tiling (KC=32, 3-stage) ----
#define KC      32
#define ASTRH   40
#define BSTR    40
#define A_STG   (128 * ASTRH)
#define B_STG   (128 * BSTR)
#define SMEM_PE ((3 * (A_STG + B_STG)) * 2)   // 61440 B

// ---- gemm_nn tiling (KC=64, 2-stage) ----
#define NKC     64
#define NSTR    72
#define N_STG   (128 * NSTR)                  // 9216 halfs
#define SMEM_NN ((2 * (2 * N_STG)) * 2)       // 73728 B

#define FA_SMEM (128*136*2 + 2*64*136*2 + 2*32*136*4)  // 104448
#define FA_NKT  7
#define QKV_SZ  ((size_t)B_ * 2 * 394 * 128)

// ---------------- scratch ---------------------------------------------------
__device__ __half g_x16[XN];
__device__ __half g_T2[MPE * 192];
__device__ __half g_Wt[507904];      // W2 | Wp | W1perm | Wqkv, n-major [N][K]
__device__ float  g_bqkv[768];
__device__ float  g_z [MTOK * EMB_];
__device__ __half g_h16[MTOK * EMB_];
__device__ float  g_hf[MTOK * EMB_];
__device__ __half g_qkv[3 * QKV_SZ];
__device__ __half g_o16[MTOK * EMB_];
__device__ float  g_pool[B_ * 8 * EMB_];

#define OFF_W2   0
#define OFF_WP   49152
#define OFF_W1P  114688
#define OFF_WQKV 311296
#define PREP_N   508672

#define PREP_BLK 1987
#define X2H_BLK  18816
#define IM2_BLK  18816
#define IM2_N    (MPE * 192)
#define ALL_BLK  (PREP_BLK + X2H_BLK + IM2_BLK + B_)

// ---------------- helpers ----------------------------------------------------
__device__ __forceinline__ void mma16(float* acc, const unsigned* a, const unsigned* b) {
    asm volatile(
        "mma.sync.aligned.m16n8k16.row.col.f32.f16.f16.f32 "
        "{%0,%1,%2,%3}, {%4,%5,%6,%7}, {%8,%9}, {%0,%1,%2,%3};\n"
        : "+f"(acc[0]), "+f"(acc[1]), "+f"(acc[2]), "+f"(acc[3])
        : "r"(a[0]), "r"(a[1]), "r"(a[2]), "r"(a[3]), "r"(b[0]), "r"(b[1]));
}
__device__ __forceinline__ void ldm_x4(unsigned* r, unsigned addr) {
    asm volatile("ldmatrix.sync.aligned.m8n8.x4.shared.b16 {%0,%1,%2,%3}, [%4];"
                 : "=r"(r[0]), "=r"(r[1]), "=r"(r[2]), "=r"(r[3]) : "r"(addr));
}
__device__ __forceinline__ void ldm_x2(unsigned* r, unsigned addr) {
    asm volatile("ldmatrix.sync.aligned.m8n8.x2.shared.b16 {%0,%1}, [%2];"
                 : "=r"(r[0]), "=r"(r[1]) : "r"(addr));
}
__device__ __forceinline__ unsigned pack2(float a, float b) {
    __half2 h = __floats2half2_rn(a, b);
    return *reinterpret_cast<unsigned*>(&h);
}
__device__ __forceinline__ void cpa16(void* dst, const void* src, bool pred) {
    unsigned d = (unsigned)__cvta_generic_to_shared(dst);
    int sz = pred ? 16 : 0;
    asm volatile("cp.async.cg.shared.global [%0], [%1], 16, %2;\n"
                 :: "r"(d), "l"(src), "r"(sz));
}
__device__ __forceinline__ void cpa_commit() { asm volatile("cp.async.commit_group;\n"); }
template <int N>
__device__ __forceinline__ void cpa_wait() { asm volatile("cp.async.wait_group %0;\n" :: "n"(N)); }

// ---------------- fused preamble ----------------------------------------------
__global__ void prep_all(const float* __restrict__ x,
                         const float* __restrict__ W1, const float* __restrict__ W2,
                         const float* __restrict__ Wq, const float* __restrict__ Wk,
                         const float* __restrict__ Wv, const float* __restrict__ Wp,
                         const float* __restrict__ bq, const float* __restrict__ bk,
                         const float* __restrict__ bv,
                         const float* __restrict__ cls1, const float* __restrict__ cls2,
                         __half* __restrict__ x16, __half* __restrict__ T2,
                         __half* __restrict__ Wt, float* __restrict__ bqkv,
                         float* __restrict__ z) {
    int blk = blockIdx.x, tid = threadIdx.x;
    if (blk < PREP_BLK) {
        int i = blk * 256 + tid;
        if (i >= PREP_N) return;
        if (i >= 507904) {
            int j = i - 507904;
            int which = j >> 8, col = j & 255;
            const float* src = which == 0 ? bq : which == 1 ? bk : bv;
            bqkv[j] = src[col];
            return;
        }
        float v;
        if (i < OFF_WP) {                       // W2 n-major [256][192]
            int n = i / 192, k = i % 192;
            v = W2[k * 256 + n];
        } else if (i < OFF_W1P) {               // Wp n-major [256][256]
            int idx = i - OFF_WP;
            int n = idx >> 8, k = idx & 255;
            v = Wp[k * 256 + n];
        } else if (i < OFF_WQKV) {              // W1 permuted, n-major [256][768]
            int idx = i - OFF_W1P;
            int n = idx / 768, kp = idx % 768;
            int c = kp >> 8, rem = kp & 255;
            int pi = rem >> 4, pj = rem & 15;
            v = W1[((pi * 16 + pj) * 3 + c) * 256 + n];
        } else {                                // Wqkv n-major [768][256]
            int idx = i - OFF_WQKV;
            int n = idx >> 8, k = idx & 255;
            int which = n >> 8, col = n & 255;
            const float* src = which == 0 ? Wq : which == 1 ? Wk : Wv;
            v = src[k * 256 + col];
        }
        Wt[i] = __float2half_rn(v);
    } else if (blk < PREP_BLK + X2H_BLK) {
        int i = ((blk - PREP_BLK) * 256 + tid) * 4;
        float4 v = *(const float4*)(x + i);
        *(__half2*)(x16 + i)     = __floats2half2_rn(v.x, v.y);
        *(__half2*)(x16 + i + 2) = __floats2half2_rn(v.z, v.w);
    } else if (blk < PREP_BLK + X2H_BLK + IM2_BLK) {
        int o = (blk - PREP_BLK - X2H_BLK) * 256 + tid;
        if (o >= IM2_N) return;
        int row = o / 192, t = o - row * 192;
        int b = row / 196, i2 = row - b * 196;
        int jdx = 4 * i2 + 3;
        int ph = jdx / 28, pw = jdx - ph * 28;
        int pos = t / 3, c = t - pos * 3;
        int pi = pos >> 3, pj = pos & 7;
        T2[o] = __float2half_rn(
            x[(size_t)b * 150528 + (size_t)c * 50176 +
              (size_t)(ph * 8 + pi) * 224 + pw * 8 + pj]);
    } else {
        int b = blk - (PREP_BLK + X2H_BLK + IM2_BLK);
        int e = tid;
        z[((size_t)b * NTOK + 0)   * EMB_ + e] = cls2[e];
        z[((size_t)b * NTOK + 197) * EMB_ + e] = cls1[e];
    }
}

// ---------------- fused patch-embed GEMM (KC=32, 3-stage, unchanged) ----------
__global__ __launch_bounds__(256, 2)
void gemm_pe(const __half* __restrict__ x, const __half* __restrict__ T2,
             const __half* __restrict__ W1p, const __half* __restrict__ W2p,
             const float* __restrict__ b1, const float* __restrict__ b2,
             float* __restrict__ z) {
    extern __shared__ __half smem[];
    __half* As = smem;
    __half* Bs = smem + 3 * A_STG;
    int tid = threadIdx.x;
    int bn = blockIdx.x * 128;
    int wid = tid >> 5, lane = tid & 31;
    int wm = wid & 3, wn = wid >> 2;
    int gid = lane >> 2, tg = lane & 3;
    unsigned AsU0 = (unsigned)__cvta_generic_to_shared(As);
    unsigned BsU0 = (unsigned)__cvta_generic_to_shared(Bs);
    int la7 = lane & 7;
    unsigned aoff = ((unsigned)((wm * 32) + la7 + ((lane >> 3) & 1) * 8) * ASTRH
                     + (lane >> 4) * 8) * 2;
    unsigned boff = ((unsigned)((wn * 64) + la7) * BSTR + ((lane >> 3) & 1) * 8) * 2;

    if (blockIdx.y < 196) {
        int bm = blockIdx.y * 128;
        size_t rowb[2];
#pragma unroll
        for (int i = 0; i < 2; i++) {
            int m = bm + (tid >> 2) + i * 64;
            int b = m / 196, j = m % 196;
            int ph = j / 14, pw = j % 14;
            rowb[i] = (size_t)b * 150528 + (size_t)(ph * 16) * 224 + pw * 16;
        }
        int ch = tid & 3;
        int pj0 = (ch & 1) * 8, gsel = ch >> 1;

        auto loadA = [&](int s, int k0) {
            __half* dst = As + s * A_STG;
            int gidx = (k0 >> 4) + gsel;
            int c = gidx >> 4, pi = gidx & 15;
            size_t off = (size_t)c * 50176 + pi * 224 + pj0;
#pragma unroll
            for (int i = 0; i < 2; i++) {
                int row = (tid >> 2) + i * 64;
                cpa16(dst + row * ASTRH + ch * 8, x + rowb[i] + off, true);
            }
        };
        auto loadB = [&](int s, int k0) {
            __half* dst = Bs + s * B_STG;
#pragma unroll
            for (int i = 0; i < 2; i++) {
                int idx = tid + i * 256;
                int row = idx >> 2, cc = (idx & 3) << 3;
                cpa16(dst + row * BSTR + cc, W1p + (size_t)(bn + row) * 768 + k0 + cc, true);
            }
        };

        float acc[2][8][4] = {};
        const int nk = 768 / KC;
        loadA(0, 0); loadB(0, 0); cpa_commit();
        loadA(1, KC); loadB(1, KC); cpa_commit();
        for (int it = 0; it < nk; it++) {
            cpa_wait<1>(); __syncthreads();
            if (it + 2 < nk) { loadA((it + 2) % 3, (it + 2) * KC); loadB((it + 2) % 3, (it + 2) * KC); }
            cpa_commit();
            unsigned AsU = AsU0 + (it % 3) * (A_STG * 2) + aoff;
            unsigned BsU = BsU0 + (it % 3) * (B_STG * 2) + boff;
#pragma unroll
            for (int kk2 = 0; kk2 < 2; kk2++) {
                unsigned af[2][4];
                ldm_x4(af[0], AsU + kk2 * 32);
                ldm_x4(af[1], AsU + 16 * ASTRH * 2 + kk2 * 32);
                unsigned bfk[8][2];
#pragma unroll
                for (int nt = 0; nt < 8; nt++)
                    ldm_x2(bfk[nt], BsU + nt * 8 * BSTR * 2 + kk2 * 32);
#pragma unroll
                for (int mt = 0; mt < 2; mt++)
#pragma unroll
                    for (int nt = 0; nt < 8; nt++)
                        mma16(acc[mt][nt], af[mt], bfk[nt]);
            }
        }
#pragma unroll
        for (int mt = 0; mt < 2; mt++)
#pragma unroll
            for (int nt = 0; nt < 8; nt++) {
                int n = bn + wn * 64 + nt * 8 + tg * 2;
                float bv0 = b1[n], bv1 = b1[n + 1];
#pragma unroll
                for (int half_ = 0; half_ < 2; half_++) {
                    int m = bm + wm * 32 + mt * 16 + gid + half_ * 8;
                    int b = m / 196, jj = m % 196;
                    *(float2*)&z[((size_t)b * NTOK + 198 + jj) * EMB_ + n] =
                        make_float2(acc[mt][nt][half_ * 2] + bv0,
                                    acc[mt][nt][half_ * 2 + 1] + bv1);
                }
            }
    } else {
        int bm = (blockIdx.y - 196) * 128;
        auto loadA = [&](int s, int k0) {
            __half* dst = As + s * A_STG;
#pragma unroll
            for (int i = 0; i < 2; i++) {
                int idx = tid + i * 256;
                int row = idx >> 2, cc = (idx & 3) << 3;
                cpa16(dst + row * ASTRH + cc, T2 + (size_t)(bm + row) * 192 + k0 + cc, true);
            }
        };
        auto loadB = [&](int s, int k0) {
            __half* dst = Bs + s * B_STG;
#pragma unroll
            for (int i = 0; i < 2; i++) {
                int idx = tid + i * 256;
                int row = idx >> 2, cc = (idx & 3) << 3;
                cpa16(dst + row * BSTR + cc, W2p + (size_t)(bn + row) * 192 + k0 + cc, true);
            }
        };

        float acc[2][8][4] = {};
        const int nk = 192 / KC;
        loadA(0, 0); loadB(0, 0); cpa_commit();
        loadA(1, KC); loadB(1, KC); cpa_commit();
        for (int it = 0; it < nk; it++) {
            cpa_wait<1>(); __syncthreads();
            if (it + 2 < nk) { loadA((it + 2) % 3, (it + 2) * KC); loadB((it + 2) % 3, (it + 2) * KC); }
            cpa_commit();
            unsigned AsU = AsU0 + (it % 3) * (A_STG * 2) + aoff;
            unsigned BsU = BsU0 + (it % 3) * (B_STG * 2) + boff;
#pragma unroll
            for (int kk2 = 0; kk2 < 2; kk2++) {
                unsigned af[2][4];
                ldm_x4(af[0], AsU + kk2 * 32);
                ldm_x4(af[1], AsU + 16 * ASTRH * 2 + kk2 * 32);
                unsigned bfk[8][2];
#pragma unroll
                for (int nt = 0; nt < 8; nt++)
                    ldm_x2(bfk[nt], BsU + nt * 8 * BSTR * 2 + kk2 * 32);
#pragma unroll
                for (int mt = 0; mt < 2; mt++)
#pragma unroll
                    for (int nt = 0; nt < 8; nt++)
                        mma16(acc[mt][nt], af[mt], bfk[nt]);
            }
        }
#pragma unroll
        for (int mt = 0; mt < 2; mt++)
#pragma unroll
            for (int nt = 0; nt < 8; nt++) {
                int n = bn + wn * 64 + nt * 8 + tg * 2;
                float bv0 = b2[n], bv1 = b2[n + 1];
#pragma unroll
                for (int half_ = 0; half_ < 2; half_++) {
                    int m = bm + wm * 32 + mt * 16 + gid + half_ * 8;
                    int b = m / 196, jj = m % 196;
                    *(float2*)&z[((size_t)b * NTOK + 1 + jj) * EMB_ + n] =
                        make_float2(acc[mt][nt][half_ * 2] + bv0,
                                    acc[mt][nt][half_ * 2 + 1] + bv1);
                }
            }
    }
}

// ---------------- NN GEMM fp16: KC=64, 2-stage --------------------------------
__global__ __launch_bounds__(256, 2)
void gemm_nn(const __half* __restrict__ A, const __half* __restrict__ Bm,
             const float* __restrict__ bias, void* __restrict__ Cout,
             int N, int K, int mode) {
    extern __shared__ __half smem[];
    __half* As = smem;                   // [2][128*NSTR]
    __half* Bs = smem + 2 * N_STG;       // [2][128*NSTR]
    int tid = threadIdx.x;
    int bm = blockIdx.y * 128, bn = blockIdx.x * 128;
    int wid = tid >> 5, lane = tid & 31;
    int wm = wid & 3, wn = wid >> 2;
    int gid = lane >> 2, tg = lane & 3;
    unsigned AsU0 = (unsigned)__cvta_generic_to_shared(As);
    unsigned BsU0 = (unsigned)__cvta_generic_to_shared(Bs);
    int la7 = lane & 7;
    unsigned aoff = ((unsigned)((wm * 32) + la7 + ((lane >> 3) & 1) * 8) * NSTR
                     + (lane >> 4) * 8) * 2;
    unsigned boff = ((unsigned)((wn * 64) + la7) * NSTR + ((lane >> 3) & 1) * 8) * 2;

    auto loadA = [&](int s, int k0) {
        __half* dst = As + s * N_STG;
#pragma unroll
        for (int i = 0; i < 4; i++) {
            int idx = tid + i * 256;
            int row = idx >> 3, cc = (idx & 7) << 3;
            cpa16(dst + row * NSTR + cc, A + (size_t)(bm + row) * K + k0 + cc, true);
        }
    };
    auto loadB = [&](int s, int k0) {
        __half* dst = Bs + s * N_STG;
#pragma unroll
        for (int i = 0; i < 4; i++) {
            int idx = tid + i * 256;
            int row = idx >> 3, cc = (idx & 7) << 3;
            cpa16(dst + row * NSTR + cc, Bm + (size_t)(bn + row) * K + k0 + cc, true);
        }
    };

    float acc[2][8][4] = {};
    int nk = K / NKC;
    loadA(0, 0); loadB(0, 0); cpa_commit();

    for (int it = 0; it < nk; it++) {
        cpa_wait<0>(); __syncthreads();
        if (it + 1 < nk) {
            loadA((it + 1) & 1, (it + 1) * NKC);
            loadB((it + 1) & 1, (it + 1) * NKC);
            cpa_commit();
        }
        unsigned AsU = AsU0 + (it & 1) * (N_STG * 2) + aoff;
        unsigned BsU = BsU0 + (it & 1) * (N_STG * 2) + boff;
#pragma unroll
        for (int kk2 = 0; kk2 < 4; kk2++) {
            unsigned af[2][4];
            ldm_x4(af[0], AsU + kk2 * 32);
            ldm_x4(af[1], AsU + 16 * NSTR * 2 + kk2 * 32);
            unsigned bfk[8][2];
#pragma unroll
            for (int nt = 0; nt < 8; nt++)
                ldm_x2(bfk[nt], BsU + nt * 8 * NSTR * 2 + kk2 * 32);
#pragma unroll
            for (int mt = 0; mt < 2; mt++)
#pragma unroll
                for (int nt = 0; nt < 8; nt++)
                    mma16(acc[mt][nt], af[mt], bfk[nt]);
        }
    }

#pragma unroll
    for (int mt = 0; mt < 2; mt++) {
#pragma unroll
        for (int nt = 0; nt < 8; nt++) {
            int n = bn + wn * 64 + nt * 8 + tg * 2;
            float bv0 = bias ? bias[n] : 0.f;
            float bv1 = bias ? bias[n + 1] : 0.f;
#pragma unroll
            for (int half_ = 0; half_ < 2; half_++) {
                int m = bm + wm * 32 + mt * 16 + gid + half_ * 8;
                float v0 = acc[mt][nt][half_ * 2 + 0] + bv0;
                float v1 = acc[mt][nt][half_ * 2 + 1] + bv1;
                if (mode == 0) {
                    *(float2*)&((float*)Cout)[(size_t)m * 256 + n] = make_float2(v0, v1);
                } else {
                    int b = m / NTOK, t = m % NTOK;
                    int which = n >> 8, d2 = n & 255;
                    int hh = d2 >> 7, dd = d2 & 127;
                    int bh = b * 2 + hh;
                    __half* base = (__half*)Cout;
                    if (which < 2) {
                        __half2 hv = __floats2half2_rn(v0, v1);
                        *(__half2*)&base[(size_t)which * QKV_SZ +
                                         ((size_t)bh * 394 + t) * 128 + dd] = hv;
                    } else {
                        __half* vdst = base + 2 * QKV_SZ +
                                       ((size_t)bh * 197 + (t >> 1)) * 256 + dd * 2 + (t & 1);
                        vdst[0] = __float2half_rn(v0);
                        vdst[2] = __float2half_rn(v1);
                    }
                }
            }
        }
    }
}

// ---------------- flash attention fp16 (now 2 CTAs/SM) ------------------------
__global__ __launch_bounds__(256, 2)
void flash_attn(const __half* __restrict__ qkv, __half* __restrict__ Og) {
    extern __shared__ __half smem[];
    __half* Qs = smem;
    __half* Ks = Qs + 128 * 136;
    __half* Vs = Ks + 2 * 64 * 136;
    int tid = threadIdx.x, lane = tid & 31, wid = tid >> 5;
    int gid = lane >> 2, tg = lane & 3;
    int qt = blockIdx.x, bh = blockIdx.y;
    const __half* Qb = qkv + (size_t)bh * 394 * 128;
    const __half* Kb = qkv + QKV_SZ + (size_t)bh * 394 * 128;
    const __half* Vb = qkv + 2 * QKV_SZ + (size_t)bh * 197 * 256;
    __half* Ob = Og + (size_t)(bh >> 1) * NTOK * EMB_ + (bh & 1) * 128;
    int qbase = qt * 128;
    int r0 = wid * 16 + gid;

    auto loadQ = [&]() {
#pragma unroll
        for (int i = 0; i < 8; i++) {
            int idx = tid + i * 256; int row = idx >> 4; int cc = (idx & 15) << 3;
            int gr = qbase + row; if (gr >= 394) gr = 0;
            cpa16(Qs + row * 136 + cc, Qb + (size_t)gr * 128 + cc, true);
        }
    };
    auto loadK = [&](int st, int kt) {
        __half* dst = Ks + st * 64 * 136;
#pragma unroll
        for (int i = 0; i < 4; i++) {
            int idx = tid + i * 256; int row = idx >> 4; int cc = (idx & 15) << 3;
            int gr = kt * 64 + row; if (gr >= 394) gr = 0;
            cpa16(dst + row * 136 + cc, Kb + (size_t)gr * 128 + cc, true);
        }
    };
    auto loadV = [&](int st, int kt) {
        __half* dst = Vs + st * 32 * 272;
#pragma unroll
        for (int i = 0; i < 4; i++) {
            int idx = tid + i * 256; int row = idx >> 5; int cc = (idx & 31) << 3;
            int gp = kt * 32 + row; if (gp >= 197) gp = 0;
            cpa16(dst + row * 272 + cc, Vb + (size_t)gp * 256 + cc, true);
        }
    };

    loadQ(); loadK(0, 0); loadV(0, 0); cpa_commit();
    loadK(1, 1); loadV(1, 1); cpa_commit();

    float accO[16][4] = {};
    float m0 = -1e30f, m1 = -1e30f, l0 = 0.f, l1 = 0.f;

    for (int kt = 0; kt < FA_NKT; kt++) {
        int st = kt & 1;
        cpa_wait<1>();
        __syncthreads();

        float accS[8][4] = {};
        {
            const unsigned* Qu = (const unsigned*)Qs;
            const unsigned* Ku = (const unsigned*)(Ks + st * 64 * 136);
#pragma unroll
            for (int j = 0; j < 8; j++) {
                unsigned af[4];
                af[0] = Qu[r0 * 68 + j * 8 + tg];
                af[1] = Qu[(r0 + 8) * 68 + j * 8 + tg];
                af[2] = Qu[r0 * 68 + j * 8 + tg + 4];
                af[3] = Qu[(r0 + 8) * 68 + j * 8 + tg + 4];
#pragma unroll
                for (int nt = 0; nt < 8; nt++) {
                    int kv = nt * 8 + gid;
                    unsigned bf[2];
                    bf[0] = Ku[kv * 68 + j * 8 + tg];
                    bf[1] = Ku[kv * 68 + j * 8 + tg + 4];
                    mma16(accS[nt], af, bf);
                }
            }
        }
        int cb = kt * 64 + tg * 2;
#pragma unroll
        for (int nt = 0; nt < 8; nt++) {
            int c0 = cb + nt * 8;
            if (c0 >= 394)     { accS[nt][0] = -1e30f; accS[nt][2] = -1e30f; }
            if (c0 + 1 >= 394) { accS[nt][1] = -1e30f; accS[nt][3] = -1e30f; }
        }
        float rm0 = -1e30f, rm1 = -1e30f;
#pragma unroll
        for (int nt = 0; nt < 8; nt++) {
            rm0 = fmaxf(rm0, fmaxf(accS[nt][0], accS[nt][1]));
            rm1 = fmaxf(rm1, fmaxf(accS[nt][2], accS[nt][3]));
        }
        rm0 = fmaxf(rm0, __shfl_xor_sync(0xffffffffu, rm0, 1));
        rm0 = fmaxf(rm0, __shfl_xor_sync(0xffffffffu, rm0, 2));
        rm1 = fmaxf(rm1, __shfl_xor_sync(0xffffffffu, rm1, 1));
        rm1 = fmaxf(rm1, __shfl_xor_sync(0xffffffffu, rm1, 2));
        float mn0 = fmaxf(m0, rm0), mn1 = fmaxf(m1, rm1);
        float sc0 = __expf(m0 - mn0), sc1 = __expf(m1 - mn1);
        float rs0 = 0.f, rs1 = 0.f;
#pragma unroll
        for (int nt = 0; nt < 8; nt++) {
            accS[nt][0] = __expf(accS[nt][0] - mn0);
            accS[nt][1] = __expf(accS[nt][1] - mn0);
            accS[nt][2] = __expf(accS[nt][2] - mn1);
            accS[nt][3] = __expf(accS[nt][3] - mn1);
            rs0 += accS[nt][0] + accS[nt][1];
            rs1 += accS[nt][2] + accS[nt][3];
        }
        rs0 += __shfl_xor_sync(0xffffffffu, rs0, 1);
        rs0 += __shfl_xor_sync(0xffffffffu, rs0, 2);
        rs1 += __shfl_xor_sync(0xffffffffu, rs1, 1);
        rs1 += __shfl_xor_sync(0xffffffffu, rs1, 2);
        l0 = l0 * sc0 + rs0;  l1 = l1 * sc1 + rs1;
        m0 = mn0;  m1 = mn1;
#pragma unroll
        for (int nt = 0; nt < 16; nt++) {
            accO[nt][0] *= sc0; accO[nt][1] *= sc0;
            accO[nt][2] *= sc1; accO[nt][3] *= sc1;
        }
        {
            const unsigned* Vu = (const unsigned*)(Vs + st * 32 * 272);
#pragma unroll
            for (int j2 = 0; j2 < 4; j2++) {
                unsigned a[4];
                a[0] = pack2(accS[2 * j2][0],     accS[2 * j2][1]);
                a[1] = pack2(accS[2 * j2][2],     accS[2 * j2][3]);
                a[2] = pack2(accS[2 * j2 + 1][0], accS[2 * j2 + 1][1]);
                a[3] = pack2(accS[2 * j2 + 1][2], accS[2 * j2 + 1][3]);
#pragma unroll
                for (int nt = 0; nt < 16; nt++) {
                    int n = nt * 8 + gid;
                    unsigned bf[2];
                    bf[0] = Vu[(8 * j2 + tg) * 136 + n];
                    bf[1] = Vu[(8 * j2 + tg + 4) * 136 + n];
                    mma16(accO[nt], a, bf);
                }
            }
        }
        __syncthreads();
        if (kt + 2 < FA_NKT) { loadK(st, kt + 2); loadV(st, kt + 2); }
        cpa_commit();
    }

    float inv0 = 1.f / (l0 * 16.f), inv1 = 1.f / (l1 * 16.f);
    int gr0 = qbase + r0, gr1 = gr0 + 8;
#pragma unroll
    for (int nt = 0; nt < 16; nt++) {
        int col = nt * 8 + tg * 2;
        if (gr0 < 394)
            *(__half2*)&Ob[(size_t)gr0 * EMB_ + col] =
                __floats2half2_rn(accO[nt][0] * inv0, accO[nt][1] * inv0);
        if (gr1 < 394)
            *(__half2*)&Ob[(size_t)gr1 * EMB_ + col] =
                __floats2half2_rn(accO[nt][2] * inv1, accO[nt][3] * inv1);
    }
}

// ---------------- ln1: warp-per-token -----------------------------------------
__global__ __launch_bounds__(256)
void ln1_kernel(const float* __restrict__ in, const float* __restrict__ g,
                const float* __restrict__ b, __half* __restrict__ out) {
    int warp = threadIdx.x >> 5, lane = threadIdx.x & 31;
    int r = blockIdx.x * 8 + warp;
    const float* row = in + (size_t)r * EMB_ + lane * 8;
    float4 v0 = *(const float4*)row;
    float4 v1 = *(const float4*)(row + 4);
    float v[8] = {v0.x, v0.y, v0.z, v0.w, v1.x, v1.y, v1.z, v1.w};
    float s = 0.f, s2 = 0.f;
#pragma unroll
    for (int i = 0; i < 8; i++) { s += v[i]; s2 += v[i] * v[i]; }
#pragma unroll
    for (int off = 16; off > 0; off >>= 1) {
        s  += __shfl_xor_sync(0xffffffffu, s,  off);
        s2 += __shfl_xor_sync(0xffffffffu, s2, off);
    }
    float mean = s * (1.f / EMB_);
    float rstd = rsqrtf(s2 * (1.f / EMB_) - mean * mean + 1e-5f);
    float4 g0 = *(const float4*)(g + lane * 8);
    float4 g1 = *(const float4*)(g + lane * 8 + 4);
    float4 b0 = *(const float4*)(b + lane * 8);
    float4 b1 = *(const float4*)(b + lane * 8 + 4);
    float gg[8] = {g0.x, g0.y, g0.z, g0.w, g1.x, g1.y, g1.z, g1.w};
    float bb[8] = {b0.x, b0.y, b0.z, b0.w, b1.x, b1.y, b1.z, b1.w};
    __half2 h[4];
#pragma unroll
    for (int i = 0; i < 4; i++) {
        float n0 = (v[2 * i]     - mean) * rstd * gg[2 * i]     + bb[2 * i];
        float n1 = (v[2 * i + 1] - mean) * rstd * gg[2 * i + 1] + bb[2 * i + 1];
        h[i] = __floats2half2_rn(n0, n1);
    }
    *(uint4*)(out + (size_t)r * EMB_ + lane * 8) = *(uint4*)h;
}

// ---- ln2 + residual + pool partial -------------------------------------------
__global__ __launch_bounds__(256)
void ln2_pool(const float* __restrict__ h, const float* __restrict__ g,
              const float* __restrict__ bb, const float* __restrict__ z,
              float* __restrict__ pool) {
    int b = blockIdx.x, seg = blockIdx.y;
    int warp = threadIdx.x >> 5, lane = threadIdx.x & 31;
    int t0 = seg * 50, t1 = t0 + 50; if (t1 > NTOK) t1 = NTOK;
    float4 g0 = *(const float4*)(g + lane * 8);
    float4 g1 = *(const float4*)(g + lane * 8 + 4);
    float4 bv0 = *(const float4*)(bb + lane * 8);
    float4 bv1 = *(const float4*)(bb + lane * 8 + 4);
    float gg[8] = {g0.x, g0.y, g0.z, g0.w, g1.x, g1.y, g1.z, g1.w};
    float be[8] = {bv0.x, bv0.y, bv0.z, bv0.w, bv1.x, bv1.y, bv1.z, bv1.w};
    float accp[8] = {};
    for (int t = t0 + warp; t < t1; t += 8) {
        size_t base = ((size_t)b * NTOK + t) * EMB_ + lane * 8;
        float4 v0 = *(const float4*)(h + base);
        float4 v1 = *(const float4*)(h + base + 4);
        float v[8] = {v0.x, v0.y, v0.z, v0.w, v1.x, v1.y, v1.z, v1.w};
        float s = 0.f, s2 = 0.f;
#pragma unroll
        for (int i = 0; i < 8; i++) { s += v[i]; s2 += v[i] * v[i]; }
#pragma unroll
        for (int off = 16; off > 0; off >>= 1) {
            s  += __shfl_xor_sync(0xffffffffu, s,  off);
            s2 += __shfl_xor_sync(0xffffffffu, s2, off);
        }
        float mean = s * (1.f / EMB_);
        float rstd = rsqrtf(s2 * (1.f / EMB_) - mean * mean + 1e-5f);
        float4 z0 = *(const float4*)(z + base);
        float4 z1 = *(const float4*)(z + base + 4);
        float zv[8] = {z0.x, z0.y, z0.z, z0.w, z1.x, z1.y, z1.z, z1.w};
#pragma unroll
        for (int i = 0; i < 8; i++)
            accp[i] += zv[i] + (v[i] - mean) * rstd * gg[i] + be[i];
    }
    __shared__ float sm[8][256];
#pragma unroll
    for (int i = 0; i < 8; i++) sm[warp][lane * 8 + i] = accp[i];
    __syncthreads();
    int e = threadIdx.x;
    float tot = 0.f;
#pragma unroll
    for (int w = 0; w < 8; w++) tot += sm[w][e];
    pool[((size_t)b * 8 + seg) * EMB_ + e] = tot;
}

// ---------------- head ----------------------------------------------------------
__global__ __launch_bounds__(256)
void head_kernel(const float* __restrict__ pool, const float* __restrict__ g,
                 const float* __restrict__ bb, const float* __restrict__ Wc,
                 const float* __restrict__ bc, float* __restrict__ out) {
    int b = blockIdx.x, e = threadIdx.x;
    float s = 0.f;
#pragma unroll
    for (int i = 0; i < 8; i++) s += pool[((size_t)b * 8 + i) * EMB_ + e];
    float pooled = s * (1.f / NTOK);
    __shared__ float red[256];
    red[e] = pooled; __syncthreads();
    for (int st = 128; st > 0; st >>= 1) { if (e < st) red[e] += red[e + st]; __syncthreads(); }
    float mean = red[0] * (1.f / EMB_);
    __syncthreads();
    float d = pooled - mean;
    red[e] = d * d; __syncthreads();
    for (int st = 128; st > 0; st >>= 1) { if (e < st) red[e] += red[e + st]; __syncthreads(); }
    float var = red[0] * (1.f / EMB_);
    __syncthreads();
    float nv = d * rsqrtf(var + 1e-5f) * g[e] + bb[e];
    red[e] = nv * Wc[e * 2 + 0]; __syncthreads();
    for (int st = 128; st > 0; st >>= 1) { if (e < st) red[e] += red[e + st]; __syncthreads(); }
    float l0 = red[0] + bc[0];
    __syncthreads();
    red[e] = nv * Wc[e * 2 + 1]; __syncthreads();
    for (int st = 128; st > 0; st >>= 1) { if (e < st) red[e] += red[e + st]; __syncthreads(); }
    float l1 = red[0] + bc[1];
    if (e == 0) {
        float mx = fmaxf(l0, l1);
        float lse = mx + logf(expf(l0 - mx) + expf(l1 - mx));
        out[b * 2 + 0] = l0 - lse;
        out[b * 2 + 1] = l1 - lse;
    }
}

// ---------------- launch ----------------------------------------------------------
extern "C" void kernel_launch(void* const* d_in, const int* in_sizes, int n_in,
                              void* d_out, int out_size) {
    const float* x     = (const float*)d_in[0];
    const float* W1    = (const float*)d_in[1];
    const float* b1    = (const float*)d_in[2];
    const float* cls1  = (const float*)d_in[3];
    const float* W2    = (const float*)d_in[4];
    const float* b2    = (const float*)d_in[5];
    const float* cls2  = (const float*)d_in[6];
    const float* ln1_g = (const float*)d_in[7];
    const float* ln1_b = (const float*)d_in[8];
    const float* Wq    = (const float*)d_in[9];
    const float* bq    = (const float*)d_in[10];
    const float* Wk    = (const float*)d_in[11];
    const float* bk    = (const float*)d_in[12];
    const float* Wv    = (const float*)d_in[13];
    const float* bv    = (const float*)d_in[14];
    const float* Wp    = (const float*)d_in[15];
    const float* bp    = (const float*)d_in[16];
    const float* ln2_g = (const float*)d_in[17];
    const float* ln2_b = (const float*)d_in[18];
    const float* lnc_g = (const float*)d_in[19];
    const float* lnc_b = (const float*)d_in[20];
    const float* Wc    = (const float*)d_in[21];
    const float* bc    = (const float*)d_in[22];
    float* out = (float*)d_out;

    static int inited = 0;
    if (!inited) {
        cudaFuncSetAttribute(gemm_nn, cudaFuncAttributeMaxDynamicSharedMemorySize, SMEM_NN);
        cudaFuncSetAttribute(gemm_pe, cudaFuncAttributeMaxDynamicSharedMemorySize, SMEM_PE);
        cudaFuncSetAttribute(flash_attn, cudaFuncAttributeMaxDynamicSharedMemorySize, FA_SMEM);
        inited = 1;
    }

    __half *x16, *T2, *Wt, *h16, *qkv, *o16;
    float *bqkv, *z, *hf, *pool;
    cudaGetSymbolAddress((void**)&x16, g_x16);
    cudaGetSymbolAddress((void**)&T2,  g_T2);
    cudaGetSymbolAddress((void**)&Wt,  g_Wt);
    cudaGetSymbolAddress((void**)&bqkv, g_bqkv);
    cudaGetSymbolAddress((void**)&z,   g_z);
    cudaGetSymbolAddress((void**)&h16, g_h16);
    cudaGetSymbolAddress((void**)&hf,  g_hf);
    cudaGetSymbolAddress((void**)&qkv, g_qkv);
    cudaGetSymbolAddress((void**)&o16, g_o16);
    cudaGetSymbolAddress((void**)&pool, g_pool);

    prep_all<<<ALL_BLK, 256>>>(x, W1, W2, Wq, Wk, Wv, Wp, bq, bk, bv,
                               cls1, cls2, x16, T2, Wt, bqkv, z);

    gemm_pe<<<dim3(2, 392), 256, SMEM_PE>>>(x16, T2, Wt + OFF_W1P, Wt + OFF_W2, b1, b2, z);

    ln1_kernel<<<MTOK / 8, 256>>>(z, ln1_g, ln1_b, h16);

    gemm_nn<<<dim3(6, 394), 256, SMEM_NN>>>(h16, Wt + OFF_WQKV, bqkv, qkv, 768, 256, 5);

    flash_attn<<<dim3(4, 256), 256, FA_SMEM>>>(qkv, o16);

    gemm_nn<<<dim3(2, 394), 256, SMEM_NN>>>(o16, Wt + OFF_WP, bp, hf, 256, 256, 0);

    ln2_pool<<<dim3(B_, 8), 256>>>(hf, ln2_g, ln2_b, z, pool);
    head_kernel<<<B_, 256>>>(pool, lnc_g, lnc_b, Wc, bc, out);
}